// round 1
// baseline (speedup 1.0000x reference)
#include <cuda_runtime.h>

#define D  128
#define P  17
#define HF 56
#define WF 100
#define TP 16

// ---- device scratch (no allocations allowed) ----
__device__ float g_imgT[2*HF*WF*D];   // [B,H,W,C] transposed image feats (5.7MB)
__device__ float g_kT[D*D];           // k_W^T
__device__ float g_Wqk[D*D];          // q_W @ k_W^T
__device__ float g_W2[D*D];           // v_W @ out_W
__device__ float g_bqk[D];            // q_b @ k_W^T
__device__ float g_wqkb[D];           // q_W @ k_b
__device__ float g_vbp[D];            // v_b @ out_W
__device__ float g_cqkb;              // q_b . k_b

__constant__ float c_base[2*P] = {
  -1,-1, -1,0, -1,1, 0,-1, 0,0, 0,1, 1,-1, 1,0, 1,1,
  -3,-3, -3,0, -3,3, 0,-3, 0,3, 3,-3, 3,0, 3,3 };

__device__ __forceinline__ float warpSum(float v){
  #pragma unroll
  for(int o=16;o>0;o>>=1) v += __shfl_xor_sync(0xffffffffu, v, o);
  return v;
}

// Robustly read a small positive dimension that may be int32/int64/float32.
__device__ __forceinline__ int read_dim(const void* p){
  int iv = *(const int*)p;
  if (iv > 0 && iv < 1000000) return iv;  // int32, or low word of little-endian int64
  return (int)(*(const float*)p);
}

// ---- prep kernels ----
__global__ void k_img_transpose(const float* __restrict__ img){
  int pix = blockIdx.x;             // b*HF*WF + y*WF + x
  int c = threadIdx.x;
  int b = pix/(HF*WF);
  int yx = pix - b*(HF*WF);
  g_imgT[(size_t)pix*D + c] = img[((size_t)(b*D + c))*(HF*WF) + yx];
}

__global__ void k_transpose_kw(const float* __restrict__ kW){
  int dd = blockIdx.x, c = threadIdx.x;
  g_kT[dd*D + c] = kW[c*D + dd];
}

__global__ void k_prep_mats(const float* __restrict__ qW,
                            const float* __restrict__ vW,
                            const float* __restrict__ outW){
  __shared__ float row[D];
  int r = blockIdx.x, t = threadIdx.x;
  if (blockIdx.y == 0){
    row[t] = qW[r*D+t]; __syncthreads();
    float acc = 0.f;
    #pragma unroll 4
    for(int dd=0; dd<D; dd++) acc += row[dd]*g_kT[dd*D+t];
    g_Wqk[r*D+t] = acc;
  } else {
    row[t] = vW[r*D+t]; __syncthreads();
    float acc = 0.f;
    #pragma unroll 4
    for(int dd=0; dd<D; dd++) acc += row[dd]*outW[dd*D+t];
    g_W2[r*D+t] = acc;
  }
}

__global__ void k_prep_vecs(const float* __restrict__ qW, const float* __restrict__ qb,
                            const float* __restrict__ kb, const float* __restrict__ vb,
                            const float* __restrict__ outW){
  int t = threadIdx.x;
  float a=0.f, bv=0.f, w=0.f;
  for(int dd=0; dd<D; dd++){
    a  += qb[dd]*g_kT[dd*D+t];
    bv += vb[dd]*outW[dd*D+t];
    w  += qW[t*D+dd]*kb[dd];
  }
  g_bqk[t]=a; g_vbp[t]=bv; g_wqkb[t]=w;
  if(t==0){ float c=0.f; for(int dd=0; dd<D; dd++) c += qb[dd]*kb[dd]; g_cqkb=c; }
}

// ---- main fused kernel: TP points per 128-thread block ----
__global__ __launch_bounds__(128)
void k_main(const float* __restrict__ x_lidar, const int* __restrict__ indices,
            const float* __restrict__ voxel_size, const float* __restrict__ pc_range,
            const float* __restrict__ trans, const float* __restrict__ offW,
            const float* __restrict__ offb, const float* __restrict__ outb,
            const void* pH, const void* pW, float* __restrict__ out, int N)
{
  const int t = threadIdx.x;
  const int warp = t>>5, lane = t&31;
  const int n0 = blockIdx.x*TP;

  __shared__ float x_s[TP*D];
  __shared__ float qk_s[TP*D];
  __shared__ float agg_s[TP*D];
  __shared__ float sampled_s[P*D];
  __shared__ float learned_s[TP*2*P];
  __shared__ float qkb_s[TP][4];
  __shared__ float part_s[P][4];
  __shared__ float w_s[P][4];
  __shared__ int   o_s[P][4];
  __shared__ float attn_s[P];
  __shared__ float valid_s[P];
  __shared__ float S_s[TP];

  // ---- load x tile ----
  #pragma unroll
  for(int i=0;i<TP;i++){
    int n = min(n0+i, N-1);
    x_s[i*D+t] = x_lidar[(size_t)n*D + t];
  }
  __syncthreads();

  // ---- qk tile: qk = x @ Wqk + bqk  (batched GEMV, mat read amortized) ----
  {
    float acc[TP];
    #pragma unroll
    for(int i=0;i<TP;i++) acc[i]=0.f;
    for(int e=0;e<D;e+=4){
      float w0=g_Wqk[(e+0)*D+t], w1=g_Wqk[(e+1)*D+t],
            w2=g_Wqk[(e+2)*D+t], w3=g_Wqk[(e+3)*D+t];
      #pragma unroll
      for(int i=0;i<TP;i++){
        float4 xv = *(const float4*)&x_s[i*D+e];
        acc[i] += xv.x*w0 + xv.y*w1 + xv.z*w2 + xv.w*w3;
      }
    }
    float bq = g_bqk[t];
    #pragma unroll
    for(int i=0;i<TP;i++) qk_s[i*D+t] = acc[i]+bq;
  }

  // ---- qkb scalar partials:  x . (q_W k_b) ----
  {
    float wq = g_wqkb[t];
    #pragma unroll
    for(int i=0;i<TP;i++){
      float pp = warpSum(x_s[i*D+t]*wq);
      if(lane==0) qkb_s[i][warp]=pp;
    }
  }

  // ---- learned offsets: tanh(x @ offW + offb) * range ----
  {
    const float du = 2.0f/(WF-1), dv = 2.0f/(HF-1);
    for(int j=t; j<TP*2*P; j+=D){
      int pt = j/(2*P), c = j - pt*(2*P);
      float acc = offb[c];
      for(int e=0;e<D;e++) acc += x_s[pt*D+e]*offW[e*(2*P)+c];
      learned_s[j] = tanhf(acc) * ((c&1)? 1.5f*dv : 1.5f*du);
    }
  }
  __syncthreads();

  const int Wi = read_dim(pW), Hi = read_dim(pH);

  // ---- per-point: sample + attention + aggregate ----
  for(int i=0;i<TP;i++){
    int n = min(n0+i, N-1);
    if(t < P){
      const int4 idx = *(const int4*)(indices + (size_t)n*4);
      int b = idx.x;
      float cvx=voxel_size[0]*8.f, cvy=voxel_size[1]*8.f, cvz=voxel_size[2]*8.f;
      float phx = (float)idx.w*cvx + pc_range[0] + 0.5f*cvx;
      float phy = (float)idx.z*cvy + pc_range[1] + 0.5f*cvy;
      float phz = (float)idx.y*cvz + pc_range[2] + 0.5f*cvz;
      const float* T = trans + b*12;
      float p0 = T[0]*phx + T[1]*phy + T[2]*phz  + T[3];
      float p1 = T[4]*phx + T[5]*phy + T[6]*phz  + T[7];
      float p2 = T[8]*phx + T[9]*phy + T[10]*phz + T[11];
      float depth = fmaxf(p2, 1e-5f);
      const float du = 2.0f/(WF-1), dv = 2.0f/(HF-1);
      float uf = p0/depth * ((float)WF/(float)Wi);
      float vf = p1/depth * ((float)HF/(float)Hi);
      float gx = uf*du - 1.0f + c_base[2*t]  *du + learned_s[i*2*P + 2*t];
      float gy = vf*dv - 1.0f + c_base[2*t+1]*dv + learned_s[i*2*P + 2*t+1];
      valid_s[t] = (fabsf(gx)<=1.f && fabsf(gy)<=1.f) ? 1.f : 0.f;
      float px = (gx+1.f)*0.5f*(WF-1);
      float py = (gy+1.f)*0.5f*(HF-1);
      float fxf = floorf(px), fyf = floorf(py);
      int x0=(int)fxf, y0=(int)fyf;
      float fx = px-fxf, fy = py-fyf;
      int bb = b*HF*WF;
      #pragma unroll
      for(int tap=0;tap<4;tap++){
        int xc = x0 + (tap&1), yc = y0 + (tap>>1);
        bool inb = (xc>=0 && xc<WF && yc>=0 && yc<HF);
        float wx = (tap&1)? fx : 1.f-fx;
        float wy = (tap>>1)? fy : 1.f-fy;
        w_s[t][tap] = inb ? wx*wy : 0.f;
        int xcc = min(max(xc,0),WF-1), ycc = min(max(yc,0),HF-1);
        o_s[t][tap] = (bb + ycc*WF + xcc)*D;
      }
    }
    __syncthreads();

    // bilinear sample (contiguous 512B loads) + attn dot partials
    float qkr = qk_s[i*D+t];
    for(int p=0;p<P;p++){
      float val = w_s[p][0]*g_imgT[o_s[p][0]+t]
                + w_s[p][1]*g_imgT[o_s[p][1]+t]
                + w_s[p][2]*g_imgT[o_s[p][2]+t]
                + w_s[p][3]*g_imgT[o_s[p][3]+t];
      sampled_s[p*D+t] = val;
      float pp = warpSum(val*qkr);
      if(lane==0) part_s[p][warp]=pp;
    }
    __syncthreads();

    // masked softmax + renorm + aux scalars (serial on t==0, it's 17 values)
    if(t==0){
      float qkb = qkb_s[i][0]+qkb_s[i][1]+qkb_s[i][2]+qkb_s[i][3] + g_cqkb;
      const float scale = 0.17677669529663687f;  // 1/sqrt(128/4)
      float lg[P]; float mx = -3.0e38f;
      #pragma unroll
      for(int p=0;p<P;p++){
        float raw = (part_s[p][0]+part_s[p][1]+part_s[p][2]+part_s[p][3] + qkb)*scale;
        float l = (valid_s[p]>0.f)? raw : -10000.f;
        lg[p]=l; mx=fmaxf(mx,l);
      }
      float se=0.f;
      #pragma unroll
      for(int p=0;p<P;p++){ float e2=expf(lg[p]-mx); lg[p]=e2; se+=e2; }
      float inv=1.f/se, S=0.f;
      #pragma unroll
      for(int p=0;p<P;p++){ float a=lg[p]*inv*valid_s[p]; lg[p]=a; S+=a; }
      float rden = 1.f/fmaxf(S,1e-6f);
      float S2=0.f, ent=0.f, vcnt=0.f;
      #pragma unroll
      for(int p=0;p<P;p++){
        float a = lg[p]*rden; attn_s[p]=a; S2+=a;
        float pc = fmaxf(a,1e-6f); ent -= pc*logf(pc);
        vcnt += valid_s[p];
      }
      S_s[i]=S2;
      float snorm=0.f;
      #pragma unroll
      for(int p=0;p<P;p++){
        float lx=learned_s[i*2*P+2*p], ly=learned_s[i*2*P+2*p+1];
        snorm += sqrtf(lx*lx+ly*ly);
      }
      const float du=2.0f/(WF-1), dv=2.0f/(HF-1);
      float inst = (snorm/(float)P) / (1.5f*sqrtf(du*du+dv*dv));
      if(n0+i < N){
        size_t base = (size_t)N*D;
        out[base + (size_t)(n0+i)]              = vcnt/(float)P;
        out[base + (size_t)N   + (size_t)(n0+i)] = fminf(fmaxf(expf(-inst),0.f),1.f);
        out[base + 2*(size_t)N + (size_t)(n0+i)] = fminf(fmaxf(1.f - ent/logf((float)P),0.f),1.f);
      }
    }
    __syncthreads();

    // agg_c = sum_p attn_p * sampled[p][c]
    float aggv = 0.f;
    #pragma unroll
    for(int p=0;p<P;p++) aggv += attn_s[p]*sampled_s[p*D+t];
    agg_s[i*D+t]=aggv;
    __syncthreads();
  }

  // ---- final: out = agg @ W2 + S*vbp + out_b  (batched GEMV) ----
  {
    float acc[TP];
    #pragma unroll
    for(int i2=0;i2<TP;i2++) acc[i2]=0.f;
    for(int e=0;e<D;e+=4){
      float w0=g_W2[(e+0)*D+t], w1=g_W2[(e+1)*D+t],
            w2=g_W2[(e+2)*D+t], w3=g_W2[(e+3)*D+t];
      #pragma unroll
      for(int i2=0;i2<TP;i2++){
        float4 av = *(const float4*)&agg_s[i2*D+e];
        acc[i2] += av.x*w0 + av.y*w1 + av.z*w2 + av.w*w3;
      }
    }
    float ob = outb[t], vb = g_vbp[t];
    #pragma unroll
    for(int i2=0;i2<TP;i2++){
      int n = n0+i2;
      if(n<N) out[(size_t)n*D+t] = acc[i2] + ob + S_s[i2]*vb;
    }
  }
}

extern "C" void kernel_launch(void* const* d_in, const int* in_sizes, int n_in,
                              void* d_out, int out_size) {
  const float* x      = (const float*)d_in[0];
  const int*   indices= (const int*)  d_in[1];
  const float* img    = (const float*)d_in[2];
  const float* voxel  = (const float*)d_in[3];
  const float* pcr    = (const float*)d_in[4];
  const float* trans  = (const float*)d_in[5];
  const float* offW   = (const float*)d_in[6];
  const float* offb   = (const float*)d_in[7];
  const float* qW     = (const float*)d_in[8];
  const float* qb     = (const float*)d_in[9];
  const float* kW     = (const float*)d_in[10];
  const float* vW     = (const float*)d_in[12];
  const float* vb     = (const float*)d_in[13];
  const float* outW   = (const float*)d_in[14];
  const float* outb   = (const float*)d_in[15];
  const void*  pH     = d_in[16];
  const void*  pW     = d_in[17];
  const float* kb     = (const float*)d_in[11];

  int N = in_sizes[0]/D;
  int B = in_sizes[5]/12;

  k_img_transpose<<<B*HF*WF, D>>>(img);
  k_transpose_kw<<<D, D>>>(kW);
  dim3 g(D,2);
  k_prep_mats<<<g, D>>>(qW, vW, outW);
  k_prep_vecs<<<1, D>>>(qW, qb, kb, vb, outW);
  k_main<<<(N+TP-1)/TP, D>>>(x, indices, voxel, pcr, trans, offW, offb, outb,
                             pH, pW, (float*)d_out, N);
}

// round 2
// speedup vs baseline: 1.3676x; 1.3676x over previous
#include <cuda_runtime.h>

#define D   128
#define P   17
#define HF  56
#define WF  100
#define TP  16
#define NPIX (HF*WF)

// ---- device scratch ----
__device__ float g_imgT[2*NPIX*D];    // [B,H,W,C]
__device__ float g_kT[D*D];           // k_W^T
__device__ float g_Wqk[D*D];          // q_W @ k_W^T
__device__ float g_W2[D*D];           // v_W @ out_W
__device__ float g_bqk[D];            // q_b @ k_W^T
__device__ float g_vbp[D];            // v_b @ out_W

__constant__ float c_base[2*P] = {
  -1,-1, -1,0, -1,1, 0,-1, 0,0, 0,1, 1,-1, 1,0, 1,1,
  -3,-3, -3,0, -3,3, 0,-3, 0,3, 3,-3, 3,0, 3,3 };

__device__ __forceinline__ float warpSum(float v){
  #pragma unroll
  for(int o=16;o>0;o>>=1) v += __shfl_xor_sync(0xffffffffu, v, o);
  return v;
}
__device__ __forceinline__ float warpMax(float v){
  #pragma unroll
  for(int o=16;o>0;o>>=1) v = fmaxf(v, __shfl_xor_sync(0xffffffffu, v, o));
  return v;
}
__device__ __forceinline__ int read_dim(const void* p){
  int iv = *(const int*)p;
  if (iv > 0 && iv < 1000000) return iv;
  return (int)(*(const float*)p);
}
__device__ __forceinline__ void barhalf(int half){
  asm volatile("bar.sync %0, 128;" :: "r"(half+1) : "memory");
}

// ---- tiled img transpose: [B,C,H,W] -> [B,H,W,C], fully coalesced ----
__global__ void k_img_transpose(const float* __restrict__ img){
  __shared__ float tile[32][33];
  const int b  = blockIdx.z;
  const int yx0 = blockIdx.x*32, c0 = blockIdx.y*32;
  const int tx = threadIdx.x, ty = threadIdx.y;   // 32x8
  #pragma unroll
  for(int cc=0;cc<32;cc+=8)
    tile[cc+ty][tx] = img[((size_t)(b*D + c0+cc+ty))*NPIX + yx0 + tx];
  __syncthreads();
  #pragma unroll
  for(int yy=0;yy<32;yy+=8)
    g_imgT[((size_t)(b*NPIX + yx0+yy+ty))*D + c0 + tx] = tile[tx][yy+ty];
}

// ---- tiled kW transpose ----
__global__ void k_transpose_kw(const float* __restrict__ kW){
  __shared__ float tile[32][33];
  const int c0 = blockIdx.x*32, d0 = blockIdx.y*32;
  const int tx = threadIdx.x, ty = threadIdx.y;   // 32x8
  #pragma unroll
  for(int cc=0;cc<32;cc+=8)
    tile[cc+ty][tx] = kW[(c0+cc+ty)*D + d0 + tx];
  __syncthreads();
  #pragma unroll
  for(int yy=0;yy<32;yy+=8)
    g_kT[(d0+yy+ty)*D + c0 + tx] = tile[tx][yy+ty];
}

// ---- matrix + vector preps: y=0 -> Wqk row, y=1 -> W2 row, y=2 -> bqk/vbp ----
__global__ void k_prep_mats(const float* __restrict__ qW,
                            const float* __restrict__ vW,
                            const float* __restrict__ outW,
                            const float* __restrict__ kW,
                            const float* __restrict__ qb,
                            const float* __restrict__ vb){
  const int r = blockIdx.x, t = threadIdx.x;
  if (blockIdx.y == 0){
    __shared__ float row[D];
    row[t] = qW[r*D+t]; __syncthreads();
    float acc = 0.f;
    #pragma unroll 4
    for(int dd=0; dd<D; dd++) acc = fmaf(row[dd], g_kT[dd*D+t], acc);
    g_Wqk[r*D+t] = acc;
  } else if (blockIdx.y == 1){
    __shared__ float row[D];
    row[t] = vW[r*D+t]; __syncthreads();
    float acc = 0.f;
    #pragma unroll 4
    for(int dd=0; dd<D; dd++) acc = fmaf(row[dd], outW[dd*D+t], acc);
    g_W2[r*D+t] = acc;
  } else {
    // g_bqk[r] = sum_dd qb[dd]*kW[r*D+dd] ; g_vbp[r] = sum_dd vb[dd]*outW[dd*D+r]
    __shared__ float red1[4], red2[4];
    float s1 = qb[t]*kW[r*D+t];
    float s2 = vb[t]*outW[t*D+r];
    s1 = warpSum(s1); s2 = warpSum(s2);
    if((t&31)==0){ red1[t>>5]=s1; red2[t>>5]=s2; }
    __syncthreads();
    if(t==0){
      g_bqk[r] = red1[0]+red1[1]+red1[2]+red1[3];
      g_vbp[r] = red2[0]+red2[1]+red2[2]+red2[3];
    }
  }
}

// ---- main fused kernel: 256 threads, 2 points in flight (one per half) ----
__global__ __launch_bounds__(256)
void k_main(const float* __restrict__ x_lidar, const int* __restrict__ indices,
            const float* __restrict__ voxel_size, const float* __restrict__ pc_range,
            const float* __restrict__ trans, const float* __restrict__ offW,
            const float* __restrict__ offb, const float* __restrict__ outb,
            const void* pH, const void* pW, float* __restrict__ out, int N)
{
  const int t    = threadIdx.x;
  const int half = t >> 7;
  const int tc   = t & 127;
  const int lane = t & 31;
  const int n0   = blockIdx.x * TP;
  const float du = 2.0f/(WF-1), dv = 2.0f/(HF-1);

  __shared__ __align__(16) float xagg_s[TP*D];        // x, later agg
  __shared__ __align__(16) float qk_s[TP*D];
  __shared__ __align__(16) float sampled_s[2][P*D];
  __shared__ __align__(16) float w_s[TP][P][4];
  __shared__ __align__(16) int   o_s[TP][P][4];
  __shared__ float learned_s[TP][2*P];
  __shared__ float centers_s[TP][2];
  __shared__ int   boff_s[TP];
  __shared__ float valid_s[TP][P];
  __shared__ float logits_s[2][P];
  __shared__ float attn_s[2][P];
  __shared__ float S_s[TP];

  // ---- load x tile (parity-consistent with later phases) ----
  #pragma unroll
  for(int j=0;j<8;j++){
    int i = half + 2*j;
    int n = min(n0+i, N-1);
    xagg_s[i*D+tc] = x_lidar[(size_t)n*D + tc];
  }
  __syncthreads();

  // ---- Phase A: GEMV1 (qk), learned offsets, centers ----
  {
    float acc[8];
    #pragma unroll
    for(int j=0;j<8;j++) acc[j]=0.f;
    for(int e=0;e<D;e+=4){
      float w0=__ldg(&g_Wqk[(e+0)*D+tc]), w1=__ldg(&g_Wqk[(e+1)*D+tc]),
            w2=__ldg(&g_Wqk[(e+2)*D+tc]), w3=__ldg(&g_Wqk[(e+3)*D+tc]);
      #pragma unroll
      for(int j=0;j<8;j++){
        const float4 xv = *(const float4*)&xagg_s[(half+2*j)*D + e];
        acc[j] = fmaf(xv.x,w0, fmaf(xv.y,w1, fmaf(xv.z,w2, fmaf(xv.w,w3, acc[j]))));
      }
    }
    float bq = g_bqk[tc];
    #pragma unroll
    for(int j=0;j<8;j++) qk_s[(half+2*j)*D+tc] = acc[j]+bq;
  }
  for(int j=t; j<TP*2*P; j+=256){
    int pt = j/(2*P), c = j - pt*2*P;
    float acc = offb[c];
    #pragma unroll 4
    for(int e=0;e<D;e++) acc = fmaf(xagg_s[pt*D+e], offW[e*2*P+c], acc);
    learned_s[pt][c] = tanhf(acc) * ((c&1)? 1.5f*dv : 1.5f*du);
  }
  if(t < TP){
    int n = min(n0+t, N-1);
    const int4 idx = *(const int4*)(indices + (size_t)n*4);
    float cvx=voxel_size[0]*8.f, cvy=voxel_size[1]*8.f, cvz=voxel_size[2]*8.f;
    float phx = (float)idx.w*cvx + pc_range[0] + 0.5f*cvx;
    float phy = (float)idx.z*cvy + pc_range[1] + 0.5f*cvy;
    float phz = (float)idx.y*cvz + pc_range[2] + 0.5f*cvz;
    const float* T = trans + idx.x*12;
    float p0 = T[0]*phx + T[1]*phy + T[2]*phz  + T[3];
    float p1 = T[4]*phx + T[5]*phy + T[6]*phz  + T[7];
    float p2 = T[8]*phx + T[9]*phy + T[10]*phz + T[11];
    float depth = fmaxf(p2, 1e-5f);
    const int Wi = read_dim(pW), Hi = read_dim(pH);
    float uf = p0/depth * ((float)WF/(float)Wi);
    float vf = p1/depth * ((float)HF/(float)Hi);
    centers_s[t][0] = uf*du - 1.0f;
    centers_s[t][1] = vf*dv - 1.0f;
    boff_s[t] = idx.x * NPIX;
  }
  __syncthreads();

  // ---- Phase B: geometry for all TP*P sample points ----
  for(int j=t; j<TP*P; j+=256){
    int pt = j/P, p = j - pt*P;
    float gx = centers_s[pt][0] + c_base[2*p]  *du + learned_s[pt][2*p];
    float gy = centers_s[pt][1] + c_base[2*p+1]*dv + learned_s[pt][2*p+1];
    valid_s[pt][p] = (fabsf(gx)<=1.f && fabsf(gy)<=1.f) ? 1.f : 0.f;
    float px = (gx+1.f)*0.5f*(WF-1);
    float py = (gy+1.f)*0.5f*(HF-1);
    float fxf = floorf(px), fyf = floorf(py);
    int x0=(int)fxf, y0=(int)fyf;
    float fx = px-fxf, fy = py-fyf;
    int bb = boff_s[pt];
    #pragma unroll
    for(int tap=0;tap<4;tap++){
      int xc = x0 + (tap&1), yc = y0 + (tap>>1);
      bool inb = (xc>=0 && xc<WF && yc>=0 && yc<HF);
      float wx = (tap&1)? fx : 1.f-fx;
      float wy = (tap>>1)? fy : 1.f-fy;
      w_s[pt][p][tap] = inb ? wx*wy : 0.f;
      int xcc = min(max(xc,0),WF-1), ycc = min(max(yc,0),HF-1);
      o_s[pt][p][tap] = (bb + ycc*WF + xcc)*D;
    }
  }
  __syncthreads();

  const float scale = 0.17677669529663687f;  // 1/sqrt(D/NUM_HEADS)

  // ---- main loop: each half owns points of its parity ----
  for(int ii=0; ii<TP; ii+=2){
    const int i = ii + half;

    // bilinear sample (contiguous 512B line per tap)
    #pragma unroll 4
    for(int p=0;p<P;p++){
      const float4 wv = *(const float4*)w_s[i][p];
      const int4  ov = *(const int4*) o_s[i][p];
      float val = wv.x*__ldg(&g_imgT[ov.x+tc])
                + wv.y*__ldg(&g_imgT[ov.y+tc])
                + wv.z*__ldg(&g_imgT[ov.z+tc])
                + wv.w*__ldg(&g_imgT[ov.w+tc]);
      sampled_s[half][p*D+tc] = val;
    }
    barhalf(half);

    // logits: 4 warps of this half, p strided by 4, float4 dot + warpSum
    {
      const int wih = tc>>5;
      for(int p=wih; p<P; p+=4){
        const float4 sv = *(const float4*)&sampled_s[half][p*D + lane*4];
        const float4 qv = *(const float4*)&qk_s[i*D + lane*4];
        float d = sv.x*qv.x + sv.y*qv.y + sv.z*qv.z + sv.w*qv.w;
        d = warpSum(d);
        if(lane==0) logits_s[half][p] = d;
      }
    }
    barhalf(half);

    // warp-parallel masked softmax + aux (warp 0 of half, lanes = points)
    if((tc>>5)==0){
      const bool act = lane < P;
      float vld = act ? valid_s[i][lane] : 0.f;
      float l = act ? ((vld>0.f) ? logits_s[half][lane]*scale : -10000.f)
                    : -3.0e38f;
      float mx = warpMax(l);
      float e  = act ? expf(l - mx) : 0.f;
      float se = warpSum(e);
      float a1 = e * (1.f/se) * vld;
      float S  = warpSum(a1);
      float a  = a1 * (1.f/fmaxf(S, 1e-6f));
      if(act) attn_s[half][lane] = a;
      float S2 = warpSum(act ? a : 0.f);
      float pc = fmaxf(a, 1e-6f);
      float ent = warpSum(act ? -pc*logf(pc) : 0.f);
      float vcnt = warpSum(vld);
      float lx = act ? learned_s[i][2*lane]   : 0.f;
      float ly = act ? learned_s[i][2*lane+1] : 0.f;
      float nrm = warpSum(act ? sqrtf(lx*lx+ly*ly) : 0.f);
      if(lane==0){
        S_s[i] = S2;
        int n = n0 + i;
        if(n < N){
          float inst = (nrm/(float)P) / (1.5f*sqrtf(du*du+dv*dv));
          size_t base = (size_t)N*D;
          out[base + n]              = vcnt/(float)P;
          out[base + (size_t)N + n]  = fminf(fmaxf(expf(-inst),0.f),1.f);
          out[base + 2*(size_t)N + n]= fminf(fmaxf(1.f - ent/logf((float)P),0.f),1.f);
        }
      }
    }
    barhalf(half);

    // aggregate: agg_c = sum_p attn_p * sampled[p][c]
    {
      float aggv = 0.f;
      #pragma unroll
      for(int p=0;p<P;p++) aggv = fmaf(attn_s[half][p], sampled_s[half][p*D+tc], aggv);
      xagg_s[i*D+tc] = aggv;
    }
    barhalf(half);
  }

  // ---- GEMV2: out = agg @ W2 + S*vbp + out_b (parity-consistent) ----
  {
    float acc[8];
    #pragma unroll
    for(int j=0;j<8;j++) acc[j]=0.f;
    for(int e=0;e<D;e+=4){
      float w0=__ldg(&g_W2[(e+0)*D+tc]), w1=__ldg(&g_W2[(e+1)*D+tc]),
            w2=__ldg(&g_W2[(e+2)*D+tc]), w3=__ldg(&g_W2[(e+3)*D+tc]);
      #pragma unroll
      for(int j=0;j<8;j++){
        const float4 av = *(const float4*)&xagg_s[(half+2*j)*D + e];
        acc[j] = fmaf(av.x,w0, fmaf(av.y,w1, fmaf(av.z,w2, fmaf(av.w,w3, acc[j]))));
      }
    }
    float ob = outb[tc], vbp = g_vbp[tc];
    #pragma unroll
    for(int j=0;j<8;j++){
      int i = half + 2*j;
      int n = n0 + i;
      if(n < N) out[(size_t)n*D+tc] = acc[j] + ob + S_s[i]*vbp;
    }
  }
}

extern "C" void kernel_launch(void* const* d_in, const int* in_sizes, int n_in,
                              void* d_out, int out_size) {
  const float* x      = (const float*)d_in[0];
  const int*   indices= (const int*)  d_in[1];
  const float* img    = (const float*)d_in[2];
  const float* voxel  = (const float*)d_in[3];
  const float* pcr    = (const float*)d_in[4];
  const float* trans  = (const float*)d_in[5];
  const float* offW   = (const float*)d_in[6];
  const float* offb   = (const float*)d_in[7];
  const float* qW     = (const float*)d_in[8];
  const float* qb     = (const float*)d_in[9];
  const float* kW     = (const float*)d_in[10];
  const float* kb     = (const float*)d_in[11];
  const float* vW     = (const float*)d_in[12];
  const float* vb     = (const float*)d_in[13];
  const float* outW   = (const float*)d_in[14];
  const float* outb   = (const float*)d_in[15];
  const void*  pH     = d_in[16];
  const void*  pW     = d_in[17];
  (void)kb;

  int N = in_sizes[0]/D;
  int B = in_sizes[5]/12;

  dim3 tb(32,8);
  k_img_transpose<<<dim3(NPIX/32, D/32, B), tb>>>(img);
  k_transpose_kw<<<dim3(D/32, D/32), tb>>>(kW);
  k_prep_mats<<<dim3(D,3), D>>>(qW, vW, outW, kW, qb, vb);
  k_main<<<(N+TP-1)/TP, 256>>>(x, indices, voxel, pcr, trans, offW, offb, outb,
                               pH, pW, (float*)d_out, N);
}

// round 3
// speedup vs baseline: 1.7484x; 1.2785x over previous
#include <cuda_runtime.h>

#define D   128
#define P   17
#define HF  56
#define WF  100
#define TP  16
#define NPIX (HF*WF)

// ---- device scratch ----
__device__ float g_imgT[2*NPIX*D];    // [B,H,W,C]
__device__ float g_kT[D*D];           // k_W^T
__device__ float g_Wqk[D*D];          // q_W @ k_W^T, quad-interleaved [(e/4)][tc][e%4]
__device__ float g_W2[D*D];           // v_W @ out_W,  quad-interleaved
__device__ float g_bqk[D];            // q_b @ k_W^T
__device__ float g_vbp[D];            // v_b @ out_W

__constant__ float c_base[2*P] = {
  -1,-1, -1,0, -1,1, 0,-1, 0,0, 0,1, 1,-1, 1,0, 1,1,
  -3,-3, -3,0, -3,3, 0,-3, 0,3, 3,-3, 3,0, 3,3 };

union SmemU {
  float offW[2*P*D];                  // 4352 floats (Phase A only)
  struct {
    float w[TP][P][4];                // (Phase B onward)
    int   o[TP][P][4];
    float pagg[2][4][D];
  } s;
};

__device__ __forceinline__ float warpSum(float v){
  #pragma unroll
  for(int o=16;o>0;o>>=1) v += __shfl_xor_sync(0xffffffffu, v, o);
  return v;
}
__device__ __forceinline__ float warpMax(float v){
  #pragma unroll
  for(int o=16;o>0;o>>=1) v = fmaxf(v, __shfl_xor_sync(0xffffffffu, v, o));
  return v;
}
__device__ __forceinline__ int read_dim(const void* p){
  int iv = *(const int*)p;
  if (iv > 0 && iv < 1000000) return iv;
  return (int)(*(const float*)p);
}
__device__ __forceinline__ void barhalf(int half){
  asm volatile("bar.sync %0, 128;" :: "r"(half+1) : "memory");
}

// ---- tiled img transpose: [B,C,H,W] -> [B,H,W,C] ----
__global__ void k_img_transpose(const float* __restrict__ img){
  __shared__ float tile[32][33];
  const int b  = blockIdx.z;
  const int yx0 = blockIdx.x*32, c0 = blockIdx.y*32;
  const int tx = threadIdx.x, ty = threadIdx.y;   // 32x8
  #pragma unroll
  for(int cc=0;cc<32;cc+=8)
    tile[cc+ty][tx] = img[((size_t)(b*D + c0+cc+ty))*NPIX + yx0 + tx];
  __syncthreads();
  #pragma unroll
  for(int yy=0;yy<32;yy+=8)
    g_imgT[((size_t)(b*NPIX + yx0+yy+ty))*D + c0 + tx] = tile[tx][yy+ty];
}

// ---- tiled kW transpose ----
__global__ void k_transpose_kw(const float* __restrict__ kW){
  __shared__ float tile[32][33];
  const int c0 = blockIdx.x*32, d0 = blockIdx.y*32;
  const int tx = threadIdx.x, ty = threadIdx.y;
  #pragma unroll
  for(int cc=0;cc<32;cc+=8)
    tile[cc+ty][tx] = kW[(c0+cc+ty)*D + d0 + tx];
  __syncthreads();
  #pragma unroll
  for(int yy=0;yy<32;yy+=8)
    g_kT[(d0+yy+ty)*D + c0 + tx] = tile[tx][yy+ty];
}

// ---- matrix + vector preps (matrices stored quad-interleaved) ----
__global__ void k_prep_mats(const float* __restrict__ qW,
                            const float* __restrict__ vW,
                            const float* __restrict__ outW,
                            const float* __restrict__ kW,
                            const float* __restrict__ qb,
                            const float* __restrict__ vb){
  const int r = blockIdx.x, t = threadIdx.x;
  const int widx = (r>>2)*(4*D) + t*4 + (r&3);
  if (blockIdx.y == 0){
    __shared__ float row[D];
    row[t] = qW[r*D+t]; __syncthreads();
    float acc = 0.f;
    #pragma unroll 4
    for(int dd=0; dd<D; dd++) acc = fmaf(row[dd], g_kT[dd*D+t], acc);
    g_Wqk[widx] = acc;
  } else if (blockIdx.y == 1){
    __shared__ float row[D];
    row[t] = vW[r*D+t]; __syncthreads();
    float acc = 0.f;
    #pragma unroll 4
    for(int dd=0; dd<D; dd++) acc = fmaf(row[dd], outW[dd*D+t], acc);
    g_W2[widx] = acc;
  } else {
    __shared__ float red1[4], red2[4];
    float s1 = qb[t]*kW[r*D+t];
    float s2 = vb[t]*outW[t*D+r];
    s1 = warpSum(s1); s2 = warpSum(s2);
    if((t&31)==0){ red1[t>>5]=s1; red2[t>>5]=s2; }
    __syncthreads();
    if(t==0){
      g_bqk[r] = red1[0]+red1[1]+red1[2]+red1[3];
      g_vbp[r] = red2[0]+red2[1]+red2[2]+red2[3];
    }
  }
}

// ---- main fused kernel ----
__global__ __launch_bounds__(256, 4)
void k_main(const float* __restrict__ x_lidar, const int* __restrict__ indices,
            const float* __restrict__ voxel_size, const float* __restrict__ pc_range,
            const float* __restrict__ trans, const float* __restrict__ offW,
            const float* __restrict__ offb, const float* __restrict__ outb,
            const void* pH, const void* pW, float* __restrict__ out, int N)
{
  const int t    = threadIdx.x;
  const int half = t >> 7;
  const int tc   = t & 127;
  const int lane = t & 31;
  const int wih  = tc >> 5;          // warp within half
  const int n0   = blockIdx.x * TP;
  const float du = 2.0f/(WF-1), dv = 2.0f/(HF-1);

  __shared__ __align__(16) float xagg_s[TP*D];    // x, later agg
  __shared__ __align__(16) float qk_s[TP*D];
  __shared__ __align__(16) SmemU u;
  __shared__ float learned_s[TP][2*P];
  __shared__ float centers_s[TP][2];
  __shared__ int   boff_s[TP];
  __shared__ float valid_s[TP][P];
  __shared__ float logits_s[2][P];
  __shared__ float attn_s[2][P];
  __shared__ float S_s[TP];

  // ---- vectorized loads: x tile + offW stage ----
  {
    const float4* xs = (const float4*)x_lidar;
    for(int j=t; j<TP*(D/4); j+=256){
      int pt = j>>5;
      int n = n0+pt; if(n>=N) n = N-1;
      ((float4*)xagg_s)[j] = xs[(size_t)n*(D/4) + (j&31)];
    }
    const float4* ow = (const float4*)offW;
    #pragma unroll
    for(int j=t; j<(2*P*D)/4; j+=256)
      ((float4*)u.offW)[j] = ow[j];
  }
  __syncthreads();

  // ---- Phase A: GEMV1 (qk), offsets, centers ----
  {
    float acc[8];
    #pragma unroll
    for(int j=0;j<8;j++) acc[j]=0.f;
    for(int e=0;e<D;e+=4){
      const float4 wq = __ldg((const float4*)g_Wqk + (e>>2)*D + tc);
      #pragma unroll
      for(int j=0;j<8;j++){
        const float4 xv = *(const float4*)&xagg_s[(half+2*j)*D + e];
        acc[j] = fmaf(xv.x,wq.x, fmaf(xv.y,wq.y, fmaf(xv.z,wq.z, fmaf(xv.w,wq.w, acc[j]))));
      }
    }
    float bq = __ldg(&g_bqk[tc]);
    #pragma unroll
    for(int j=0;j<8;j++) qk_s[(half+2*j)*D+tc] = acc[j]+bq;
  }
  // learned offsets: one (pt, sample-point) pair per iteration
  for(int j=t; j<TP*P; j+=256){
    int pt = j/P, cp = j - pt*P;
    float ax = offb[2*cp], ay = offb[2*cp+1];
    #pragma unroll 4
    for(int e=0;e<D;e++){
      float xv = xagg_s[pt*D+e];
      const float2 wv = *(const float2*)&u.offW[e*(2*P) + 2*cp];
      ax = fmaf(xv, wv.x, ax);
      ay = fmaf(xv, wv.y, ay);
    }
    learned_s[pt][2*cp]   = tanhf(ax)*(1.5f*du);
    learned_s[pt][2*cp+1] = tanhf(ay)*(1.5f*dv);
  }
  if(t < TP){
    int n = min(n0+t, N-1);
    const int4 idx = *(const int4*)(indices + (size_t)n*4);
    float cvx=voxel_size[0]*8.f, cvy=voxel_size[1]*8.f, cvz=voxel_size[2]*8.f;
    float phx = (float)idx.w*cvx + pc_range[0] + 0.5f*cvx;
    float phy = (float)idx.z*cvy + pc_range[1] + 0.5f*cvy;
    float phz = (float)idx.y*cvz + pc_range[2] + 0.5f*cvz;
    const float* T = trans + idx.x*12;
    float p0 = T[0]*phx + T[1]*phy + T[2]*phz  + T[3];
    float p1 = T[4]*phx + T[5]*phy + T[6]*phz  + T[7];
    float p2 = T[8]*phx + T[9]*phy + T[10]*phz + T[11];
    float depth = fmaxf(p2, 1e-5f);
    const int Wi = read_dim(pW), Hi = read_dim(pH);
    float uf = p0/depth * ((float)WF/(float)Wi);
    float vf = p1/depth * ((float)HF/(float)Hi);
    centers_s[t][0] = uf*du - 1.0f;
    centers_s[t][1] = vf*dv - 1.0f;
    boff_s[t] = idx.x * NPIX;
  }
  __syncthreads();

  // ---- Phase B: geometry for all TP*P sample points (overwrites offW union) ----
  for(int j=t; j<TP*P; j+=256){
    int pt = j/P, p = j - pt*P;
    float gx = centers_s[pt][0] + c_base[2*p]  *du + learned_s[pt][2*p];
    float gy = centers_s[pt][1] + c_base[2*p+1]*dv + learned_s[pt][2*p+1];
    valid_s[pt][p] = (fabsf(gx)<=1.f && fabsf(gy)<=1.f) ? 1.f : 0.f;
    float px = (gx+1.f)*0.5f*(WF-1);
    float py = (gy+1.f)*0.5f*(HF-1);
    float fxf = floorf(px), fyf = floorf(py);
    int x0=(int)fxf, y0=(int)fyf;
    float fx = px-fxf, fy = py-fyf;
    int bb = boff_s[pt];
    #pragma unroll
    for(int tap=0;tap<4;tap++){
      int xc = x0 + (tap&1), yc = y0 + (tap>>1);
      bool inb = (xc>=0 && xc<WF && yc>=0 && yc<HF);
      float wx = (tap&1)? fx : 1.f-fx;
      float wy = (tap>>1)? fy : 1.f-fy;
      u.s.w[pt][p][tap] = inb ? wx*wy : 0.f;
      int xcc = min(max(xc,0),WF-1), ycc = min(max(yc,0),HF-1);
      u.s.o[pt][p][tap] = (bb + ycc*WF + xcc)*D;
    }
  }
  __syncthreads();

  const float scale = 0.17677669529663687f;  // 1/sqrt(D/NUM_HEADS)

  // ---- main loop: each half owns points of its parity ----
  for(int ii=0; ii<TP; ii+=2){
    const int i = ii + half;
    const float4 qv = *(const float4*)&qk_s[i*D + lane*4];
    float4 sval[5];

    // sample + dot: warp wih owns p = wih+4k (+ p=16 for wih==3)
    #pragma unroll
    for(int k=0;k<4;k++){
      const int p = wih + 4*k;
      const float4 wv = *(const float4*)u.s.w[i][p];
      const int4  ov = *(const int4*) u.s.o[i][p];
      const float4 a = __ldg((const float4*)(g_imgT+ov.x)+lane);
      const float4 b = __ldg((const float4*)(g_imgT+ov.y)+lane);
      const float4 c = __ldg((const float4*)(g_imgT+ov.z)+lane);
      const float4 d = __ldg((const float4*)(g_imgT+ov.w)+lane);
      float4 s;
      s.x = fmaf(wv.x,a.x, fmaf(wv.y,b.x, fmaf(wv.z,c.x, wv.w*d.x)));
      s.y = fmaf(wv.x,a.y, fmaf(wv.y,b.y, fmaf(wv.z,c.y, wv.w*d.y)));
      s.z = fmaf(wv.x,a.z, fmaf(wv.y,b.z, fmaf(wv.z,c.z, wv.w*d.z)));
      s.w = fmaf(wv.x,a.w, fmaf(wv.y,b.w, fmaf(wv.z,c.w, wv.w*d.w)));
      sval[k] = s;
      float dt = fmaf(s.x,qv.x, fmaf(s.y,qv.y, fmaf(s.z,qv.z, s.w*qv.w)));
      dt = warpSum(dt);
      if(lane==0) logits_s[half][p] = dt;
    }
    if(wih==3){
      const int p = 16;
      const float4 wv = *(const float4*)u.s.w[i][p];
      const int4  ov = *(const int4*) u.s.o[i][p];
      const float4 a = __ldg((const float4*)(g_imgT+ov.x)+lane);
      const float4 b = __ldg((const float4*)(g_imgT+ov.y)+lane);
      const float4 c = __ldg((const float4*)(g_imgT+ov.z)+lane);
      const float4 d = __ldg((const float4*)(g_imgT+ov.w)+lane);
      float4 s;
      s.x = fmaf(wv.x,a.x, fmaf(wv.y,b.x, fmaf(wv.z,c.x, wv.w*d.x)));
      s.y = fmaf(wv.x,a.y, fmaf(wv.y,b.y, fmaf(wv.z,c.y, wv.w*d.y)));
      s.z = fmaf(wv.x,a.z, fmaf(wv.y,b.z, fmaf(wv.z,c.z, wv.w*d.z)));
      s.w = fmaf(wv.x,a.w, fmaf(wv.y,b.w, fmaf(wv.z,c.w, wv.w*d.w)));
      sval[4] = s;
      float dt = fmaf(s.x,qv.x, fmaf(s.y,qv.y, fmaf(s.z,qv.z, s.w*qv.w)));
      dt = warpSum(dt);
      if(lane==0) logits_s[half][p] = dt;
    }
    barhalf(half);

    // warp-parallel masked softmax + aux (warp 0 of half, lanes = points)
    if(wih==0){
      const bool act = lane < P;
      float vld = act ? valid_s[i][lane] : 0.f;
      float l = act ? ((vld>0.f) ? logits_s[half][lane]*scale : -10000.f)
                    : -3.0e38f;
      float mx = warpMax(l);
      float e  = act ? expf(l - mx) : 0.f;
      float se = warpSum(e);
      float a1 = e * (1.f/se) * vld;
      float S  = warpSum(a1);
      float a  = a1 * (1.f/fmaxf(S, 1e-6f));
      if(act) attn_s[half][lane] = a;
      float S2 = warpSum(act ? a : 0.f);
      float pc = fmaxf(a, 1e-6f);
      float ent = warpSum(act ? -pc*logf(pc) : 0.f);
      float vcnt = warpSum(vld);
      float lx = act ? learned_s[i][2*lane]   : 0.f;
      float ly = act ? learned_s[i][2*lane+1] : 0.f;
      float nrm = warpSum(act ? sqrtf(lx*lx+ly*ly) : 0.f);
      if(lane==0){
        S_s[i] = S2;
        int n = n0 + i;
        if(n < N){
          float inst = (nrm/(float)P) / (1.5f*sqrtf(du*du+dv*dv));
          size_t base = (size_t)N*D;
          out[base + n]               = vcnt/(float)P;
          out[base + (size_t)N + n]   = fminf(fmaxf(expf(-inst),0.f),1.f);
          out[base + 2*(size_t)N + n] = fminf(fmaxf(1.f - ent/logf((float)P),0.f),1.f);
        }
      }
    }
    barhalf(half);

    // aggregate in registers, then cross-warp combine
    {
      float4 acc4 = make_float4(0.f,0.f,0.f,0.f);
      #pragma unroll
      for(int k=0;k<4;k++){
        float a = attn_s[half][wih+4*k];
        acc4.x = fmaf(a, sval[k].x, acc4.x);
        acc4.y = fmaf(a, sval[k].y, acc4.y);
        acc4.z = fmaf(a, sval[k].z, acc4.z);
        acc4.w = fmaf(a, sval[k].w, acc4.w);
      }
      if(wih==3){
        float a = attn_s[half][16];
        acc4.x = fmaf(a, sval[4].x, acc4.x);
        acc4.y = fmaf(a, sval[4].y, acc4.y);
        acc4.z = fmaf(a, sval[4].z, acc4.z);
        acc4.w = fmaf(a, sval[4].w, acc4.w);
      }
      *(float4*)&u.s.pagg[half][wih][lane*4] = acc4;
    }
    barhalf(half);
    xagg_s[i*D+tc] = u.s.pagg[half][0][tc] + u.s.pagg[half][1][tc]
                   + u.s.pagg[half][2][tc] + u.s.pagg[half][3][tc];
  }
  __syncthreads();

  // ---- GEMV2: out = agg @ W2 + S*vbp + out_b ----
  {
    float acc[8];
    #pragma unroll
    for(int j=0;j<8;j++) acc[j]=0.f;
    for(int e=0;e<D;e+=4){
      const float4 wq = __ldg((const float4*)g_W2 + (e>>2)*D + tc);
      #pragma unroll
      for(int j=0;j<8;j++){
        const float4 av = *(const float4*)&xagg_s[(half+2*j)*D + e];
        acc[j] = fmaf(av.x,wq.x, fmaf(av.y,wq.y, fmaf(av.z,wq.z, fmaf(av.w,wq.w, acc[j]))));
      }
    }
    float ob = outb[tc], vbp = __ldg(&g_vbp[tc]);
    #pragma unroll
    for(int j=0;j<8;j++){
      int i = half + 2*j;
      int n = n0 + i;
      if(n < N) out[(size_t)n*D+tc] = acc[j] + ob + S_s[i]*vbp;
    }
  }
}

extern "C" void kernel_launch(void* const* d_in, const int* in_sizes, int n_in,
                              void* d_out, int out_size) {
  const float* x      = (const float*)d_in[0];
  const int*   indices= (const int*)  d_in[1];
  const float* img    = (const float*)d_in[2];
  const float* voxel  = (const float*)d_in[3];
  const float* pcr    = (const float*)d_in[4];
  const float* trans  = (const float*)d_in[5];
  const float* offW   = (const float*)d_in[6];
  const float* offb   = (const float*)d_in[7];
  const float* qW     = (const float*)d_in[8];
  const float* qb     = (const float*)d_in[9];
  const float* kW     = (const float*)d_in[10];
  const float* vW     = (const float*)d_in[12];
  const float* vb     = (const float*)d_in[13];
  const float* outW   = (const float*)d_in[14];
  const float* outb   = (const float*)d_in[15];
  const void*  pH     = d_in[16];
  const void*  pW     = d_in[17];

  int N = in_sizes[0]/D;
  int B = in_sizes[5]/12;

  dim3 tb(32,8);
  k_img_transpose<<<dim3(NPIX/32, D/32, B), tb>>>(img);
  k_transpose_kw<<<dim3(D/32, D/32), tb>>>(kW);
  k_prep_mats<<<dim3(D,3), D>>>(qW, vW, outW, kW, qb, vb);
  k_main<<<(N+TP-1)/TP, 256>>>(x, indices, voxel, pcr, trans, offW, offb, outb,
                               pH, pW, (float*)d_out, N);
}

// round 4
// speedup vs baseline: 1.9292x; 1.1034x over previous
#include <cuda_runtime.h>
#include <cuda_fp16.h>

#define D   128
#define P   17
#define HF  56
#define WF  100
#define TP  16
#define NPIX (HF*WF)
#define OWP 132   // padded offWT row (conflict-free LDS.128)

// ---- device scratch ----
__device__ __half g_imgT16[2*NPIX*D];  // [B,H,W,C] fp16
__device__ float g_kT[D*D];            // k_W^T
__device__ float g_Wqk[D*D];           // q_W @ k_W^T, quad-interleaved
__device__ float g_W2[D*D];            // v_W @ out_W,  quad-interleaved
__device__ float g_bqk[D];
__device__ float g_vbp[D];

__constant__ float c_base[2*P] = {
  -1,-1, -1,0, -1,1, 0,-1, 0,0, 0,1, 1,-1, 1,0, 1,1,
  -3,-3, -3,0, -3,3, 0,-3, 0,3, 3,-3, 3,0, 3,3 };

union SmemU {
  float offWT[2*P*OWP];               // Phase A: transposed offset weights
  struct {
    float w[TP][P][4];                // Phase B onward
    int   o[TP][P][4];
    float pagg[2][4][D];
  } s;
};

__device__ __forceinline__ float warpSum(float v){
  #pragma unroll
  for(int o=16;o>0;o>>=1) v += __shfl_xor_sync(0xffffffffu, v, o);
  return v;
}
__device__ __forceinline__ float warpMax(float v){
  #pragma unroll
  for(int o=16;o>0;o>>=1) v = fmaxf(v, __shfl_xor_sync(0xffffffffu, v, o));
  return v;
}
__device__ __forceinline__ int read_dim(const void* p){
  int iv = *(const int*)p;
  if (iv > 0 && iv < 1000000) return iv;
  return (int)(*(const float*)p);
}
__device__ __forceinline__ void barhalf(int half){
  asm volatile("bar.sync %0, 128;" :: "r"(half+1) : "memory");
}

// fp16 bilinear tap: 4 taps x 4 channels (ch 2L,2L+1,64+2L,64+2L+1)
__device__ __forceinline__ float4 sample_point(const float4 wv, const int4 ov, int lane){
  const __half2* base = (const __half2*)g_imgT16;
  __half2 aL=__ldg(base+ov.x+lane), aH=__ldg(base+ov.x+32+lane);
  __half2 bL=__ldg(base+ov.y+lane), bH=__ldg(base+ov.y+32+lane);
  __half2 cL=__ldg(base+ov.z+lane), cH=__ldg(base+ov.z+32+lane);
  __half2 dL=__ldg(base+ov.w+lane), dH=__ldg(base+ov.w+32+lane);
  float2 fa=__half22float2(aL), fb=__half22float2(bL), fc=__half22float2(cL), fd=__half22float2(dL);
  float2 ga=__half22float2(aH), gb=__half22float2(bH), gc=__half22float2(cH), gd=__half22float2(dH);
  float4 s;
  s.x = fmaf(wv.x,fa.x, fmaf(wv.y,fb.x, fmaf(wv.z,fc.x, wv.w*fd.x)));
  s.y = fmaf(wv.x,fa.y, fmaf(wv.y,fb.y, fmaf(wv.z,fc.y, wv.w*fd.y)));
  s.z = fmaf(wv.x,ga.x, fmaf(wv.y,gb.x, fmaf(wv.z,gc.x, wv.w*gd.x)));
  s.w = fmaf(wv.x,ga.y, fmaf(wv.y,gb.y, fmaf(wv.z,gc.y, wv.w*gd.y)));
  return s;
}

// ---- tiled img transpose + fp16 convert: [B,C,H,W] -> [B,H,W,C] ----
__global__ void k_img_transpose(const float* __restrict__ img){
  __shared__ float tile[32][33];
  const int b  = blockIdx.z;
  const int yx0 = blockIdx.x*32, c0 = blockIdx.y*32;
  const int tx = threadIdx.x, ty = threadIdx.y;   // 32x8
  #pragma unroll
  for(int cc=0;cc<32;cc+=8)
    tile[cc+ty][tx] = img[((size_t)(b*D + c0+cc+ty))*NPIX + yx0 + tx];
  __syncthreads();
  #pragma unroll
  for(int yy=0;yy<32;yy+=8)
    g_imgT16[((size_t)(b*NPIX + yx0+yy+ty))*D + c0 + tx] = __float2half(tile[tx][yy+ty]);
}

// ---- tiled kW transpose ----
__global__ void k_transpose_kw(const float* __restrict__ kW){
  __shared__ float tile[32][33];
  const int c0 = blockIdx.x*32, d0 = blockIdx.y*32;
  const int tx = threadIdx.x, ty = threadIdx.y;
  #pragma unroll
  for(int cc=0;cc<32;cc+=8)
    tile[cc+ty][tx] = kW[(c0+cc+ty)*D + d0 + tx];
  __syncthreads();
  #pragma unroll
  for(int yy=0;yy<32;yy+=8)
    g_kT[(d0+yy+ty)*D + c0 + tx] = tile[tx][yy+ty];
}

// ---- matrix + vector preps (quad-interleaved matrices) ----
__global__ void k_prep_mats(const float* __restrict__ qW,
                            const float* __restrict__ vW,
                            const float* __restrict__ outW,
                            const float* __restrict__ kW,
                            const float* __restrict__ qb,
                            const float* __restrict__ vb){
  const int r = blockIdx.x, t = threadIdx.x;
  const int widx = (r>>2)*(4*D) + t*4 + (r&3);
  if (blockIdx.y == 0){
    __shared__ float row[D];
    row[t] = qW[r*D+t]; __syncthreads();
    float acc = 0.f;
    #pragma unroll 4
    for(int dd=0; dd<D; dd++) acc = fmaf(row[dd], g_kT[dd*D+t], acc);
    g_Wqk[widx] = acc;
  } else if (blockIdx.y == 1){
    __shared__ float row[D];
    row[t] = vW[r*D+t]; __syncthreads();
    float acc = 0.f;
    #pragma unroll 4
    for(int dd=0; dd<D; dd++) acc = fmaf(row[dd], outW[dd*D+t], acc);
    g_W2[widx] = acc;
  } else {
    __shared__ float red1[4], red2[4];
    float s1 = qb[t]*kW[r*D+t];
    float s2 = vb[t]*outW[t*D+r];
    s1 = warpSum(s1); s2 = warpSum(s2);
    if((t&31)==0){ red1[t>>5]=s1; red2[t>>5]=s2; }
    __syncthreads();
    if(t==0){
      g_bqk[r] = red1[0]+red1[1]+red1[2]+red1[3];
      g_vbp[r] = red2[0]+red2[1]+red2[2]+red2[3];
    }
  }
}

// ---- main fused kernel ----
__global__ __launch_bounds__(256, 4)
void k_main(const float* __restrict__ x_lidar, const int* __restrict__ indices,
            const float* __restrict__ voxel_size, const float* __restrict__ pc_range,
            const float* __restrict__ trans, const float* __restrict__ offW,
            const float* __restrict__ offb, const float* __restrict__ outb,
            const void* pH, const void* pW, float* __restrict__ out, int N)
{
  const int t    = threadIdx.x;
  const int half = t >> 7;
  const int tc   = t & 127;
  const int lane = t & 31;
  const int wih  = tc >> 5;
  const int w8   = t >> 5;          // warp id 0..7
  const int n0   = blockIdx.x * TP;
  const float du = 2.0f/(WF-1), dv = 2.0f/(HF-1);

  __shared__ __align__(16) float xagg_s[TP*D];
  __shared__ __align__(16) float qk_s[TP*D];
  __shared__ __align__(16) SmemU u;
  __shared__ float learned_s[TP][2*P];
  __shared__ float centers_s[TP][2];
  __shared__ int   boff_s[TP];
  __shared__ float valid_s[TP][P];
  __shared__ float logits_s[2][P];
  __shared__ float S_s[TP];

  // ---- loads: x tile + transposed offWT stage ----
  {
    const float4* xs = (const float4*)x_lidar;
    for(int j=t; j<TP*(D/4); j+=256){
      int pt = j>>5;
      int n = n0+pt; if(n>=N) n = N-1;
      ((float4*)xagg_s)[j] = xs[(size_t)n*(D/4) + (j&31)];
    }
    for(int j=t; j<D*2*P; j+=256){
      int e = j/(2*P), c = j - e*2*P;
      u.offWT[c*OWP + e] = offW[j];
    }
  }
  __syncthreads();

  // ---- Phase A: GEMV1 (qk) ----
  {
    float acc[8];
    #pragma unroll
    for(int j=0;j<8;j++) acc[j]=0.f;
    for(int e=0;e<D;e+=4){
      const float4 wq = __ldg((const float4*)g_Wqk + (e>>2)*D + tc);
      #pragma unroll
      for(int j=0;j<8;j++){
        const float4 xv = *(const float4*)&xagg_s[(half+2*j)*D + e];
        acc[j] = fmaf(xv.x,wq.x, fmaf(xv.y,wq.y, fmaf(xv.z,wq.z, fmaf(xv.w,wq.w, acc[j]))));
      }
    }
    float bq = __ldg(&g_bqk[tc]);
    #pragma unroll
    for(int j=0;j<8;j++) qk_s[(half+2*j)*D+tc] = acc[j]+bq;
  }

  // ---- Phase A: learned offsets (warp owns 2 points, x in regs, weights reused) ----
  {
    const int pt0 = 2*w8, pt1 = 2*w8+1;
    const float4 xr0 = *(const float4*)&xagg_s[pt0*D + 4*lane];
    const float4 xr1 = *(const float4*)&xagg_s[pt1*D + 4*lane];
    const bool extra = lane < 2;
    const int c0 = lane, c1 = 32 + lane;
    float a00=0.f, a01=0.f, a10=0.f, a11=0.f;
    #pragma unroll 4
    for(int g=0; g<32; g++){
      const float4 w4 = *(const float4*)&u.offWT[c0*OWP + 4*g];
      float4 w4b;
      if(extra) w4b = *(const float4*)&u.offWT[c1*OWP + 4*g];
      float4 xv0, xv1;
      xv0.x=__shfl_sync(0xffffffffu,xr0.x,g); xv0.y=__shfl_sync(0xffffffffu,xr0.y,g);
      xv0.z=__shfl_sync(0xffffffffu,xr0.z,g); xv0.w=__shfl_sync(0xffffffffu,xr0.w,g);
      xv1.x=__shfl_sync(0xffffffffu,xr1.x,g); xv1.y=__shfl_sync(0xffffffffu,xr1.y,g);
      xv1.z=__shfl_sync(0xffffffffu,xr1.z,g); xv1.w=__shfl_sync(0xffffffffu,xr1.w,g);
      a00 = fmaf(w4.x,xv0.x, fmaf(w4.y,xv0.y, fmaf(w4.z,xv0.z, fmaf(w4.w,xv0.w, a00))));
      a10 = fmaf(w4.x,xv1.x, fmaf(w4.y,xv1.y, fmaf(w4.z,xv1.z, fmaf(w4.w,xv1.w, a10))));
      if(extra){
        a01 = fmaf(w4b.x,xv0.x, fmaf(w4b.y,xv0.y, fmaf(w4b.z,xv0.z, fmaf(w4b.w,xv0.w, a01))));
        a11 = fmaf(w4b.x,xv1.x, fmaf(w4b.y,xv1.y, fmaf(w4b.z,xv1.z, fmaf(w4b.w,xv1.w, a11))));
      }
    }
    float sc0 = (c0&1)? 1.5f*dv : 1.5f*du;
    learned_s[pt0][c0] = tanhf(a00 + offb[c0]) * sc0;
    learned_s[pt1][c0] = tanhf(a10 + offb[c0]) * sc0;
    if(extra){
      float sc1 = (c1&1)? 1.5f*dv : 1.5f*du;
      learned_s[pt0][c1] = tanhf(a01 + offb[c1]) * sc1;
      learned_s[pt1][c1] = tanhf(a11 + offb[c1]) * sc1;
    }
  }
  if(t < TP){
    int n = min(n0+t, N-1);
    const int4 idx = *(const int4*)(indices + (size_t)n*4);
    float cvx=voxel_size[0]*8.f, cvy=voxel_size[1]*8.f, cvz=voxel_size[2]*8.f;
    float phx = (float)idx.w*cvx + pc_range[0] + 0.5f*cvx;
    float phy = (float)idx.z*cvy + pc_range[1] + 0.5f*cvy;
    float phz = (float)idx.y*cvz + pc_range[2] + 0.5f*cvz;
    const float* T = trans + idx.x*12;
    float p0 = T[0]*phx + T[1]*phy + T[2]*phz  + T[3];
    float p1 = T[4]*phx + T[5]*phy + T[6]*phz  + T[7];
    float p2 = T[8]*phx + T[9]*phy + T[10]*phz + T[11];
    float depth = fmaxf(p2, 1e-5f);
    const int Wi = read_dim(pW), Hi = read_dim(pH);
    float uf = p0/depth * ((float)WF/(float)Wi);
    float vf = p1/depth * ((float)HF/(float)Hi);
    centers_s[t][0] = uf*du - 1.0f;
    centers_s[t][1] = vf*dv - 1.0f;
    boff_s[t] = idx.x * NPIX;
  }
  __syncthreads();

  // ---- Phase B: geometry (overwrites offWT union) ----
  for(int j=t; j<TP*P; j+=256){
    int pt = j/P, p = j - pt*P;
    float gx = centers_s[pt][0] + c_base[2*p]  *du + learned_s[pt][2*p];
    float gy = centers_s[pt][1] + c_base[2*p+1]*dv + learned_s[pt][2*p+1];
    valid_s[pt][p] = (fabsf(gx)<=1.f && fabsf(gy)<=1.f) ? 1.f : 0.f;
    float px = (gx+1.f)*0.5f*(WF-1);
    float py = (gy+1.f)*0.5f*(HF-1);
    float fxf = floorf(px), fyf = floorf(py);
    int x0=(int)fxf, y0=(int)fyf;
    float fx = px-fxf, fy = py-fyf;
    int bb = boff_s[pt];
    #pragma unroll
    for(int tap=0;tap<4;tap++){
      int xc = x0 + (tap&1), yc = y0 + (tap>>1);
      bool inb = (xc>=0 && xc<WF && yc>=0 && yc<HF);
      float wx = (tap&1)? fx : 1.f-fx;
      float wy = (tap>>1)? fy : 1.f-fy;
      u.s.w[pt][p][tap] = inb ? wx*wy : 0.f;
      int xcc = min(max(xc,0),WF-1), ycc = min(max(yc,0),HF-1);
      u.s.o[pt][p][tap] = (bb + ycc*WF + xcc)*(D/2);   // half2 index
    }
  }
  __syncthreads();

  const float scale = 0.17677669529663687f;

  // ---- main loop: each half owns points of its parity ----
  for(int ii=0; ii<TP; ii+=2){
    const int i = ii + half;
    const float2 qa = *(const float2*)&qk_s[i*D + 2*lane];
    const float2 qb2 = *(const float2*)&qk_s[i*D + 64 + 2*lane];
    float4 sval[5];

    #pragma unroll
    for(int k=0;k<4;k++){
      const int p = wih + 4*k;
      const float4 wv = *(const float4*)u.s.w[i][p];
      const int4  ov = *(const int4*) u.s.o[i][p];
      float4 s = sample_point(wv, ov, lane);
      sval[k] = s;
      float dt = fmaf(s.x,qa.x, fmaf(s.y,qa.y, fmaf(s.z,qb2.x, s.w*qb2.y)));
      dt = warpSum(dt);
      if(lane==0) logits_s[half][p] = dt;
    }
    if(wih==3){
      const float4 wv = *(const float4*)u.s.w[i][16];
      const int4  ov = *(const int4*) u.s.o[i][16];
      float4 s = sample_point(wv, ov, lane);
      sval[4] = s;
      float dt = fmaf(s.x,qa.x, fmaf(s.y,qa.y, fmaf(s.z,qb2.x, s.w*qb2.y)));
      dt = warpSum(dt);
      if(lane==0) logits_s[half][16] = dt;
    }
    barhalf(half);

    // softmax in every warp (lanes = points); aux written by wih==0 only
    float myA;
    {
      const bool act = lane < P;
      float vld = act ? valid_s[i][lane] : 0.f;
      float l = act ? ((vld>0.f) ? logits_s[half][lane]*scale : -10000.f)
                    : -3.0e38f;
      float mx = warpMax(l);
      float e  = act ? expf(l - mx) : 0.f;
      float se = warpSum(e);
      float a1 = e * (1.f/se) * vld;
      float S  = warpSum(a1);
      myA = a1 * (1.f/fmaxf(S, 1e-6f));
      if(!act) myA = 0.f;
      if(wih==0){
        float S2 = warpSum(myA);
        float pc = fmaxf(myA, 1e-6f);
        float ent = warpSum(act ? -pc*logf(pc) : 0.f);
        float vcnt = warpSum(vld);
        float lx = act ? learned_s[i][2*lane]   : 0.f;
        float ly = act ? learned_s[i][2*lane+1] : 0.f;
        float nrm = warpSum(act ? sqrtf(lx*lx+ly*ly) : 0.f);
        if(lane==0){
          S_s[i] = S2;
          int n = n0 + i;
          if(n < N){
            float inst = (nrm/(float)P) / (1.5f*sqrtf(du*du+dv*dv));
            size_t base = (size_t)N*D;
            out[base + n]               = vcnt/(float)P;
            out[base + (size_t)N + n]   = fminf(fmaxf(expf(-inst),0.f),1.f);
            out[base + 2*(size_t)N + n] = fminf(fmaxf(1.f - ent/logf((float)P),0.f),1.f);
          }
        }
      }
    }

    // aggregate in registers with shfl-broadcast attn, then cross-warp combine
    {
      float4 acc4 = make_float4(0.f,0.f,0.f,0.f);
      #pragma unroll
      for(int k=0;k<4;k++){
        float a = __shfl_sync(0xffffffffu, myA, wih+4*k);
        acc4.x = fmaf(a, sval[k].x, acc4.x);
        acc4.y = fmaf(a, sval[k].y, acc4.y);
        acc4.z = fmaf(a, sval[k].z, acc4.z);
        acc4.w = fmaf(a, sval[k].w, acc4.w);
      }
      float a16 = __shfl_sync(0xffffffffu, myA, 16);
      if(wih==3){
        acc4.x = fmaf(a16, sval[4].x, acc4.x);
        acc4.y = fmaf(a16, sval[4].y, acc4.y);
        acc4.z = fmaf(a16, sval[4].z, acc4.z);
        acc4.w = fmaf(a16, sval[4].w, acc4.w);
      }
      *(float2*)&u.s.pagg[half][wih][2*lane]      = make_float2(acc4.x, acc4.y);
      *(float2*)&u.s.pagg[half][wih][64 + 2*lane] = make_float2(acc4.z, acc4.w);
    }
    barhalf(half);
    xagg_s[i*D+tc] = u.s.pagg[half][0][tc] + u.s.pagg[half][1][tc]
                   + u.s.pagg[half][2][tc] + u.s.pagg[half][3][tc];
  }
  __syncthreads();

  // ---- GEMV2: out = agg @ W2 + S*vbp + out_b ----
  {
    float acc[8];
    #pragma unroll
    for(int j=0;j<8;j++) acc[j]=0.f;
    for(int e=0;e<D;e+=4){
      const float4 wq = __ldg((const float4*)g_W2 + (e>>2)*D + tc);
      #pragma unroll
      for(int j=0;j<8;j++){
        const float4 av = *(const float4*)&xagg_s[(half+2*j)*D + e];
        acc[j] = fmaf(av.x,wq.x, fmaf(av.y,wq.y, fmaf(av.z,wq.z, fmaf(av.w,wq.w, acc[j]))));
      }
    }
    float ob = outb[tc], vbp = __ldg(&g_vbp[tc]);
    #pragma unroll
    for(int j=0;j<8;j++){
      int i = half + 2*j;
      int n = n0 + i;
      if(n < N) out[(size_t)n*D+tc] = acc[j] + ob + S_s[i]*vbp;
    }
  }
}

extern "C" void kernel_launch(void* const* d_in, const int* in_sizes, int n_in,
                              void* d_out, int out_size) {
  const float* x      = (const float*)d_in[0];
  const int*   indices= (const int*)  d_in[1];
  const float* img    = (const float*)d_in[2];
  const float* voxel  = (const float*)d_in[3];
  const float* pcr    = (const float*)d_in[4];
  const float* trans  = (const float*)d_in[5];
  const float* offW   = (const float*)d_in[6];
  const float* offb   = (const float*)d_in[7];
  const float* qW     = (const float*)d_in[8];
  const float* qb     = (const float*)d_in[9];
  const float* kW     = (const float*)d_in[10];
  const float* vW     = (const float*)d_in[12];
  const float* vb     = (const float*)d_in[13];
  const float* outW   = (const float*)d_in[14];
  const float* outb   = (const float*)d_in[15];
  const void*  pH     = d_in[16];
  const void*  pW     = d_in[17];

  int N = in_sizes[0]/D;
  int B = in_sizes[5]/12;

  dim3 tb(32,8);
  k_img_transpose<<<dim3(NPIX/32, D/32, B), tb>>>(img);
  k_transpose_kw<<<dim3(D/32, D/32), tb>>>(kW);
  k_prep_mats<<<dim3(D,3), D>>>(qW, vW, outW, kW, qb, vb);
  k_main<<<(N+TP-1)/TP, 256>>>(x, indices, voxel, pcr, trans, offW, offb, outb,
                               pH, pW, (float*)d_out, N);
}

// round 5
// speedup vs baseline: 2.0539x; 1.0647x over previous
#include <cuda_runtime.h>
#include <cuda_fp16.h>

#define D   128
#define P   17
#define HF  56
#define WF  100
#define TP  16
#define NPIX (HF*WF)
#define OWP 132   // padded offWT row (conflict-free LDS.128)

// ---- device scratch ----
__device__ __half g_imgT16[2*NPIX*D];            // [B,H,W,C] fp16
__device__ float g_kT[D*D];                      // k_W^T
// fp16 GEMV weights, layout: half idx = ((e/4)*64 + ch/2)*8 + (e%4)*2 + (ch%2)
__device__ __align__(16) __half g_Wqk16[D*D];
__device__ __align__(16) __half g_W216[D*D];
__device__ float g_bqk[D];
__device__ float g_vbp[D];

__constant__ float c_base[2*P] = {
  -1,-1, -1,0, -1,1, 0,-1, 0,0, 0,1, 1,-1, 1,0, 1,1,
  -3,-3, -3,0, -3,3, 0,-3, 0,3, 3,-3, 3,0, 3,3 };

union SmemU {
  float offWT[2*P*OWP];               // Phase A: transposed offset weights
  struct {
    float w[TP][P][4];                // Phase B onward
    int   o[TP][P][4];
    float pagg[2][4][D];
  } s;
};

__device__ __forceinline__ float warpSum(float v){
  #pragma unroll
  for(int o=16;o>0;o>>=1) v += __shfl_xor_sync(0xffffffffu, v, o);
  return v;
}
__device__ __forceinline__ float warpMax(float v){
  #pragma unroll
  for(int o=16;o>0;o>>=1) v = fmaxf(v, __shfl_xor_sync(0xffffffffu, v, o));
  return v;
}
__device__ __forceinline__ int read_dim(const void* p){
  int iv = *(const int*)p;
  if (iv > 0 && iv < 1000000) return iv;
  return (int)(*(const float*)p);
}
__device__ __forceinline__ void barhalf(int half){
  asm volatile("bar.sync %0, 128;" :: "r"(half+1) : "memory");
}

// fp16 bilinear tap: 4 taps x 4 channels (ch 2L,2L+1,64+2L,64+2L+1)
__device__ __forceinline__ float4 sample_point(const float4 wv, const int4 ov, int lane){
  const __half2* base = (const __half2*)g_imgT16;
  __half2 aL=__ldg(base+ov.x+lane), aH=__ldg(base+ov.x+32+lane);
  __half2 bL=__ldg(base+ov.y+lane), bH=__ldg(base+ov.y+32+lane);
  __half2 cL=__ldg(base+ov.z+lane), cH=__ldg(base+ov.z+32+lane);
  __half2 dL=__ldg(base+ov.w+lane), dH=__ldg(base+ov.w+32+lane);
  float2 fa=__half22float2(aL), fb=__half22float2(bL), fc=__half22float2(cL), fd=__half22float2(dL);
  float2 ga=__half22float2(aH), gb=__half22float2(bH), gc=__half22float2(cH), gd=__half22float2(dH);
  float4 s;
  s.x = fmaf(wv.x,fa.x, fmaf(wv.y,fb.x, fmaf(wv.z,fc.x, wv.w*fd.x)));
  s.y = fmaf(wv.x,fa.y, fmaf(wv.y,fb.y, fmaf(wv.z,fc.y, wv.w*fd.y)));
  s.z = fmaf(wv.x,ga.x, fmaf(wv.y,gb.x, fmaf(wv.z,gc.x, wv.w*gd.x)));
  s.w = fmaf(wv.x,ga.y, fmaf(wv.y,gb.y, fmaf(wv.z,gc.y, wv.w*gd.y)));
  return s;
}

// ---- tiled img transpose + fp16 convert ----
__global__ void k_img_transpose(const float* __restrict__ img){
  __shared__ float tile[32][33];
  const int b  = blockIdx.z;
  const int yx0 = blockIdx.x*32, c0 = blockIdx.y*32;
  const int tx = threadIdx.x, ty = threadIdx.y;   // 32x8
  #pragma unroll
  for(int cc=0;cc<32;cc+=8)
    tile[cc+ty][tx] = img[((size_t)(b*D + c0+cc+ty))*NPIX + yx0 + tx];
  __syncthreads();
  #pragma unroll
  for(int yy=0;yy<32;yy+=8)
    g_imgT16[((size_t)(b*NPIX + yx0+yy+ty))*D + c0 + tx] = __float2half(tile[tx][yy+ty]);
}

// ---- tiled kW transpose ----
__global__ void k_transpose_kw(const float* __restrict__ kW){
  __shared__ float tile[32][33];
  const int c0 = blockIdx.x*32, d0 = blockIdx.y*32;
  const int tx = threadIdx.x, ty = threadIdx.y;
  #pragma unroll
  for(int cc=0;cc<32;cc+=8)
    tile[cc+ty][tx] = kW[(c0+cc+ty)*D + d0 + tx];
  __syncthreads();
  #pragma unroll
  for(int yy=0;yy<32;yy+=8)
    g_kT[(d0+yy+ty)*D + c0 + tx] = tile[tx][yy+ty];
}

// ---- matrix + vector preps (fp16, GEMV-tiled layout) ----
__global__ void k_prep_mats(const float* __restrict__ qW,
                            const float* __restrict__ vW,
                            const float* __restrict__ outW,
                            const float* __restrict__ kW,
                            const float* __restrict__ qb,
                            const float* __restrict__ vb){
  const int r = blockIdx.x, t = threadIdx.x;   // r = e, t = ch
  const int hidx = ((r>>2)*64 + (t>>1))*8 + (r&3)*2 + (t&1);
  if (blockIdx.y == 0){
    __shared__ float row[D];
    row[t] = qW[r*D+t]; __syncthreads();
    float acc = 0.f;
    #pragma unroll 4
    for(int dd=0; dd<D; dd++) acc = fmaf(row[dd], g_kT[dd*D+t], acc);
    g_Wqk16[hidx] = __float2half(acc);
  } else if (blockIdx.y == 1){
    __shared__ float row[D];
    row[t] = vW[r*D+t]; __syncthreads();
    float acc = 0.f;
    #pragma unroll 4
    for(int dd=0; dd<D; dd++) acc = fmaf(row[dd], outW[dd*D+t], acc);
    g_W216[hidx] = __float2half(acc);
  } else {
    __shared__ float red1[4], red2[4];
    float s1 = qb[t]*kW[r*D+t];
    float s2 = vb[t]*outW[t*D+r];
    s1 = warpSum(s1); s2 = warpSum(s2);
    if((t&31)==0){ red1[t>>5]=s1; red2[t>>5]=s2; }
    __syncthreads();
    if(t==0){
      g_bqk[r] = red1[0]+red1[1]+red1[2]+red1[3];
      g_vbp[r] = red2[0]+red2[1]+red2[2]+red2[3];
    }
  }
}

// (p=4, c=2) batched GEMV: warp w8 handles points pa..pa+3, channels chh*64+2*lane{,+1}
__device__ __forceinline__ void gemv_p4c2(const __half* Wh, const float* __restrict__ in_s,
                                          float2 acc[4], int chh, int pa, int lane){
  #pragma unroll 4
  for(int eg=0; eg<32; eg++){
    const float4 raw = __ldg((const float4*)Wh + eg*64 + chh*32 + lane);
    const __half2* hw = (const __half2*)&raw;
    const float2 w0 = __half22float2(hw[0]);
    const float2 w1 = __half22float2(hw[1]);
    const float2 w2 = __half22float2(hw[2]);
    const float2 w3 = __half22float2(hw[3]);
    #pragma unroll
    for(int j=0;j<4;j++){
      const float4 xv = *(const float4*)&in_s[(pa+j)*D + 4*eg];
      acc[j].x = fmaf(xv.x,w0.x, fmaf(xv.y,w1.x, fmaf(xv.z,w2.x, fmaf(xv.w,w3.x, acc[j].x))));
      acc[j].y = fmaf(xv.x,w0.y, fmaf(xv.y,w1.y, fmaf(xv.z,w2.y, fmaf(xv.w,w3.y, acc[j].y))));
    }
  }
}

// ---- main fused kernel ----
__global__ __launch_bounds__(256, 4)
void k_main(const float* __restrict__ x_lidar, const int* __restrict__ indices,
            const float* __restrict__ voxel_size, const float* __restrict__ pc_range,
            const float* __restrict__ trans, const float* __restrict__ offW,
            const float* __restrict__ offb, const float* __restrict__ outb,
            const void* pH, const void* pW, float* __restrict__ out, int N)
{
  const int t    = threadIdx.x;
  const int half = t >> 7;
  const int tc   = t & 127;
  const int lane = t & 31;
  const int wih  = tc >> 5;
  const int w8   = t >> 5;          // warp id 0..7
  const int chh  = w8 >> 2;         // GEMV ch-half
  const int pa   = (w8 & 3) * 4;    // GEMV first point
  const int n0   = blockIdx.x * TP;
  const float du = 2.0f/(WF-1), dv = 2.0f/(HF-1);

  __shared__ __align__(16) float xagg_s[TP*D];
  __shared__ __align__(16) float qk_s[TP*D];
  __shared__ __align__(16) SmemU u;
  __shared__ float learned_s[TP][2*P];
  __shared__ float centers_s[TP][2];
  __shared__ int   boff_s[TP];
  __shared__ float valid_s[TP][P];
  __shared__ float logits_s[2][P];
  __shared__ float S_s[TP];

  // ---- loads: x tile + transposed offWT stage ----
  {
    const float4* xs = (const float4*)x_lidar;
    for(int j=t; j<TP*(D/4); j+=256){
      int pt = j>>5;
      int n = n0+pt; if(n>=N) n = N-1;
      ((float4*)xagg_s)[j] = xs[(size_t)n*(D/4) + (j&31)];
    }
    for(int j=t; j<D*2*P; j+=256){
      int e = j/(2*P), c = j - e*2*P;
      u.offWT[c*OWP + e] = offW[j];
    }
  }
  __syncthreads();

  // ---- Phase A: GEMV1 (qk), (p=4,c=2) fp16 weights ----
  {
    float2 acc[4];
    #pragma unroll
    for(int j=0;j<4;j++) acc[j] = make_float2(0.f,0.f);
    gemv_p4c2(g_Wqk16, xagg_s, acc, chh, pa, lane);
    const int ch0 = chh*64 + 2*lane;
    const float2 bq = *(const float2*)&g_bqk[ch0];
    #pragma unroll
    for(int j=0;j<4;j++)
      *(float2*)&qk_s[(pa+j)*D + ch0] = make_float2(acc[j].x+bq.x, acc[j].y+bq.y);
  }

  // ---- Phase A: learned offsets (warp owns 2 points, x via shfl, weights LDS) ----
  {
    const int pt0 = 2*w8, pt1 = 2*w8+1;
    const float4 xr0 = *(const float4*)&xagg_s[pt0*D + 4*lane];
    const float4 xr1 = *(const float4*)&xagg_s[pt1*D + 4*lane];
    const bool extra = lane < 2;
    const int c0 = lane, c1 = 32 + lane;
    float a00=0.f, a01=0.f, a10=0.f, a11=0.f;
    #pragma unroll 4
    for(int g=0; g<32; g++){
      const float4 w4 = *(const float4*)&u.offWT[c0*OWP + 4*g];
      float4 w4b;
      if(extra) w4b = *(const float4*)&u.offWT[c1*OWP + 4*g];
      float4 xv0, xv1;
      xv0.x=__shfl_sync(0xffffffffu,xr0.x,g); xv0.y=__shfl_sync(0xffffffffu,xr0.y,g);
      xv0.z=__shfl_sync(0xffffffffu,xr0.z,g); xv0.w=__shfl_sync(0xffffffffu,xr0.w,g);
      xv1.x=__shfl_sync(0xffffffffu,xr1.x,g); xv1.y=__shfl_sync(0xffffffffu,xr1.y,g);
      xv1.z=__shfl_sync(0xffffffffu,xr1.z,g); xv1.w=__shfl_sync(0xffffffffu,xr1.w,g);
      a00 = fmaf(w4.x,xv0.x, fmaf(w4.y,xv0.y, fmaf(w4.z,xv0.z, fmaf(w4.w,xv0.w, a00))));
      a10 = fmaf(w4.x,xv1.x, fmaf(w4.y,xv1.y, fmaf(w4.z,xv1.z, fmaf(w4.w,xv1.w, a10))));
      if(extra){
        a01 = fmaf(w4b.x,xv0.x, fmaf(w4b.y,xv0.y, fmaf(w4b.z,xv0.z, fmaf(w4b.w,xv0.w, a01))));
        a11 = fmaf(w4b.x,xv1.x, fmaf(w4b.y,xv1.y, fmaf(w4b.z,xv1.z, fmaf(w4b.w,xv1.w, a11))));
      }
    }
    float sc0 = (c0&1)? 1.5f*dv : 1.5f*du;
    learned_s[pt0][c0] = tanhf(a00 + offb[c0]) * sc0;
    learned_s[pt1][c0] = tanhf(a10 + offb[c0]) * sc0;
    if(extra){
      float sc1 = (c1&1)? 1.5f*dv : 1.5f*du;
      learned_s[pt0][c1] = tanhf(a01 + offb[c1]) * sc1;
      learned_s[pt1][c1] = tanhf(a11 + offb[c1]) * sc1;
    }
  }
  if(t < TP){
    int n = min(n0+t, N-1);
    const int4 idx = *(const int4*)(indices + (size_t)n*4);
    float cvx=voxel_size[0]*8.f, cvy=voxel_size[1]*8.f, cvz=voxel_size[2]*8.f;
    float phx = (float)idx.w*cvx + pc_range[0] + 0.5f*cvx;
    float phy = (float)idx.z*cvy + pc_range[1] + 0.5f*cvy;
    float phz = (float)idx.y*cvz + pc_range[2] + 0.5f*cvz;
    const float* T = trans + idx.x*12;
    float p0 = T[0]*phx + T[1]*phy + T[2]*phz  + T[3];
    float p1 = T[4]*phx + T[5]*phy + T[6]*phz  + T[7];
    float p2 = T[8]*phx + T[9]*phy + T[10]*phz + T[11];
    float depth = fmaxf(p2, 1e-5f);
    const int Wi = read_dim(pW), Hi = read_dim(pH);
    float uf = p0/depth * ((float)WF/(float)Wi);
    float vf = p1/depth * ((float)HF/(float)Hi);
    centers_s[t][0] = uf*du - 1.0f;
    centers_s[t][1] = vf*dv - 1.0f;
    boff_s[t] = idx.x * NPIX;
  }
  __syncthreads();

  // ---- Phase B: geometry (overwrites offWT union) ----
  for(int j=t; j<TP*P; j+=256){
    int pt = j/P, p = j - pt*P;
    float gx = centers_s[pt][0] + c_base[2*p]  *du + learned_s[pt][2*p];
    float gy = centers_s[pt][1] + c_base[2*p+1]*dv + learned_s[pt][2*p+1];
    valid_s[pt][p] = (fabsf(gx)<=1.f && fabsf(gy)<=1.f) ? 1.f : 0.f;
    float px = (gx+1.f)*0.5f*(WF-1);
    float py = (gy+1.f)*0.5f*(HF-1);
    float fxf = floorf(px), fyf = floorf(py);
    int x0=(int)fxf, y0=(int)fyf;
    float fx = px-fxf, fy = py-fyf;
    int bb = boff_s[pt];
    #pragma unroll
    for(int tap=0;tap<4;tap++){
      int xc = x0 + (tap&1), yc = y0 + (tap>>1);
      bool inb = (xc>=0 && xc<WF && yc>=0 && yc<HF);
      float wx = (tap&1)? fx : 1.f-fx;
      float wy = (tap>>1)? fy : 1.f-fy;
      u.s.w[pt][p][tap] = inb ? wx*wy : 0.f;
      int xcc = min(max(xc,0),WF-1), ycc = min(max(yc,0),HF-1);
      u.s.o[pt][p][tap] = (bb + ycc*WF + xcc)*(D/2);   // half2 index
    }
  }
  __syncthreads();

  const float scale = 0.17677669529663687f;

  // ---- main loop: each half owns points of its parity ----
  for(int ii=0; ii<TP; ii+=2){
    const int i = ii + half;
    const float2 qa = *(const float2*)&qk_s[i*D + 2*lane];
    const float2 qb2 = *(const float2*)&qk_s[i*D + 64 + 2*lane];
    float4 sval[5];

    #pragma unroll
    for(int k=0;k<4;k++){
      const int p = wih + 4*k;
      const float4 wv = *(const float4*)u.s.w[i][p];
      const int4  ov = *(const int4*) u.s.o[i][p];
      float4 s = sample_point(wv, ov, lane);
      sval[k] = s;
      float dt = fmaf(s.x,qa.x, fmaf(s.y,qa.y, fmaf(s.z,qb2.x, s.w*qb2.y)));
      dt = warpSum(dt);
      if(lane==0) logits_s[half][p] = dt;
    }
    if(wih==3){
      const float4 wv = *(const float4*)u.s.w[i][16];
      const int4  ov = *(const int4*) u.s.o[i][16];
      float4 s = sample_point(wv, ov, lane);
      sval[4] = s;
      float dt = fmaf(s.x,qa.x, fmaf(s.y,qa.y, fmaf(s.z,qb2.x, s.w*qb2.y)));
      dt = warpSum(dt);
      if(lane==0) logits_s[half][16] = dt;
    }
    barhalf(half);

    // softmax in every warp (lanes = points); aux written by wih==0 only
    float myA;
    {
      const bool act = lane < P;
      float vld = act ? valid_s[i][lane] : 0.f;
      float l = act ? ((vld>0.f) ? logits_s[half][lane]*scale : -10000.f)
                    : -3.0e38f;
      float mx = warpMax(l);
      float e  = act ? expf(l - mx) : 0.f;
      float se = warpSum(e);
      float a1 = e * (1.f/se) * vld;
      float S  = warpSum(a1);
      myA = a1 * (1.f/fmaxf(S, 1e-6f));
      if(!act) myA = 0.f;
      if(wih==0){
        float S2 = warpSum(myA);
        float pc = fmaxf(myA, 1e-6f);
        float ent = warpSum(act ? -pc*logf(pc) : 0.f);
        float vcnt = warpSum(vld);
        float lx = act ? learned_s[i][2*lane]   : 0.f;
        float ly = act ? learned_s[i][2*lane+1] : 0.f;
        float nrm = warpSum(act ? sqrtf(lx*lx+ly*ly) : 0.f);
        if(lane==0){
          S_s[i] = S2;
          int n = n0 + i;
          if(n < N){
            float inst = (nrm/(float)P) / (1.5f*sqrtf(du*du+dv*dv));
            size_t base = (size_t)N*D;
            out[base + n]               = vcnt/(float)P;
            out[base + (size_t)N + n]   = fminf(fmaxf(expf(-inst),0.f),1.f);
            out[base + 2*(size_t)N + n] = fminf(fmaxf(1.f - ent/logf((float)P),0.f),1.f);
          }
        }
      }
    }

    // aggregate in registers with shfl-broadcast attn, then cross-warp combine
    {
      float4 acc4 = make_float4(0.f,0.f,0.f,0.f);
      #pragma unroll
      for(int k=0;k<4;k++){
        float a = __shfl_sync(0xffffffffu, myA, wih+4*k);
        acc4.x = fmaf(a, sval[k].x, acc4.x);
        acc4.y = fmaf(a, sval[k].y, acc4.y);
        acc4.z = fmaf(a, sval[k].z, acc4.z);
        acc4.w = fmaf(a, sval[k].w, acc4.w);
      }
      float a16 = __shfl_sync(0xffffffffu, myA, 16);
      if(wih==3){
        acc4.x = fmaf(a16, sval[4].x, acc4.x);
        acc4.y = fmaf(a16, sval[4].y, acc4.y);
        acc4.z = fmaf(a16, sval[4].z, acc4.z);
        acc4.w = fmaf(a16, sval[4].w, acc4.w);
      }
      *(float2*)&u.s.pagg[half][wih][2*lane]      = make_float2(acc4.x, acc4.y);
      *(float2*)&u.s.pagg[half][wih][64 + 2*lane] = make_float2(acc4.z, acc4.w);
    }
    barhalf(half);
    xagg_s[i*D+tc] = u.s.pagg[half][0][tc] + u.s.pagg[half][1][tc]
                   + u.s.pagg[half][2][tc] + u.s.pagg[half][3][tc];
  }
  __syncthreads();

  // ---- GEMV2: out = agg @ W2 + S*vbp + out_b, (p=4,c=2) fp16 ----
  {
    float2 acc[4];
    #pragma unroll
    for(int j=0;j<4;j++) acc[j] = make_float2(0.f,0.f);
    gemv_p4c2(g_W216, xagg_s, acc, chh, pa, lane);
    const int ch0 = chh*64 + 2*lane;
    const float2 ob  = *(const float2*)&outb[ch0];
    const float2 vbp = *(const float2*)&g_vbp[ch0];
    #pragma unroll
    for(int j=0;j<4;j++){
      int i = pa + j;
      int n = n0 + i;
      if(n < N){
        float S = S_s[i];
        float2 r = make_float2(acc[j].x + ob.x + S*vbp.x,
                               acc[j].y + ob.y + S*vbp.y);
        *(float2*)&out[(size_t)n*D + ch0] = r;
      }
    }
  }
}

extern "C" void kernel_launch(void* const* d_in, const int* in_sizes, int n_in,
                              void* d_out, int out_size) {
  const float* x      = (const float*)d_in[0];
  const int*   indices= (const int*)  d_in[1];
  const float* img    = (const float*)d_in[2];
  const float* voxel  = (const float*)d_in[3];
  const float* pcr    = (const float*)d_in[4];
  const float* trans  = (const float*)d_in[5];
  const float* offW   = (const float*)d_in[6];
  const float* offb   = (const float*)d_in[7];
  const float* qW     = (const float*)d_in[8];
  const float* qb     = (const float*)d_in[9];
  const float* kW     = (const float*)d_in[10];
  const float* vW     = (const float*)d_in[12];
  const float* vb     = (const float*)d_in[13];
  const float* outW   = (const float*)d_in[14];
  const float* outb   = (const float*)d_in[15];
  const void*  pH     = d_in[16];
  const void*  pW     = d_in[17];

  int N = in_sizes[0]/D;
  int B = in_sizes[5]/12;

  dim3 tb(32,8);
  k_img_transpose<<<dim3(NPIX/32, D/32, B), tb>>>(img);
  k_transpose_kw<<<dim3(D/32, D/32), tb>>>(kW);
  k_prep_mats<<<dim3(D,3), D>>>(qW, vW, outW, kW, qb, vb);
  k_main<<<(N+TP-1)/TP, 256>>>(x, indices, voxel, pcr, trans, offW, offb, outb,
                               pH, pW, (float*)d_out, N);
}

// round 8
// speedup vs baseline: 2.6251x; 1.2781x over previous
#include <cuda_runtime.h>
#include <cuda_fp16.h>
#include <cstdint>

#define D   128
#define P   17
#define HF  56
#define WF  100
#define TP  16
#define NPIX (HF*WF)
#define OWP 132   // padded offWT row (conflict-free LDS.128)
#define XHP 136   // fp16 x-tile row pitch (halves)

// ---- device scratch ----
__device__ __half g_imgT16[2*NPIX*D];            // [B,H,W,C] fp16
__device__ float g_kT[D*D];                      // k_W^T
// fragment-linear fp16 weights for mma.m16n8k16 (B operand, col-major frags)
__device__ __align__(16) __half g_Wqkf[D*D];
__device__ __align__(16) __half g_W2f[D*D];
__device__ float g_bqk[D];
__device__ float g_vbp[D];

__constant__ float c_base[2*P] = {
  -1,-1, -1,0, -1,1, 0,-1, 0,0, 0,1, 1,-1, 1,0, 1,1,
  -3,-3, -3,0, -3,3, 0,-3, 0,3, 3,-3, 3,0, 3,3 };

union SmemU {
  float offWT[2*P*OWP];               // Phase A: transposed offset weights
  struct {
    float w[TP][P][4];                // Phase B onward
    int   o[TP][P][4];
    float pagg[2][4][D];
  } s;
};

__device__ __forceinline__ float warpSum(float v){
  #pragma unroll
  for(int o=16;o>0;o>>=1) v += __shfl_xor_sync(0xffffffffu, v, o);
  return v;
}
__device__ __forceinline__ float warpMax(float v){
  #pragma unroll
  for(int o=16;o>0;o>>=1) v = fmaxf(v, __shfl_xor_sync(0xffffffffu, v, o));
  return v;
}
__device__ __forceinline__ int read_dim(const void* p){
  int iv = *(const int*)p;
  if (iv > 0 && iv < 1000000) return iv;
  return (int)(*(const float*)p);
}
__device__ __forceinline__ void barhalf(int half){
  asm volatile("bar.sync %0, 128;" :: "r"(half+1) : "memory");
}
__device__ __forceinline__ unsigned int smem_u32(const void* p){
  return (unsigned int)__cvta_generic_to_shared(p);
}
__device__ __forceinline__ void ldmatrix_x4(unsigned int r[4], unsigned int addr){
  asm volatile("ldmatrix.sync.aligned.m8n8.x4.shared.b16 {%0,%1,%2,%3}, [%4];"
    : "=r"(r[0]),"=r"(r[1]),"=r"(r[2]),"=r"(r[3]) : "r"(addr));
}
__device__ __forceinline__ void mma16816(float4& d, const unsigned int a[4], uint2 b){
  asm volatile("mma.sync.aligned.m16n8k16.row.col.f32.f16.f16.f32 "
    "{%0,%1,%2,%3}, {%4,%5,%6,%7}, {%8,%9}, {%0,%1,%2,%3};"
    : "+f"(d.x),"+f"(d.y),"+f"(d.z),"+f"(d.w)
    : "r"(a[0]),"r"(a[1]),"r"(a[2]),"r"(a[3]), "r"(b.x),"r"(b.y));
}

// element (e,ch) -> fragment-linear half index (B operand of m16n8k16.row.col)
__device__ __forceinline__ int frag_idx(int e, int ch){
  int tn = ch>>3, tk = e>>4, nl = ch&7, kl = e&15;
  int lane = nl*4 + ((kl&7)>>1);
  int reg  = kl>>3, pair = kl&1;
  return ((tn*8+tk)*32 + lane)*4 + reg*2 + pair;
}

// fp16 bilinear tap: 4 taps x 4 channels (ch 2L,2L+1,64+2L,64+2L+1)
__device__ __forceinline__ float4 sample_point(const float4 wv, const int4 ov, int lane){
  const __half2* base = (const __half2*)g_imgT16;
  __half2 aL=__ldg(base+ov.x+lane), aH=__ldg(base+ov.x+32+lane);
  __half2 bL=__ldg(base+ov.y+lane), bH=__ldg(base+ov.y+32+lane);
  __half2 cL=__ldg(base+ov.z+lane), cH=__ldg(base+ov.z+32+lane);
  __half2 dL=__ldg(base+ov.w+lane), dH=__ldg(base+ov.w+32+lane);
  float2 fa=__half22float2(aL), fb=__half22float2(bL), fc=__half22float2(cL), fd=__half22float2(dL);
  float2 ga=__half22float2(aH), gb=__half22float2(bH), gc=__half22float2(cH), gd=__half22float2(dH);
  float4 s;
  s.x = fmaf(wv.x,fa.x, fmaf(wv.y,fb.x, fmaf(wv.z,fc.x, wv.w*fd.x)));
  s.y = fmaf(wv.x,fa.y, fmaf(wv.y,fb.y, fmaf(wv.z,fc.y, wv.w*fd.y)));
  s.z = fmaf(wv.x,ga.x, fmaf(wv.y,gb.x, fmaf(wv.z,gc.x, wv.w*gd.x)));
  s.w = fmaf(wv.x,ga.y, fmaf(wv.y,gb.y, fmaf(wv.z,gc.y, wv.w*gd.y)));
  return s;
}

// ---- tiled img transpose + fp16 convert ----
__global__ void k_img_transpose(const float* __restrict__ img){
  __shared__ float tile[32][33];
  const int b  = blockIdx.z;
  const int yx0 = blockIdx.x*32, c0 = blockIdx.y*32;
  const int tx = threadIdx.x, ty = threadIdx.y;   // 32x8
  #pragma unroll
  for(int cc=0;cc<32;cc+=8)
    tile[cc+ty][tx] = img[((size_t)(b*D + c0+cc+ty))*NPIX + yx0 + tx];
  __syncthreads();
  #pragma unroll
  for(int yy=0;yy<32;yy+=8)
    g_imgT16[((size_t)(b*NPIX + yx0+yy+ty))*D + c0 + tx] = __float2half(tile[tx][yy+ty]);
}

// ---- tiled kW transpose ----
__global__ void k_transpose_kw(const float* __restrict__ kW){
  __shared__ float tile[32][33];
  const int c0 = blockIdx.x*32, d0 = blockIdx.y*32;
  const int tx = threadIdx.x, ty = threadIdx.y;
  #pragma unroll
  for(int cc=0;cc<32;cc+=8)
    tile[cc+ty][tx] = kW[(c0+cc+ty)*D + d0 + tx];
  __syncthreads();
  #pragma unroll
  for(int yy=0;yy<32;yy+=8)
    g_kT[(d0+yy+ty)*D + c0 + tx] = tile[tx][yy+ty];
}

// ---- matrix + vector preps (fragment-linear fp16) ----
__global__ void k_prep_mats(const float* __restrict__ qW,
                            const float* __restrict__ vW,
                            const float* __restrict__ outW,
                            const float* __restrict__ kW,
                            const float* __restrict__ qb,
                            const float* __restrict__ vb){
  const int r = blockIdx.x, t = threadIdx.x;   // r = e, t = ch
  if (blockIdx.y == 0){
    __shared__ float row[D];
    row[t] = qW[r*D+t]; __syncthreads();
    float acc = 0.f;
    #pragma unroll 4
    for(int dd=0; dd<D; dd++) acc = fmaf(row[dd], g_kT[dd*D+t], acc);
    g_Wqkf[frag_idx(r,t)] = __float2half(acc);
  } else if (blockIdx.y == 1){
    __shared__ float row[D];
    row[t] = vW[r*D+t]; __syncthreads();
    float acc = 0.f;
    #pragma unroll 4
    for(int dd=0; dd<D; dd++) acc = fmaf(row[dd], outW[dd*D+t], acc);
    g_W2f[frag_idx(r,t)] = __float2half(acc);
  } else {
    __shared__ float red1[4], red2[4];
    float s1 = qb[t]*kW[r*D+t];
    float s2 = vb[t]*outW[t*D+r];
    s1 = warpSum(s1); s2 = warpSum(s2);
    if((t&31)==0){ red1[t>>5]=s1; red2[t>>5]=s2; }
    __syncthreads();
    if(t==0){
      g_bqk[r] = red1[0]+red1[1]+red1[2]+red1[3];
      g_vbp[r] = red2[0]+red2[1]+red2[2]+red2[3];
    }
  }
}

// ---- main fused kernel ----
__global__ __launch_bounds__(256, 4)
void k_main(const float* __restrict__ x_lidar, const int* __restrict__ indices,
            const float* __restrict__ voxel_size, const float* __restrict__ pc_range,
            const float* __restrict__ trans, const float* __restrict__ offW,
            const float* __restrict__ offb, const float* __restrict__ outb,
            const void* pH, const void* pW, float* __restrict__ out, int N)
{
  const int t    = threadIdx.x;
  const int half = t >> 7;
  const int tc   = t & 127;
  const int lane = t & 31;
  const int wih  = tc >> 5;
  const int w8   = t >> 5;          // warp id 0..7
  const int n0   = blockIdx.x * TP;
  const float du = 2.0f/(WF-1), dv = 2.0f/(HF-1);

  __shared__ __align__(16) float xagg_s[TP*D];      // fp32 x (offsets GEMM)
  __shared__ __align__(16) __half xh_s[TP][XHP];    // fp16 x, later fp16 agg
  __shared__ __align__(16) float qk_s[TP*D];
  __shared__ __align__(16) SmemU u;
  __shared__ float learned_s[TP][2*P];
  __shared__ float centers_s[TP][2];
  __shared__ int   boff_s[TP];
  __shared__ float valid_s[TP][P];
  __shared__ float logits_s[2][P];
  __shared__ float S_s[TP];

  // ---- loads: x tile (fp32 + fp16) + transposed offWT stage ----
  {
    const float4* xs = (const float4*)x_lidar;
    for(int j=t; j<TP*(D/4); j+=256){
      int pt = j>>5;
      int n = n0+pt; if(n>=N) n = N-1;
      float4 v = xs[(size_t)n*(D/4) + (j&31)];
      ((float4*)xagg_s)[j] = v;
      int c = (j&31)*4;
      *(__half2*)&xh_s[pt][c]   = __float22half2_rn(make_float2(v.x,v.y));
      *(__half2*)&xh_s[pt][c+2] = __float22half2_rn(make_float2(v.z,v.w));
    }
    for(int j=t; j<D*2*P; j+=256){
      int e = j/(2*P), c = j - e*2*P;
      u.offWT[c*OWP + e] = offW[j];
    }
  }
  __syncthreads();

  // ---- Phase A: GEMV1 via tensor cores: qk = x @ Wqk + bqk ----
  {
    const unsigned int abase = smem_u32(&xh_s[0][0]);
    const int arow = lane & 15, acolblk = (lane >> 4) * 8;
    float4 acc0 = make_float4(0.f,0.f,0.f,0.f);
    float4 acc1 = make_float4(0.f,0.f,0.f,0.f);
    const uint2* Bf = (const uint2*)g_Wqkf;
    #pragma unroll
    for(int tk=0; tk<8; tk++){
      unsigned int a[4];
      ldmatrix_x4(a, abase + (arow*XHP + tk*16 + acolblk)*2);
      uint2 b0 = __ldg(&Bf[((2*w8  )*8+tk)*32 + lane]);
      uint2 b1 = __ldg(&Bf[((2*w8+1)*8+tk)*32 + lane]);
      mma16816(acc0, a, b0);
      mma16816(acc1, a, b1);
    }
    const int r0 = lane>>2, c0 = (lane&3)*2;
    const int ch0 = (2*w8)*8 + c0, ch1 = (2*w8+1)*8 + c0;
    const float2 bq0 = *(const float2*)&g_bqk[ch0];
    const float2 bq1 = *(const float2*)&g_bqk[ch1];
    *(float2*)&qk_s[r0*D+ch0]     = make_float2(acc0.x+bq0.x, acc0.y+bq0.y);
    *(float2*)&qk_s[(r0+8)*D+ch0] = make_float2(acc0.z+bq0.x, acc0.w+bq0.y);
    *(float2*)&qk_s[r0*D+ch1]     = make_float2(acc1.x+bq1.x, acc1.y+bq1.y);
    *(float2*)&qk_s[(r0+8)*D+ch1] = make_float2(acc1.z+bq1.x, acc1.w+bq1.y);
  }

  // ---- Phase A: learned offsets (fp32 — protects valid-bit boundaries) ----
  {
    const int pt0 = 2*w8, pt1 = 2*w8+1;
    const float4 xr0 = *(const float4*)&xagg_s[pt0*D + 4*lane];
    const float4 xr1 = *(const float4*)&xagg_s[pt1*D + 4*lane];
    const bool extra = lane < 2;
    const int c0 = lane, c1 = 32 + lane;
    float a00=0.f, a01=0.f, a10=0.f, a11=0.f;
    #pragma unroll 4
    for(int g=0; g<32; g++){
      const float4 w4 = *(const float4*)&u.offWT[c0*OWP + 4*g];
      float4 w4b;
      if(extra) w4b = *(const float4*)&u.offWT[c1*OWP + 4*g];
      float4 xv0, xv1;
      xv0.x=__shfl_sync(0xffffffffu,xr0.x,g); xv0.y=__shfl_sync(0xffffffffu,xr0.y,g);
      xv0.z=__shfl_sync(0xffffffffu,xr0.z,g); xv0.w=__shfl_sync(0xffffffffu,xr0.w,g);
      xv1.x=__shfl_sync(0xffffffffu,xr1.x,g); xv1.y=__shfl_sync(0xffffffffu,xr1.y,g);
      xv1.z=__shfl_sync(0xffffffffu,xr1.z,g); xv1.w=__shfl_sync(0xffffffffu,xr1.w,g);
      a00 = fmaf(w4.x,xv0.x, fmaf(w4.y,xv0.y, fmaf(w4.z,xv0.z, fmaf(w4.w,xv0.w, a00))));
      a10 = fmaf(w4.x,xv1.x, fmaf(w4.y,xv1.y, fmaf(w4.z,xv1.z, fmaf(w4.w,xv1.w, a10))));
      if(extra){
        a01 = fmaf(w4b.x,xv0.x, fmaf(w4b.y,xv0.y, fmaf(w4b.z,xv0.z, fmaf(w4b.w,xv0.w, a01))));
        a11 = fmaf(w4b.x,xv1.x, fmaf(w4b.y,xv1.y, fmaf(w4b.z,xv1.z, fmaf(w4b.w,xv1.w, a11))));
      }
    }
    float sc0 = (c0&1)? 1.5f*dv : 1.5f*du;
    learned_s[pt0][c0] = tanhf(a00 + offb[c0]) * sc0;
    learned_s[pt1][c0] = tanhf(a10 + offb[c0]) * sc0;
    if(extra){
      float sc1 = (c1&1)? 1.5f*dv : 1.5f*du;
      learned_s[pt0][c1] = tanhf(a01 + offb[c1]) * sc1;
      learned_s[pt1][c1] = tanhf(a11 + offb[c1]) * sc1;
    }
  }
  if(t < TP){
    int n = min(n0+t, N-1);
    const int4 idx = *(const int4*)(indices + (size_t)n*4);
    float cvx=voxel_size[0]*8.f, cvy=voxel_size[1]*8.f, cvz=voxel_size[2]*8.f;
    float phx = (float)idx.w*cvx + pc_range[0] + 0.5f*cvx;
    float phy = (float)idx.z*cvy + pc_range[1] + 0.5f*cvy;
    float phz = (float)idx.y*cvz + pc_range[2] + 0.5f*cvz;
    const float* T = trans + idx.x*12;
    float p0 = T[0]*phx + T[1]*phy + T[2]*phz  + T[3];
    float p1 = T[4]*phx + T[5]*phy + T[6]*phz  + T[7];
    float p2 = T[8]*phx + T[9]*phy + T[10]*phz + T[11];
    float depth = fmaxf(p2, 1e-5f);
    const int Wi = read_dim(pW), Hi = read_dim(pH);
    float uf = p0/depth * ((float)WF/(float)Wi);
    float vf = p1/depth * ((float)HF/(float)Hi);
    centers_s[t][0] = uf*du - 1.0f;
    centers_s[t][1] = vf*dv - 1.0f;
    boff_s[t] = idx.x * NPIX;
  }
  __syncthreads();

  // ---- Phase B: geometry (overwrites offWT union) ----
  for(int j=t; j<TP*P; j+=256){
    int pt = j/P, p = j - pt*P;
    float gx = centers_s[pt][0] + c_base[2*p]  *du + learned_s[pt][2*p];
    float gy = centers_s[pt][1] + c_base[2*p+1]*dv + learned_s[pt][2*p+1];
    valid_s[pt][p] = (fabsf(gx)<=1.f && fabsf(gy)<=1.f) ? 1.f : 0.f;
    float px = (gx+1.f)*0.5f*(WF-1);
    float py = (gy+1.f)*0.5f*(HF-1);
    float fxf = floorf(px), fyf = floorf(py);
    int x0=(int)fxf, y0=(int)fyf;
    float fx = px-fxf, fy = py-fyf;
    int bb = boff_s[pt];
    #pragma unroll
    for(int tap=0;tap<4;tap++){
      int xc = x0 + (tap&1), yc = y0 + (tap>>1);
      bool inb = (xc>=0 && xc<WF && yc>=0 && yc<HF);
      float wx = (tap&1)? fx : 1.f-fx;
      float wy = (tap>>1)? fy : 1.f-fy;
      u.s.w[pt][p][tap] = inb ? wx*wy : 0.f;
      int xcc = min(max(xc,0),WF-1), ycc = min(max(yc,0),HF-1);
      u.s.o[pt][p][tap] = (bb + ycc*WF + xcc)*(D/2);   // half2 index
    }
  }
  __syncthreads();

  const float scale = 0.17677669529663687f;

  // ---- main loop: each half owns points of its parity ----
  for(int ii=0; ii<TP; ii+=2){
    const int i = ii + half;
    const float2 qa = *(const float2*)&qk_s[i*D + 2*lane];
    const float2 qb2 = *(const float2*)&qk_s[i*D + 64 + 2*lane];
    float4 sval[5];

    #pragma unroll
    for(int k=0;k<4;k++){
      const int p = wih + 4*k;
      const float4 wv = *(const float4*)u.s.w[i][p];
      const int4  ov = *(const int4*) u.s.o[i][p];
      float4 s = sample_point(wv, ov, lane);
      sval[k] = s;
      float dt = fmaf(s.x,qa.x, fmaf(s.y,qa.y, fmaf(s.z,qb2.x, s.w*qb2.y)));
      dt = warpSum(dt);
      if(lane==0) logits_s[half][p] = dt;
    }
    if(wih==3){
      const float4 wv = *(const float4*)u.s.w[i][16];
      const int4  ov = *(const int4*) u.s.o[i][16];
      float4 s = sample_point(wv, ov, lane);
      sval[4] = s;
      float dt = fmaf(s.x,qa.x, fmaf(s.y,qa.y, fmaf(s.z,qb2.x, s.w*qb2.y)));
      dt = warpSum(dt);
      if(lane==0) logits_s[half][16] = dt;
    }
    barhalf(half);

    // softmax in every warp (lanes = points); aux written by wih==0 only
    float myA;
    {
      const bool act = lane < P;
      float vld = act ? valid_s[i][lane] : 0.f;
      float l = act ? ((vld>0.f) ? logits_s[half][lane]*scale : -10000.f)
                    : -3.0e38f;
      float mx = warpMax(l);
      float e  = act ? expf(l - mx) : 0.f;
      float se = warpSum(e);
      float a1 = e * (1.f/se) * vld;
      float S  = warpSum(a1);
      myA = a1 * (1.f/fmaxf(S, 1e-6f));
      if(!act) myA = 0.f;
      if(wih==0){
        float S2 = warpSum(myA);
        float pc = fmaxf(myA, 1e-6f);
        float ent = warpSum(act ? -pc*logf(pc) : 0.f);
        float vcnt = warpSum(vld);
        float lx = act ? learned_s[i][2*lane]   : 0.f;
        float ly = act ? learned_s[i][2*lane+1] : 0.f;
        float nrm = warpSum(act ? sqrtf(lx*lx+ly*ly) : 0.f);
        if(lane==0){
          S_s[i] = S2;
          int n = n0 + i;
          if(n < N){
            float inst = (nrm/(float)P) / (1.5f*sqrtf(du*du+dv*dv));
            size_t base = (size_t)N*D;
            out[base + n]               = vcnt/(float)P;
            out[base + (size_t)N + n]   = fminf(fmaxf(expf(-inst),0.f),1.f);
            out[base + 2*(size_t)N + n] = fminf(fmaxf(1.f - ent/logf((float)P),0.f),1.f);
          }
        }
      }
    }

    // aggregate in registers with shfl-broadcast attn, then cross-warp combine
    {
      float4 acc4 = make_float4(0.f,0.f,0.f,0.f);
      #pragma unroll
      for(int k=0;k<4;k++){
        float a = __shfl_sync(0xffffffffu, myA, wih+4*k);
        acc4.x = fmaf(a, sval[k].x, acc4.x);
        acc4.y = fmaf(a, sval[k].y, acc4.y);
        acc4.z = fmaf(a, sval[k].z, acc4.z);
        acc4.w = fmaf(a, sval[k].w, acc4.w);
      }
      float a16 = __shfl_sync(0xffffffffu, myA, 16);
      if(wih==3){
        acc4.x = fmaf(a16, sval[4].x, acc4.x);
        acc4.y = fmaf(a16, sval[4].y, acc4.y);
        acc4.z = fmaf(a16, sval[4].z, acc4.z);
        acc4.w = fmaf(a16, sval[4].w, acc4.w);
      }
      *(float2*)&u.s.pagg[half][wih][2*lane]      = make_float2(acc4.x, acc4.y);
      *(float2*)&u.s.pagg[half][wih][64 + 2*lane] = make_float2(acc4.z, acc4.w);
    }
    barhalf(half);
    // combine -> fp16 agg tile (reuses xh_s; x fp16 no longer needed)
    xh_s[i][tc] = __float2half(u.s.pagg[half][0][tc] + u.s.pagg[half][1][tc]
                             + u.s.pagg[half][2][tc] + u.s.pagg[half][3][tc]);
  }
  __syncthreads();

  // ---- GEMV2 via tensor cores: out = agg @ W2 + S*vbp + out_b ----
  {
    const unsigned int abase = smem_u32(&xh_s[0][0]);
    const int arow = lane & 15, acolblk = (lane >> 4) * 8;
    float4 acc0 = make_float4(0.f,0.f,0.f,0.f);
    float4 acc1 = make_float4(0.f,0.f,0.f,0.f);
    const uint2* Bf = (const uint2*)g_W2f;
    #pragma unroll
    for(int tk=0; tk<8; tk++){
      unsigned int a[4];
      ldmatrix_x4(a, abase + (arow*XHP + tk*16 + acolblk)*2);
      uint2 b0 = __ldg(&Bf[((2*w8  )*8+tk)*32 + lane]);
      uint2 b1 = __ldg(&Bf[((2*w8+1)*8+tk)*32 + lane]);
      mma16816(acc0, a, b0);
      mma16816(acc1, a, b1);
    }
    const int r0 = lane>>2, c0 = (lane&3)*2;
    const float S0 = S_s[r0], S1 = S_s[r0+8];
    #pragma unroll
    for(int nt=0; nt<2; nt++){
      const int ch = (2*w8+nt)*8 + c0;
      const float4 acc = nt ? acc1 : acc0;
      const float2 ob  = *(const float2*)&outb[ch];
      const float2 vbp = *(const float2*)&g_vbp[ch];
      if(n0+r0 < N)
        *(float2*)&out[(size_t)(n0+r0)*D + ch] =
          make_float2(acc.x + ob.x + S0*vbp.x, acc.y + ob.y + S0*vbp.y);
      if(n0+r0+8 < N)
        *(float2*)&out[(size_t)(n0+r0+8)*D + ch] =
          make_float2(acc.z + ob.x + S1*vbp.x, acc.w + ob.y + S1*vbp.y);
    }
  }
}

extern "C" void kernel_launch(void* const* d_in, const int* in_sizes, int n_in,
                              void* d_out, int out_size) {
  const float* x      = (const float*)d_in[0];
  const int*   indices= (const int*)  d_in[1];
  const float* img    = (const float*)d_in[2];
  const float* voxel  = (const float*)d_in[3];
  const float* pcr    = (const float*)d_in[4];
  const float* trans  = (const float*)d_in[5];
  const float* offW   = (const float*)d_in[6];
  const float* offb   = (const float*)d_in[7];
  const float* qW     = (const float*)d_in[8];
  const float* qb     = (const float*)d_in[9];
  const float* kW     = (const float*)d_in[10];
  const float* vW     = (const float*)d_in[12];
  const float* vb     = (const float*)d_in[13];
  const float* outW   = (const float*)d_in[14];
  const float* outb   = (const float*)d_in[15];
  const void*  pH     = d_in[16];
  const void*  pW     = d_in[17];

  int N = in_sizes[0]/D;
  int B = in_sizes[5]/12;

  dim3 tb(32,8);
  k_img_transpose<<<dim3(NPIX/32, D/32, B), tb>>>(img);
  k_transpose_kw<<<dim3(D/32, D/32), tb>>>(kW);
  k_prep_mats<<<dim3(D,3), D>>>(qW, vW, outW, kW, qb, vb);
  k_main<<<(N+TP-1)/TP, 256>>>(x, indices, voxel, pcr, trans, offW, offb, outb,
                               pH, pW, (float*)d_out, N);
}

// round 10
// speedup vs baseline: 2.6824x; 1.0218x over previous
#include <cuda_runtime.h>
#include <cuda_fp16.h>
#include <cstdint>

#define D   128
#define P   17
#define HF  56
#define WF  100
#define TP  16
#define NPIX (HF*WF)
#define OWP 132   // padded offWT row (conflict-free LDS.128)
#define XHP 136   // fp16 x-tile row pitch (halves)

// ---- device scratch ----
__device__ __half g_imgT16[2*NPIX*D];            // [B,H,W,C] fp16
__device__ float g_kT[D*D];                      // k_W^T
// fragment-linear fp16 weights for mma.m16n8k16 (B operand, col-major frags)
__device__ __align__(16) __half g_Wqkf[D*D];
__device__ __align__(16) __half g_W2f[D*D];
__device__ float g_bqk[D];
__device__ float g_vbp[D];

__constant__ float c_base[2*P] = {
  -1,-1, -1,0, -1,1, 0,-1, 0,0, 0,1, 1,-1, 1,0, 1,1,
  -3,-3, -3,0, -3,3, 0,-3, 0,3, 3,-3, 3,0, 3,3 };

union SmemU {
  float offWT[2*P*OWP];               // Phase A: transposed offset weights
  struct {
    __half2 w[TP][P][4];              // Phase B onward: dup'd fp16 tap weights
    int     o[TP][P][4];
    float   pagg[2][4][D];
  } s;
};

// sm_100: no redux.sync.f32 — use shfl butterfly
__device__ __forceinline__ float warpSum(float v){
  #pragma unroll
  for(int o=16;o>0;o>>=1) v += __shfl_xor_sync(0xffffffffu, v, o);
  return v;
}
__device__ __forceinline__ float warpMax(float v){
  #pragma unroll
  for(int o=16;o>0;o>>=1) v = fmaxf(v, __shfl_xor_sync(0xffffffffu, v, o));
  return v;
}
__device__ __forceinline__ int read_dim(const void* p){
  int iv = *(const int*)p;
  if (iv > 0 && iv < 1000000) return iv;
  return (int)(*(const float*)p);
}
__device__ __forceinline__ void barhalf(int half){
  asm volatile("bar.sync %0, 128;" :: "r"(half+1) : "memory");
}
__device__ __forceinline__ unsigned int smem_u32(const void* p){
  return (unsigned int)__cvta_generic_to_shared(p);
}
__device__ __forceinline__ void ldmatrix_x4(unsigned int r[4], unsigned int addr){
  asm volatile("ldmatrix.sync.aligned.m8n8.x4.shared.b16 {%0,%1,%2,%3}, [%4];"
    : "=r"(r[0]),"=r"(r[1]),"=r"(r[2]),"=r"(r[3]) : "r"(addr));
}
__device__ __forceinline__ void mma16816(float4& d, const unsigned int a[4], uint2 b){
  asm volatile("mma.sync.aligned.m16n8k16.row.col.f32.f16.f16.f32 "
    "{%0,%1,%2,%3}, {%4,%5,%6,%7}, {%8,%9}, {%0,%1,%2,%3};"
    : "+f"(d.x),"+f"(d.y),"+f"(d.z),"+f"(d.w)
    : "r"(a[0]),"r"(a[1]),"r"(a[2]),"r"(a[3]), "r"(b.x),"r"(b.y));
}

// element (e,ch) -> fragment-linear half index (B operand of m16n8k16.row.col)
__device__ __forceinline__ int frag_idx(int e, int ch){
  int tn = ch>>3, tk = e>>4, nl = ch&7, kl = e&15;
  int lane = nl*4 + ((kl&7)>>1);
  int reg  = kl>>3, pair = kl&1;
  return ((tn*8+tk)*32 + lane)*4 + reg*2 + pair;
}

// fp16 bilinear tap via HFMA2: lane covers ch pairs (2L,2L+1) and (64+2L,64+2L+1)
__device__ __forceinline__ void sample_h2(uint4 wraw, int4 ov, int lane,
                                          __half2& s0, __half2& s1){
  const __half2 w0 = *(const __half2*)&wraw.x;
  const __half2 w1 = *(const __half2*)&wraw.y;
  const __half2 w2 = *(const __half2*)&wraw.z;
  const __half2 w3 = *(const __half2*)&wraw.w;
  const __half2* base = (const __half2*)g_imgT16;
  __half2 aL=__ldg(base+ov.x+lane), aH=__ldg(base+ov.x+32+lane);
  __half2 bL=__ldg(base+ov.y+lane), bH=__ldg(base+ov.y+32+lane);
  __half2 cL=__ldg(base+ov.z+lane), cH=__ldg(base+ov.z+32+lane);
  __half2 dL=__ldg(base+ov.w+lane), dH=__ldg(base+ov.w+32+lane);
  s0 = __hfma2(w3,dL, __hfma2(w2,cL, __hfma2(w1,bL, __hmul2(w0,aL))));
  s1 = __hfma2(w3,dH, __hfma2(w2,cH, __hfma2(w1,bH, __hmul2(w0,aH))));
}

// ---- tiled img transpose + fp16 convert ----
__global__ void k_img_transpose(const float* __restrict__ img){
  __shared__ float tile[32][33];
  const int b  = blockIdx.z;
  const int yx0 = blockIdx.x*32, c0 = blockIdx.y*32;
  const int tx = threadIdx.x, ty = threadIdx.y;   // 32x8
  #pragma unroll
  for(int cc=0;cc<32;cc+=8)
    tile[cc+ty][tx] = img[((size_t)(b*D + c0+cc+ty))*NPIX + yx0 + tx];
  __syncthreads();
  #pragma unroll
  for(int yy=0;yy<32;yy+=8)
    g_imgT16[((size_t)(b*NPIX + yx0+yy+ty))*D + c0 + tx] = __float2half(tile[tx][yy+ty]);
}

// ---- tiled kW transpose ----
__global__ void k_transpose_kw(const float* __restrict__ kW){
  __shared__ float tile[32][33];
  const int c0 = blockIdx.x*32, d0 = blockIdx.y*32;
  const int tx = threadIdx.x, ty = threadIdx.y;
  #pragma unroll
  for(int cc=0;cc<32;cc+=8)
    tile[cc+ty][tx] = kW[(c0+cc+ty)*D + d0 + tx];
  __syncthreads();
  #pragma unroll
  for(int yy=0;yy<32;yy+=8)
    g_kT[(d0+yy+ty)*D + c0 + tx] = tile[tx][yy+ty];
}

// ---- matrix + vector preps (fragment-linear fp16) ----
__global__ void k_prep_mats(const float* __restrict__ qW,
                            const float* __restrict__ vW,
                            const float* __restrict__ outW,
                            const float* __restrict__ kW,
                            const float* __restrict__ qb,
                            const float* __restrict__ vb){
  const int r = blockIdx.x, t = threadIdx.x;   // r = e, t = ch
  if (blockIdx.y == 0){
    __shared__ float row[D];
    row[t] = qW[r*D+t]; __syncthreads();
    float acc = 0.f;
    #pragma unroll 4
    for(int dd=0; dd<D; dd++) acc = fmaf(row[dd], g_kT[dd*D+t], acc);
    g_Wqkf[frag_idx(r,t)] = __float2half(acc);
  } else if (blockIdx.y == 1){
    __shared__ float row[D];
    row[t] = vW[r*D+t]; __syncthreads();
    float acc = 0.f;
    #pragma unroll 4
    for(int dd=0; dd<D; dd++) acc = fmaf(row[dd], outW[dd*D+t], acc);
    g_W2f[frag_idx(r,t)] = __float2half(acc);
  } else {
    __shared__ float red1[4], red2[4];
    float s1 = qb[t]*kW[r*D+t];
    float s2 = vb[t]*outW[t*D+r];
    s1 = warpSum(s1); s2 = warpSum(s2);
    if((t&31)==0){ red1[t>>5]=s1; red2[t>>5]=s2; }
    __syncthreads();
    if(t==0){
      g_bqk[r] = red1[0]+red1[1]+red1[2]+red1[3];
      g_vbp[r] = red2[0]+red2[1]+red2[2]+red2[3];
    }
  }
}

// ---- main fused kernel ----
__global__ __launch_bounds__(256, 4)
void k_main(const float* __restrict__ x_lidar, const int* __restrict__ indices,
            const float* __restrict__ voxel_size, const float* __restrict__ pc_range,
            const float* __restrict__ trans, const float* __restrict__ offW,
            const float* __restrict__ offb, const float* __restrict__ outb,
            const void* pH, const void* pW, float* __restrict__ out, int N)
{
  const int t    = threadIdx.x;
  const int half = t >> 7;
  const int tc   = t & 127;
  const int lane = t & 31;
  const int wih  = tc >> 5;
  const int w8   = t >> 5;          // warp id 0..7
  const int n0   = blockIdx.x * TP;
  const float du = 2.0f/(WF-1), dv = 2.0f/(HF-1);

  __shared__ __align__(16) float xagg_s[TP*D];      // fp32 x (offsets GEMM)
  __shared__ __align__(16) __half xh_s[TP][XHP];    // fp16 x, later fp16 agg
  __shared__ __align__(16) __half2 qkh_s[TP][64];   // fp16 qk tile
  __shared__ __align__(16) SmemU u;
  __shared__ float learned_s[TP][2*P];
  __shared__ float centers_s[TP][2];
  __shared__ int   boff_s[TP];
  __shared__ float valid_s[TP][P];
  __shared__ float logits_s[2][P];
  __shared__ float S_s[TP];

  // ---- loads: x tile (fp32 + fp16) + transposed offWT stage ----
  {
    const float4* xs = (const float4*)x_lidar;
    for(int j=t; j<TP*(D/4); j+=256){
      int pt = j>>5;
      int n = n0+pt; if(n>=N) n = N-1;
      float4 v = xs[(size_t)n*(D/4) + (j&31)];
      ((float4*)xagg_s)[j] = v;
      int c = (j&31)*4;
      *(__half2*)&xh_s[pt][c]   = __float22half2_rn(make_float2(v.x,v.y));
      *(__half2*)&xh_s[pt][c+2] = __float22half2_rn(make_float2(v.z,v.w));
    }
    for(int j=t; j<D*2*P; j+=256){
      int e = j/(2*P), c = j - e*2*P;
      u.offWT[c*OWP + e] = offW[j];
    }
  }
  __syncthreads();

  // ---- Phase A: GEMV1 via tensor cores: qk = x @ Wqk + bqk (fp16 out) ----
  {
    const unsigned int abase = smem_u32(&xh_s[0][0]);
    const int arow = lane & 15, acolblk = (lane >> 4) * 8;
    float4 acc0 = make_float4(0.f,0.f,0.f,0.f);
    float4 acc1 = make_float4(0.f,0.f,0.f,0.f);
    const uint2* Bf = (const uint2*)g_Wqkf;
    #pragma unroll
    for(int tk=0; tk<8; tk++){
      unsigned int a[4];
      ldmatrix_x4(a, abase + (arow*XHP + tk*16 + acolblk)*2);
      uint2 b0 = __ldg(&Bf[((2*w8  )*8+tk)*32 + lane]);
      uint2 b1 = __ldg(&Bf[((2*w8+1)*8+tk)*32 + lane]);
      mma16816(acc0, a, b0);
      mma16816(acc1, a, b1);
    }
    const int r0 = lane>>2, c0 = (lane&3)*2;
    const int ch0 = (2*w8)*8 + c0, ch1 = (2*w8+1)*8 + c0;
    const int pi0 = w8*8 + (lane&3), pi1 = pi0 + 4;
    const float2 bq0 = *(const float2*)&g_bqk[ch0];
    const float2 bq1 = *(const float2*)&g_bqk[ch1];
    qkh_s[r0][pi0]   = __float22half2_rn(make_float2(acc0.x+bq0.x, acc0.y+bq0.y));
    qkh_s[r0+8][pi0] = __float22half2_rn(make_float2(acc0.z+bq0.x, acc0.w+bq0.y));
    qkh_s[r0][pi1]   = __float22half2_rn(make_float2(acc1.x+bq1.x, acc1.y+bq1.y));
    qkh_s[r0+8][pi1] = __float22half2_rn(make_float2(acc1.z+bq1.x, acc1.w+bq1.y));
  }

  // ---- Phase A: learned offsets (fp32 — protects valid-bit boundaries) ----
  {
    const int pt0 = 2*w8, pt1 = 2*w8+1;
    const float4 xr0 = *(const float4*)&xagg_s[pt0*D + 4*lane];
    const float4 xr1 = *(const float4*)&xagg_s[pt1*D + 4*lane];
    const bool extra = lane < 2;
    const int c0 = lane, c1 = 32 + lane;
    float a00=0.f, a01=0.f, a10=0.f, a11=0.f;
    #pragma unroll 4
    for(int g=0; g<32; g++){
      const float4 w4 = *(const float4*)&u.offWT[c0*OWP + 4*g];
      float4 w4b;
      if(extra) w4b = *(const float4*)&u.offWT[c1*OWP + 4*g];
      float4 xv0, xv1;
      xv0.x=__shfl_sync(0xffffffffu,xr0.x,g); xv0.y=__shfl_sync(0xffffffffu,xr0.y,g);
      xv0.z=__shfl_sync(0xffffffffu,xr0.z,g); xv0.w=__shfl_sync(0xffffffffu,xr0.w,g);
      xv1.x=__shfl_sync(0xffffffffu,xr1.x,g); xv1.y=__shfl_sync(0xffffffffu,xr1.y,g);
      xv1.z=__shfl_sync(0xffffffffu,xr1.z,g); xv1.w=__shfl_sync(0xffffffffu,xr1.w,g);
      a00 = fmaf(w4.x,xv0.x, fmaf(w4.y,xv0.y, fmaf(w4.z,xv0.z, fmaf(w4.w,xv0.w, a00))));
      a10 = fmaf(w4.x,xv1.x, fmaf(w4.y,xv1.y, fmaf(w4.z,xv1.z, fmaf(w4.w,xv1.w, a10))));
      if(extra){
        a01 = fmaf(w4b.x,xv0.x, fmaf(w4b.y,xv0.y, fmaf(w4b.z,xv0.z, fmaf(w4b.w,xv0.w, a01))));
        a11 = fmaf(w4b.x,xv1.x, fmaf(w4b.y,xv1.y, fmaf(w4b.z,xv1.z, fmaf(w4b.w,xv1.w, a11))));
      }
    }
    float sc0 = (c0&1)? 1.5f*dv : 1.5f*du;
    learned_s[pt0][c0] = tanhf(a00 + offb[c0]) * sc0;
    learned_s[pt1][c0] = tanhf(a10 + offb[c0]) * sc0;
    if(extra){
      float sc1 = (c1&1)? 1.5f*dv : 1.5f*du;
      learned_s[pt0][c1] = tanhf(a01 + offb[c1]) * sc1;
      learned_s[pt1][c1] = tanhf(a11 + offb[c1]) * sc1;
    }
  }
  if(t < TP){
    int n = min(n0+t, N-1);
    const int4 idx = *(const int4*)(indices + (size_t)n*4);
    float cvx=voxel_size[0]*8.f, cvy=voxel_size[1]*8.f, cvz=voxel_size[2]*8.f;
    float phx = (float)idx.w*cvx + pc_range[0] + 0.5f*cvx;
    float phy = (float)idx.z*cvy + pc_range[1] + 0.5f*cvy;
    float phz = (float)idx.y*cvz + pc_range[2] + 0.5f*cvz;
    const float* T = trans + idx.x*12;
    float p0 = T[0]*phx + T[1]*phy + T[2]*phz  + T[3];
    float p1 = T[4]*phx + T[5]*phy + T[6]*phz  + T[7];
    float p2 = T[8]*phx + T[9]*phy + T[10]*phz + T[11];
    float depth = fmaxf(p2, 1e-5f);
    const int Wi = read_dim(pW), Hi = read_dim(pH);
    float uf = p0/depth * ((float)WF/(float)Wi);
    float vf = p1/depth * ((float)HF/(float)Hi);
    centers_s[t][0] = uf*du - 1.0f;
    centers_s[t][1] = vf*dv - 1.0f;
    boff_s[t] = idx.x * NPIX;
  }
  __syncthreads();

  // ---- Phase B: geometry (overwrites offWT union) ----
  for(int j=t; j<TP*P; j+=256){
    int pt = j/P, p = j - pt*P;
    float gx = centers_s[pt][0] + c_base[2*p]  *du + learned_s[pt][2*p];
    float gy = centers_s[pt][1] + c_base[2*p+1]*dv + learned_s[pt][2*p+1];
    valid_s[pt][p] = (fabsf(gx)<=1.f && fabsf(gy)<=1.f) ? 1.f : 0.f;
    float px = (gx+1.f)*0.5f*(WF-1);
    float py = (gy+1.f)*0.5f*(HF-1);
    float fxf = floorf(px), fyf = floorf(py);
    int x0=(int)fxf, y0=(int)fyf;
    float fx = px-fxf, fy = py-fyf;
    int bb = boff_s[pt];
    #pragma unroll
    for(int tap=0;tap<4;tap++){
      int xc = x0 + (tap&1), yc = y0 + (tap>>1);
      bool inb = (xc>=0 && xc<WF && yc>=0 && yc<HF);
      float wx = (tap&1)? fx : 1.f-fx;
      float wy = (tap>>1)? fy : 1.f-fy;
      u.s.w[pt][p][tap] = __float2half2_rn(inb ? wx*wy : 0.f);
      int xcc = min(max(xc,0),WF-1), ycc = min(max(yc,0),HF-1);
      u.s.o[pt][p][tap] = (bb + ycc*WF + xcc)*(D/2);   // half2 index
    }
  }
  __syncthreads();

  const float scale = 0.17677669529663687f;

  // ---- main loop: each half owns points of its parity ----
  for(int ii=0; ii<TP; ii+=2){
    const int i = ii + half;
    const __half2 q0 = qkh_s[i][lane];
    const __half2 q1 = qkh_s[i][32+lane];
    __half2 sv0[5], sv1[5];

    #pragma unroll
    for(int k=0;k<4;k++){
      const int p = wih + 4*k;
      const uint4 wraw = *(const uint4*)u.s.w[i][p];
      const int4  ov = *(const int4*) u.s.o[i][p];
      __half2 s0, s1;
      sample_h2(wraw, ov, lane, s0, s1);
      sv0[k]=s0; sv1[k]=s1;
      const __half2 d2 = __hfma2(s1, q1, __hmul2(s0, q0));
      const float2 df = __half22float2(d2);
      const float dt = warpSum(df.x + df.y);
      if(lane==0) logits_s[half][p] = dt;
    }
    if(wih==3){
      const uint4 wraw = *(const uint4*)u.s.w[i][16];
      const int4  ov = *(const int4*) u.s.o[i][16];
      __half2 s0, s1;
      sample_h2(wraw, ov, lane, s0, s1);
      sv0[4]=s0; sv1[4]=s1;
      const __half2 d2 = __hfma2(s1, q1, __hmul2(s0, q0));
      const float2 df = __half22float2(d2);
      const float dt = warpSum(df.x + df.y);
      if(lane==0) logits_s[half][16] = dt;
    }
    barhalf(half);

    // softmax in every warp (lanes = points); aux written by wih==0 only
    float myA;
    {
      const bool act = lane < P;
      float vld = act ? valid_s[i][lane] : 0.f;
      float l = act ? ((vld>0.f) ? logits_s[half][lane]*scale : -10000.f)
                    : -3.0e38f;
      float mx = warpMax(l);
      float e  = act ? expf(l - mx) : 0.f;
      float se = warpSum(e);
      float a1 = e * (1.f/se) * vld;
      float S  = warpSum(a1);
      myA = a1 * (1.f/fmaxf(S, 1e-6f));
      if(!act) myA = 0.f;
      if(wih==0){
        float S2 = warpSum(myA);
        float pc = fmaxf(myA, 1e-6f);
        float ent = warpSum(act ? -pc*logf(pc) : 0.f);
        float vcnt = warpSum(vld);
        float lx = act ? learned_s[i][2*lane]   : 0.f;
        float ly = act ? learned_s[i][2*lane+1] : 0.f;
        float nrm = warpSum(act ? sqrtf(lx*lx+ly*ly) : 0.f);
        if(lane==0){
          S_s[i] = S2;
          int n = n0 + i;
          if(n < N){
            float inst = (nrm/(float)P) / (1.5f*sqrtf(du*du+dv*dv));
            size_t base = (size_t)N*D;
            out[base + n]               = vcnt/(float)P;
            out[base + (size_t)N + n]   = fminf(fmaxf(expf(-inst),0.f),1.f);
            out[base + 2*(size_t)N + n] = fminf(fmaxf(1.f - ent/logf((float)P),0.f),1.f);
          }
        }
      }
    }

    // aggregate in registers with shfl-broadcast attn, then cross-warp combine
    {
      float4 acc4 = make_float4(0.f,0.f,0.f,0.f);
      #pragma unroll
      for(int k=0;k<4;k++){
        float a = __shfl_sync(0xffffffffu, myA, wih+4*k);
        const float2 lo = __half22float2(sv0[k]);
        const float2 hi = __half22float2(sv1[k]);
        acc4.x = fmaf(a, lo.x, acc4.x);
        acc4.y = fmaf(a, lo.y, acc4.y);
        acc4.z = fmaf(a, hi.x, acc4.z);
        acc4.w = fmaf(a, hi.y, acc4.w);
      }
      float a16 = __shfl_sync(0xffffffffu, myA, 16);
      if(wih==3){
        const float2 lo = __half22float2(sv0[4]);
        const float2 hi = __half22float2(sv1[4]);
        acc4.x = fmaf(a16, lo.x, acc4.x);
        acc4.y = fmaf(a16, lo.y, acc4.y);
        acc4.z = fmaf(a16, hi.x, acc4.z);
        acc4.w = fmaf(a16, hi.y, acc4.w);
      }
      *(float2*)&u.s.pagg[half][wih][2*lane]      = make_float2(acc4.x, acc4.y);
      *(float2*)&u.s.pagg[half][wih][64 + 2*lane] = make_float2(acc4.z, acc4.w);
    }
    barhalf(half);
    // combine -> fp16 agg tile (reuses xh_s; x fp16 no longer needed)
    xh_s[i][tc] = __float2half(u.s.pagg[half][0][tc] + u.s.pagg[half][1][tc]
                             + u.s.pagg[half][2][tc] + u.s.pagg[half][3][tc]);
  }
  __syncthreads();

  // ---- GEMV2 via tensor cores: out = agg @ W2 + S*vbp + out_b ----
  {
    const unsigned int abase = smem_u32(&xh_s[0][0]);
    const int arow = lane & 15, acolblk = (lane >> 4) * 8;
    float4 acc0 = make_float4(0.f,0.f,0.f,0.f);
    float4 acc1 = make_float4(0.f,0.f,0.f,0.f);
    const uint2* Bf = (const uint2*)g_W2f;
    #pragma unroll
    for(int tk=0; tk<8; tk++){
      unsigned int a[4];
      ldmatrix_x4(a, abase + (arow*XHP + tk*16 + acolblk)*2);
      uint2 b0 = __ldg(&Bf[((2*w8  )*8+tk)*32 + lane]);
      uint2 b1 = __ldg(&Bf[((2*w8+1)*8+tk)*32 + lane]);
      mma16816(acc0, a, b0);
      mma16816(acc1, a, b1);
    }
    const int r0 = lane>>2, c0 = (lane&3)*2;
    const float S0 = S_s[r0], S1 = S_s[r0+8];
    #pragma unroll
    for(int nt=0; nt<2; nt++){
      const int ch = (2*w8+nt)*8 + c0;
      const float4 acc = nt ? acc1 : acc0;
      const float2 ob  = *(const float2*)&outb[ch];
      const float2 vbp = *(const float2*)&g_vbp[ch];
      if(n0+r0 < N)
        *(float2*)&out[(size_t)(n0+r0)*D + ch] =
          make_float2(acc.x + ob.x + S0*vbp.x, acc.y + ob.y + S0*vbp.y);
      if(n0+r0+8 < N)
        *(float2*)&out[(size_t)(n0+r0+8)*D + ch] =
          make_float2(acc.z + ob.x + S1*vbp.x, acc.w + ob.y + S1*vbp.y);
    }
  }
}

extern "C" void kernel_launch(void* const* d_in, const int* in_sizes, int n_in,
                              void* d_out, int out_size) {
  const float* x      = (const float*)d_in[0];
  const int*   indices= (const int*)  d_in[1];
  const float* img    = (const float*)d_in[2];
  const float* voxel  = (const float*)d_in[3];
  const float* pcr    = (const float*)d_in[4];
  const float* trans  = (const float*)d_in[5];
  const float* offW   = (const float*)d_in[6];
  const float* offb   = (const float*)d_in[7];
  const float* qW     = (const float*)d_in[8];
  const float* qb     = (const float*)d_in[9];
  const float* kW     = (const float*)d_in[10];
  const float* vW     = (const float*)d_in[12];
  const float* vb     = (const float*)d_in[13];
  const float* outW   = (const float*)d_in[14];
  const float* outb   = (const float*)d_in[15];
  const void*  pH     = d_in[16];
  const void*  pW     = d_in[17];

  int N = in_sizes[0]/D;
  int B = in_sizes[5]/12;

  dim3 tb(32,8);
  k_img_transpose<<<dim3(NPIX/32, D/32, B), tb>>>(img);
  k_transpose_kw<<<dim3(D/32, D/32), tb>>>(kW);
  k_prep_mats<<<dim3(D,3), D>>>(qW, vW, outW, kW, qb, vb);
  k_main<<<(N+TP-1)/TP, 256>>>(x, indices, voxel, pcr, trans, offW, offb, outb,
                               pH, pW, (float*)d_out, N);
}

// round 11
// speedup vs baseline: 2.9823x; 1.1118x over previous
#include <cuda_runtime.h>
#include <cuda_fp16.h>
#include <cstdint>

#define D   128
#define P   17
#define HF  56
#define WF  100
#define TP  16
#define NPIX (HF*WF)
#define OWP 132   // padded offWT row (conflict-free LDS.128)
#define XHP 136   // fp16 x-tile row pitch (halves)

// ---- device scratch ----
__device__ __half g_imgT16[2*NPIX*D];            // [B,H,W,C] fp16
__device__ float g_kT[D*D];                      // k_W^T
// fragment-linear fp16 weights for mma.m16n8k16 (B operand, col-major frags)
__device__ __align__(16) __half g_Wqkf[D*D];
__device__ __align__(16) __half g_W2f[D*D];
__device__ float g_bqk[D];
__device__ float g_vbp[D];

__constant__ float c_base[2*P] = {
  -1,-1, -1,0, -1,1, 0,-1, 0,0, 0,1, 1,-1, 1,0, 1,1,
  -3,-3, -3,0, -3,3, 0,-3, 0,3, 3,-3, 3,0, 3,3 };

union SmemU {
  float offWT[2*P*OWP];               // Phase A: transposed offset weights
  struct {
    __half2 w[TP][P][4];              // Phase B onward: dup'd fp16 tap weights
    int     o[TP][P][4];
    float   pagg[2][4][D];
  } s;
};

// sm_100: no redux.sync.f32 — use shfl butterfly
__device__ __forceinline__ float warpSum(float v){
  #pragma unroll
  for(int o=16;o>0;o>>=1) v += __shfl_xor_sync(0xffffffffu, v, o);
  return v;
}
__device__ __forceinline__ int read_dim(const void* p){
  int iv = *(const int*)p;
  if (iv > 0 && iv < 1000000) return iv;
  return (int)(*(const float*)p);
}
__device__ __forceinline__ void barhalf(int half){
  asm volatile("bar.sync %0, 128;" :: "r"(half+1) : "memory");
}
__device__ __forceinline__ unsigned int smem_u32(const void* p){
  return (unsigned int)__cvta_generic_to_shared(p);
}
__device__ __forceinline__ void ldmatrix_x4(unsigned int r[4], unsigned int addr){
  asm volatile("ldmatrix.sync.aligned.m8n8.x4.shared.b16 {%0,%1,%2,%3}, [%4];"
    : "=r"(r[0]),"=r"(r[1]),"=r"(r[2]),"=r"(r[3]) : "r"(addr));
}
__device__ __forceinline__ void mma16816(float4& d, const unsigned int a[4], uint2 b){
  asm volatile("mma.sync.aligned.m16n8k16.row.col.f32.f16.f16.f32 "
    "{%0,%1,%2,%3}, {%4,%5,%6,%7}, {%8,%9}, {%0,%1,%2,%3};"
    : "+f"(d.x),"+f"(d.y),"+f"(d.z),"+f"(d.w)
    : "r"(a[0]),"r"(a[1]),"r"(a[2]),"r"(a[3]), "r"(b.x),"r"(b.y));
}

// element (e,ch) -> fragment-linear half index (B operand of m16n8k16.row.col)
__device__ __forceinline__ int frag_idx(int e, int ch){
  int tn = ch>>3, tk = e>>4, nl = ch&7, kl = e&15;
  int lane = nl*4 + ((kl&7)>>1);
  int reg  = kl>>3, pair = kl&1;
  return ((tn*8+tk)*32 + lane)*4 + reg*2 + pair;
}

// fp16 bilinear tap via HFMA2: lane covers ch pairs (2L,2L+1) and (64+2L,64+2L+1)
__device__ __forceinline__ void sample_h2(uint4 wraw, int4 ov, int lane,
                                          __half2& s0, __half2& s1){
  const __half2 w0 = *(const __half2*)&wraw.x;
  const __half2 w1 = *(const __half2*)&wraw.y;
  const __half2 w2 = *(const __half2*)&wraw.z;
  const __half2 w3 = *(const __half2*)&wraw.w;
  const __half2* base = (const __half2*)g_imgT16;
  __half2 aL=__ldg(base+ov.x+lane), aH=__ldg(base+ov.x+32+lane);
  __half2 bL=__ldg(base+ov.y+lane), bH=__ldg(base+ov.y+32+lane);
  __half2 cL=__ldg(base+ov.z+lane), cH=__ldg(base+ov.z+32+lane);
  __half2 dL=__ldg(base+ov.w+lane), dH=__ldg(base+ov.w+32+lane);
  s0 = __hfma2(w3,dL, __hfma2(w2,cL, __hfma2(w1,bL, __hmul2(w0,aL))));
  s1 = __hfma2(w3,dH, __hfma2(w2,cH, __hfma2(w1,bH, __hmul2(w0,aH))));
}

// ---- tiled img transpose + fp16 convert ----
__global__ void k_img_transpose(const float* __restrict__ img){
  __shared__ float tile[32][33];
  const int b  = blockIdx.z;
  const int yx0 = blockIdx.x*32, c0 = blockIdx.y*32;
  const int tx = threadIdx.x, ty = threadIdx.y;   // 32x8
  #pragma unroll
  for(int cc=0;cc<32;cc+=8)
    tile[cc+ty][tx] = img[((size_t)(b*D + c0+cc+ty))*NPIX + yx0 + tx];
  __syncthreads();
  #pragma unroll
  for(int yy=0;yy<32;yy+=8)
    g_imgT16[((size_t)(b*NPIX + yx0+yy+ty))*D + c0 + tx] = __float2half(tile[tx][yy+ty]);
}

// ---- tiled kW transpose ----
__global__ void k_transpose_kw(const float* __restrict__ kW){
  __shared__ float tile[32][33];
  const int c0 = blockIdx.x*32, d0 = blockIdx.y*32;
  const int tx = threadIdx.x, ty = threadIdx.y;
  #pragma unroll
  for(int cc=0;cc<32;cc+=8)
    tile[cc+ty][tx] = kW[(c0+cc+ty)*D + d0 + tx];
  __syncthreads();
  #pragma unroll
  for(int yy=0;yy<32;yy+=8)
    g_kT[(d0+yy+ty)*D + c0 + tx] = tile[tx][yy+ty];
}

// ---- matrix + vector preps (fragment-linear fp16) ----
__global__ void k_prep_mats(const float* __restrict__ qW,
                            const float* __restrict__ vW,
                            const float* __restrict__ outW,
                            const float* __restrict__ kW,
                            const float* __restrict__ qb,
                            const float* __restrict__ vb){
  const int r = blockIdx.x, t = threadIdx.x;   // r = e, t = ch
  if (blockIdx.y == 0){
    __shared__ float row[D];
    row[t] = qW[r*D+t]; __syncthreads();
    float acc = 0.f;
    #pragma unroll 4
    for(int dd=0; dd<D; dd++) acc = fmaf(row[dd], g_kT[dd*D+t], acc);
    g_Wqkf[frag_idx(r,t)] = __float2half(acc);
  } else if (blockIdx.y == 1){
    __shared__ float row[D];
    row[t] = vW[r*D+t]; __syncthreads();
    float acc = 0.f;
    #pragma unroll 4
    for(int dd=0; dd<D; dd++) acc = fmaf(row[dd], outW[dd*D+t], acc);
    g_W2f[frag_idx(r,t)] = __float2half(acc);
  } else {
    __shared__ float red1[4], red2[4];
    float s1 = qb[t]*kW[r*D+t];
    float s2 = vb[t]*outW[t*D+r];
    s1 = warpSum(s1); s2 = warpSum(s2);
    if((t&31)==0){ red1[t>>5]=s1; red2[t>>5]=s2; }
    __syncthreads();
    if(t==0){
      g_bqk[r] = red1[0]+red1[1]+red1[2]+red1[3];
      g_vbp[r] = red2[0]+red2[1]+red2[2]+red2[3];
    }
  }
}

// ---- main fused kernel ----
__global__ __launch_bounds__(256, 4)
void k_main(const float* __restrict__ x_lidar, const int* __restrict__ indices,
            const float* __restrict__ voxel_size, const float* __restrict__ pc_range,
            const float* __restrict__ trans, const float* __restrict__ offW,
            const float* __restrict__ offb, const float* __restrict__ outb,
            const void* pH, const void* pW, float* __restrict__ out, int N)
{
  const int t    = threadIdx.x;
  const int half = t >> 7;
  const int tc   = t & 127;
  const int lane = t & 31;
  const int wih  = tc >> 5;
  const int w8   = t >> 5;          // warp id 0..7
  const int n0   = blockIdx.x * TP;
  const float du = 2.0f/(WF-1), dv = 2.0f/(HF-1);

  __shared__ __align__(16) float xagg_s[TP*D];      // fp32 x (offsets GEMM)
  __shared__ __align__(16) __half xh_s[TP][XHP];    // fp16 x, later fp16 agg
  __shared__ __align__(16) __half2 qkh_s[TP][64];   // fp16 qk tile
  __shared__ __align__(16) SmemU u;
  __shared__ float learned_s[TP][2*P];
  __shared__ float centers_s[TP][2];
  __shared__ int   boff_s[TP];
  __shared__ float valid_s[TP][P];
  __shared__ float logits_s[2][P];
  __shared__ float S_s[TP];

  // ---- loads: x tile (fp32 + fp16) + transposed offWT stage ----
  {
    const float4* xs = (const float4*)x_lidar;
    for(int j=t; j<TP*(D/4); j+=256){
      int pt = j>>5;
      int n = n0+pt; if(n>=N) n = N-1;
      float4 v = xs[(size_t)n*(D/4) + (j&31)];
      ((float4*)xagg_s)[j] = v;
      int c = (j&31)*4;
      *(__half2*)&xh_s[pt][c]   = __float22half2_rn(make_float2(v.x,v.y));
      *(__half2*)&xh_s[pt][c+2] = __float22half2_rn(make_float2(v.z,v.w));
    }
    for(int j=t; j<D*2*P; j+=256){
      int e = j/(2*P), c = j - e*2*P;
      u.offWT[c*OWP + e] = offW[j];
    }
  }
  __syncthreads();

  // ---- Phase A: GEMV1 via tensor cores: qk = x @ Wqk + bqk (fp16 out) ----
  {
    const unsigned int abase = smem_u32(&xh_s[0][0]);
    const int arow = lane & 15, acolblk = (lane >> 4) * 8;
    float4 acc0 = make_float4(0.f,0.f,0.f,0.f);
    float4 acc1 = make_float4(0.f,0.f,0.f,0.f);
    const uint2* Bf = (const uint2*)g_Wqkf;
    #pragma unroll
    for(int tk=0; tk<8; tk++){
      unsigned int a[4];
      ldmatrix_x4(a, abase + (arow*XHP + tk*16 + acolblk)*2);
      uint2 b0 = __ldg(&Bf[((2*w8  )*8+tk)*32 + lane]);
      uint2 b1 = __ldg(&Bf[((2*w8+1)*8+tk)*32 + lane]);
      mma16816(acc0, a, b0);
      mma16816(acc1, a, b1);
    }
    const int r0 = lane>>2, c0 = (lane&3)*2;
    const int ch0 = (2*w8)*8 + c0, ch1 = (2*w8+1)*8 + c0;
    const int pi0 = w8*8 + (lane&3), pi1 = pi0 + 4;
    const float2 bq0 = *(const float2*)&g_bqk[ch0];
    const float2 bq1 = *(const float2*)&g_bqk[ch1];
    qkh_s[r0][pi0]   = __float22half2_rn(make_float2(acc0.x+bq0.x, acc0.y+bq0.y));
    qkh_s[r0+8][pi0] = __float22half2_rn(make_float2(acc0.z+bq0.x, acc0.w+bq0.y));
    qkh_s[r0][pi1]   = __float22half2_rn(make_float2(acc1.x+bq1.x, acc1.y+bq1.y));
    qkh_s[r0+8][pi1] = __float22half2_rn(make_float2(acc1.z+bq1.x, acc1.w+bq1.y));
  }

  // ---- Phase A: learned offsets (fp32, broadcast-LDS x reads — no shfl) ----
  {
    const int pt0 = 2*w8, pt1 = 2*w8+1;
    const bool extra = lane < 2;
    const int c0 = lane, c1 = 32 + lane;
    float a00=0.f, a01=0.f, a10=0.f, a11=0.f;
    #pragma unroll 4
    for(int g=0; g<32; g++){
      const float4 w4 = *(const float4*)&u.offWT[c0*OWP + 4*g];
      float4 w4b;
      if(extra) w4b = *(const float4*)&u.offWT[c1*OWP + 4*g];
      const float4 xv0 = *(const float4*)&xagg_s[pt0*D + 4*g];   // broadcast
      const float4 xv1 = *(const float4*)&xagg_s[pt1*D + 4*g];   // broadcast
      a00 = fmaf(w4.x,xv0.x, fmaf(w4.y,xv0.y, fmaf(w4.z,xv0.z, fmaf(w4.w,xv0.w, a00))));
      a10 = fmaf(w4.x,xv1.x, fmaf(w4.y,xv1.y, fmaf(w4.z,xv1.z, fmaf(w4.w,xv1.w, a10))));
      if(extra){
        a01 = fmaf(w4b.x,xv0.x, fmaf(w4b.y,xv0.y, fmaf(w4b.z,xv0.z, fmaf(w4b.w,xv0.w, a01))));
        a11 = fmaf(w4b.x,xv1.x, fmaf(w4b.y,xv1.y, fmaf(w4b.z,xv1.z, fmaf(w4b.w,xv1.w, a11))));
      }
    }
    float sc0 = (c0&1)? 1.5f*dv : 1.5f*du;
    learned_s[pt0][c0] = tanhf(a00 + offb[c0]) * sc0;
    learned_s[pt1][c0] = tanhf(a10 + offb[c0]) * sc0;
    if(extra){
      float sc1 = (c1&1)? 1.5f*dv : 1.5f*du;
      learned_s[pt0][c1] = tanhf(a01 + offb[c1]) * sc1;
      learned_s[pt1][c1] = tanhf(a11 + offb[c1]) * sc1;
    }
  }
  if(t < TP){
    int n = min(n0+t, N-1);
    const int4 idx = *(const int4*)(indices + (size_t)n*4);
    float cvx=voxel_size[0]*8.f, cvy=voxel_size[1]*8.f, cvz=voxel_size[2]*8.f;
    float phx = (float)idx.w*cvx + pc_range[0] + 0.5f*cvx;
    float phy = (float)idx.z*cvy + pc_range[1] + 0.5f*cvy;
    float phz = (float)idx.y*cvz + pc_range[2] + 0.5f*cvz;
    const float* T = trans + idx.x*12;
    float p0 = T[0]*phx + T[1]*phy + T[2]*phz  + T[3];
    float p1 = T[4]*phx + T[5]*phy + T[6]*phz  + T[7];
    float p2 = T[8]*phx + T[9]*phy + T[10]*phz + T[11];
    float depth = fmaxf(p2, 1e-5f);
    const int Wi = read_dim(pW), Hi = read_dim(pH);
    float uf = p0/depth * ((float)WF/(float)Wi);
    float vf = p1/depth * ((float)HF/(float)Hi);
    centers_s[t][0] = uf*du - 1.0f;
    centers_s[t][1] = vf*dv - 1.0f;
    boff_s[t] = idx.x * NPIX;
  }
  __syncthreads();

  // ---- Phase B: geometry (overwrites offWT union) ----
  for(int j=t; j<TP*P; j+=256){
    int pt = j/P, p = j - pt*P;
    float gx = centers_s[pt][0] + c_base[2*p]  *du + learned_s[pt][2*p];
    float gy = centers_s[pt][1] + c_base[2*p+1]*dv + learned_s[pt][2*p+1];
    valid_s[pt][p] = (fabsf(gx)<=1.f && fabsf(gy)<=1.f) ? 1.f : 0.f;
    float px = (gx+1.f)*0.5f*(WF-1);
    float py = (gy+1.f)*0.5f*(HF-1);
    float fxf = floorf(px), fyf = floorf(py);
    int x0=(int)fxf, y0=(int)fyf;
    float fx = px-fxf, fy = py-fyf;
    int bb = boff_s[pt];
    #pragma unroll
    for(int tap=0;tap<4;tap++){
      int xc = x0 + (tap&1), yc = y0 + (tap>>1);
      bool inb = (xc>=0 && xc<WF && yc>=0 && yc<HF);
      float wx = (tap&1)? fx : 1.f-fx;
      float wy = (tap>>1)? fy : 1.f-fy;
      u.s.w[pt][p][tap] = __float2half2_rn(inb ? wx*wy : 0.f);
      int xcc = min(max(xc,0),WF-1), ycc = min(max(yc,0),HF-1);
      u.s.o[pt][p][tap] = (bb + ycc*WF + xcc)*(D/2);   // half2 index
    }
  }
  __syncthreads();

  const float scale = 0.17677669529663687f;

  // ---- main loop: each half owns points of its parity ----
  for(int ii=0; ii<TP; ii+=2){
    const int i = ii + half;
    const __half2 q0 = qkh_s[i][lane];
    const __half2 q1 = qkh_s[i][32+lane];
    __half2 sv0[5], sv1[5];

    #pragma unroll
    for(int k=0;k<4;k++){
      const int p = wih + 4*k;
      const uint4 wraw = *(const uint4*)u.s.w[i][p];
      const int4  ov = *(const int4*) u.s.o[i][p];
      __half2 s0, s1;
      sample_h2(wraw, ov, lane, s0, s1);
      sv0[k]=s0; sv1[k]=s1;
      const __half2 d2 = __hfma2(s1, q1, __hmul2(s0, q0));
      const float2 df = __half22float2(d2);
      const float dt = warpSum(df.x + df.y);
      if(lane==0) logits_s[half][p] = dt;
    }
    if(wih==3){
      const uint4 wraw = *(const uint4*)u.s.w[i][16];
      const int4  ov = *(const int4*) u.s.o[i][16];
      __half2 s0, s1;
      sample_h2(wraw, ov, lane, s0, s1);
      sv0[4]=s0; sv1[4]=s1;
      const __half2 d2 = __hfma2(s1, q1, __hmul2(s0, q0));
      const float2 df = __half22float2(d2);
      const float dt = warpSum(df.x + df.y);
      if(lane==0) logits_s[half][16] = dt;
    }
    barhalf(half);

    // collapsed masked softmax: attn = e*vld / sum(e*vld); sum(attn) = any_valid
    // (identical to reference: exp(-10000-mx) underflows to exact 0 there too)
    float myA;
    {
      const bool act = lane < P;
      const bool isv = act && (valid_s[i][lane] > 0.f);
      float l = isv ? logits_s[half][lane]*scale : -10000.f;
      float e = isv ? expf(l) : 0.f;
      float Ssum = warpSum(e);
      unsigned int vmask = __ballot_sync(0xffffffffu, isv);
      myA = vmask ? e * (1.f/Ssum) : 0.f;
      if(wih==0){
        float pc = fmaxf(myA, 1e-6f);
        float ent = warpSum(act ? -pc*logf(pc) : 0.f);
        float lx = act ? learned_s[i][2*lane]   : 0.f;
        float ly = act ? learned_s[i][2*lane+1] : 0.f;
        float nrm = warpSum(act ? sqrtf(lx*lx+ly*ly) : 0.f);
        if(lane==0){
          S_s[i] = vmask ? 1.f : 0.f;
          int n = n0 + i;
          if(n < N){
            float vcnt = (float)__popc(vmask);
            float inst = (nrm/(float)P) / (1.5f*sqrtf(du*du+dv*dv));
            size_t base = (size_t)N*D;
            out[base + n]               = vcnt/(float)P;
            out[base + (size_t)N + n]   = fminf(fmaxf(expf(-inst),0.f),1.f);
            out[base + 2*(size_t)N + n] = fminf(fmaxf(1.f - ent/logf((float)P),0.f),1.f);
          }
        }
      }
    }

    // aggregate in registers with shfl-broadcast attn, then cross-warp combine
    {
      float4 acc4 = make_float4(0.f,0.f,0.f,0.f);
      #pragma unroll
      for(int k=0;k<4;k++){
        float a = __shfl_sync(0xffffffffu, myA, wih+4*k);
        const float2 lo = __half22float2(sv0[k]);
        const float2 hi = __half22float2(sv1[k]);
        acc4.x = fmaf(a, lo.x, acc4.x);
        acc4.y = fmaf(a, lo.y, acc4.y);
        acc4.z = fmaf(a, hi.x, acc4.z);
        acc4.w = fmaf(a, hi.y, acc4.w);
      }
      float a16 = __shfl_sync(0xffffffffu, myA, 16);
      if(wih==3){
        const float2 lo = __half22float2(sv0[4]);
        const float2 hi = __half22float2(sv1[4]);
        acc4.x = fmaf(a16, lo.x, acc4.x);
        acc4.y = fmaf(a16, lo.y, acc4.y);
        acc4.z = fmaf(a16, hi.x, acc4.z);
        acc4.w = fmaf(a16, hi.y, acc4.w);
      }
      *(float2*)&u.s.pagg[half][wih][2*lane]      = make_float2(acc4.x, acc4.y);
      *(float2*)&u.s.pagg[half][wih][64 + 2*lane] = make_float2(acc4.z, acc4.w);
    }
    barhalf(half);
    // combine -> fp16 agg tile (reuses xh_s; x fp16 no longer needed)
    xh_s[i][tc] = __float2half(u.s.pagg[half][0][tc] + u.s.pagg[half][1][tc]
                             + u.s.pagg[half][2][tc] + u.s.pagg[half][3][tc]);
  }
  __syncthreads();

  // ---- GEMV2 via tensor cores: out = agg @ W2 + S*vbp + out_b ----
  {
    const unsigned int abase = smem_u32(&xh_s[0][0]);
    const int arow = lane & 15, acolblk = (lane >> 4) * 8;
    float4 acc0 = make_float4(0.f,0.f,0.f,0.f);
    float4 acc1 = make_float4(0.f,0.f,0.f,0.f);
    const uint2* Bf = (const uint2*)g_W2f;
    #pragma unroll
    for(int tk=0; tk<8; tk++){
      unsigned int a[4];
      ldmatrix_x4(a, abase + (arow*XHP + tk*16 + acolblk)*2);
      uint2 b0 = __ldg(&Bf[((2*w8  )*8+tk)*32 + lane]);
      uint2 b1 = __ldg(&Bf[((2*w8+1)*8+tk)*32 + lane]);
      mma16816(acc0, a, b0);
      mma16816(acc1, a, b1);
    }
    const int r0 = lane>>2, c0 = (lane&3)*2;
    const float S0 = S_s[r0], S1 = S_s[r0+8];
    #pragma unroll
    for(int nt=0; nt<2; nt++){
      const int ch = (2*w8+nt)*8 + c0;
      const float4 acc = nt ? acc1 : acc0;
      const float2 ob  = *(const float2*)&outb[ch];
      const float2 vbp = *(const float2*)&g_vbp[ch];
      if(n0+r0 < N)
        *(float2*)&out[(size_t)(n0+r0)*D + ch] =
          make_float2(acc.x + ob.x + S0*vbp.x, acc.y + ob.y + S0*vbp.y);
      if(n0+r0+8 < N)
        *(float2*)&out[(size_t)(n0+r0+8)*D + ch] =
          make_float2(acc.z + ob.x + S1*vbp.x, acc.w + ob.y + S1*vbp.y);
    }
  }
}

extern "C" void kernel_launch(void* const* d_in, const int* in_sizes, int n_in,
                              void* d_out, int out_size) {
  const float* x      = (const float*)d_in[0];
  const int*   indices= (const int*)  d_in[1];
  const float* img    = (const float*)d_in[2];
  const float* voxel  = (const float*)d_in[3];
  const float* pcr    = (const float*)d_in[4];
  const float* trans  = (const float*)d_in[5];
  const float* offW   = (const float*)d_in[6];
  const float* offb   = (const float*)d_in[7];
  const float* qW     = (const float*)d_in[8];
  const float* qb     = (const float*)d_in[9];
  const float* kW     = (const float*)d_in[10];
  const float* vW     = (const float*)d_in[12];
  const float* vb     = (const float*)d_in[13];
  const float* outW   = (const float*)d_in[14];
  const float* outb   = (const float*)d_in[15];
  const void*  pH     = d_in[16];
  const void*  pW     = d_in[17];

  int N = in_sizes[0]/D;
  int B = in_sizes[5]/12;

  dim3 tb(32,8);
  k_img_transpose<<<dim3(NPIX/32, D/32, B), tb>>>(img);
  k_transpose_kw<<<dim3(D/32, D/32), tb>>>(kW);
  k_prep_mats<<<dim3(D,3), D>>>(qW, vW, outW, kW, qb, vb);
  k_main<<<(N+TP-1)/TP, 256>>>(x, indices, voxel, pcr, trans, offW, offb, outb,
                               pH, pW, (float*)d_out, N);
}

// round 12
// speedup vs baseline: 3.3285x; 1.1161x over previous
#include <cuda_runtime.h>
#include <cuda_fp16.h>
#include <cstdint>

#define D   128
#define P   17
#define HF  56
#define WF  100
#define TP  16
#define NPIX (HF*WF)
#define OWP 132   // padded offWT row (conflict-free LDS.128)
#define XHP 136   // fp16 x-tile row pitch (halves)

// ---- device scratch ----
__device__ __half g_imgT16[2*NPIX*D];            // [B,H,W,C] fp16
__device__ float g_kT[D*D];                      // k_W^T
__device__ __align__(16) __half g_Wqkf[D*D];     // fragment-linear fp16 weights
__device__ __align__(16) __half g_W2f[D*D];
__device__ float g_bqk[D];
__device__ float g_vbp[D];

__constant__ float c_base[2*P] = {
  -1,-1, -1,0, -1,1, 0,-1, 0,0, 0,1, 1,-1, 1,0, 1,1,
  -3,-3, -3,0, -3,3, 0,-3, 0,3, 3,-3, 3,0, 3,3 };

union SmemU {
  float offWT[2*P*OWP];               // Phase A: transposed offset weights
  struct {
    __half2 w[TP][P][4];              // Phase B onward: dup'd fp16 tap weights
    int     o[TP][P][4];
    __half2 paggh[2][2][4][64];       // [half][buf][warp][chpair]
  } s;
};

__device__ __forceinline__ float warpSum(float v){
  #pragma unroll
  for(int o=16;o>0;o>>=1) v += __shfl_xor_sync(0xffffffffu, v, o);
  return v;
}
__device__ __forceinline__ __half2 shfl_xor_h2(__half2 v, int o){
  unsigned int u; memcpy(&u,&v,4);
  u = __shfl_xor_sync(0xffffffffu, u, o);
  __half2 r; memcpy(&r,&u,4); return r;
}
__device__ __forceinline__ __half hsum2(__half2 v){
  return __hadd(__low2half(v), __high2half(v));
}
__device__ __forceinline__ int read_dim(const void* p){
  int iv = *(const int*)p;
  if (iv > 0 && iv < 1000000) return iv;
  return (int)(*(const float*)p);
}
__device__ __forceinline__ void barhalf(int half){
  asm volatile("bar.sync %0, 128;" :: "r"(half+1) : "memory");
}
__device__ __forceinline__ unsigned int smem_u32(const void* p){
  return (unsigned int)__cvta_generic_to_shared(p);
}
__device__ __forceinline__ void ldmatrix_x4(unsigned int r[4], unsigned int addr){
  asm volatile("ldmatrix.sync.aligned.m8n8.x4.shared.b16 {%0,%1,%2,%3}, [%4];"
    : "=r"(r[0]),"=r"(r[1]),"=r"(r[2]),"=r"(r[3]) : "r"(addr));
}
__device__ __forceinline__ void mma16816(float4& d, const unsigned int a[4], uint2 b){
  asm volatile("mma.sync.aligned.m16n8k16.row.col.f32.f16.f16.f32 "
    "{%0,%1,%2,%3}, {%4,%5,%6,%7}, {%8,%9}, {%0,%1,%2,%3};"
    : "+f"(d.x),"+f"(d.y),"+f"(d.z),"+f"(d.w)
    : "r"(a[0]),"r"(a[1]),"r"(a[2]),"r"(a[3]), "r"(b.x),"r"(b.y));
}

// element (e,ch) -> fragment-linear half index (B operand of m16n8k16.row.col)
__device__ __forceinline__ int frag_idx(int e, int ch){
  int tn = ch>>3, tk = e>>4, nl = ch&7, kl = e&15;
  int lane = nl*4 + ((kl&7)>>1);
  int reg  = kl>>3, pair = kl&1;
  return ((tn*8+tk)*32 + lane)*4 + reg*2 + pair;
}

// fp16 bilinear tap via HFMA2
__device__ __forceinline__ void sample_h2(uint4 wraw, int4 ov, int lane,
                                          __half2& s0, __half2& s1){
  const __half2 w0 = *(const __half2*)&wraw.x;
  const __half2 w1 = *(const __half2*)&wraw.y;
  const __half2 w2 = *(const __half2*)&wraw.z;
  const __half2 w3 = *(const __half2*)&wraw.w;
  const __half2* base = (const __half2*)g_imgT16;
  __half2 aL=__ldg(base+ov.x+lane), aH=__ldg(base+ov.x+32+lane);
  __half2 bL=__ldg(base+ov.y+lane), bH=__ldg(base+ov.y+32+lane);
  __half2 cL=__ldg(base+ov.z+lane), cH=__ldg(base+ov.z+32+lane);
  __half2 dL=__ldg(base+ov.w+lane), dH=__ldg(base+ov.w+32+lane);
  s0 = __hfma2(w3,dL, __hfma2(w2,cL, __hfma2(w1,bL, __hmul2(w0,aL))));
  s1 = __hfma2(w3,dH, __hfma2(w2,cH, __hfma2(w1,bH, __hmul2(w0,aH))));
}

// ---- tiled img transpose + fp16 convert ----
__global__ void k_img_transpose(const float* __restrict__ img){
  __shared__ float tile[32][33];
  const int b  = blockIdx.z;
  const int yx0 = blockIdx.x*32, c0 = blockIdx.y*32;
  const int tx = threadIdx.x, ty = threadIdx.y;   // 32x8
  #pragma unroll
  for(int cc=0;cc<32;cc+=8)
    tile[cc+ty][tx] = img[((size_t)(b*D + c0+cc+ty))*NPIX + yx0 + tx];
  __syncthreads();
  #pragma unroll
  for(int yy=0;yy<32;yy+=8)
    g_imgT16[((size_t)(b*NPIX + yx0+yy+ty))*D + c0 + tx] = __float2half(tile[tx][yy+ty]);
}

// ---- tiled kW transpose ----
__global__ void k_transpose_kw(const float* __restrict__ kW){
  __shared__ float tile[32][33];
  const int c0 = blockIdx.x*32, d0 = blockIdx.y*32;
  const int tx = threadIdx.x, ty = threadIdx.y;
  #pragma unroll
  for(int cc=0;cc<32;cc+=8)
    tile[cc+ty][tx] = kW[(c0+cc+ty)*D + d0 + tx];
  __syncthreads();
  #pragma unroll
  for(int yy=0;yy<32;yy+=8)
    g_kT[(d0+yy+ty)*D + c0 + tx] = tile[tx][yy+ty];
}

// ---- matrix + vector preps (fragment-linear fp16) ----
__global__ void k_prep_mats(const float* __restrict__ qW,
                            const float* __restrict__ vW,
                            const float* __restrict__ outW,
                            const float* __restrict__ kW,
                            const float* __restrict__ qb,
                            const float* __restrict__ vb){
  const int r = blockIdx.x, t = threadIdx.x;   // r = e, t = ch
  if (blockIdx.y == 0){
    __shared__ float row[D];
    row[t] = qW[r*D+t]; __syncthreads();
    float acc = 0.f;
    #pragma unroll 4
    for(int dd=0; dd<D; dd++) acc = fmaf(row[dd], g_kT[dd*D+t], acc);
    g_Wqkf[frag_idx(r,t)] = __float2half(acc);
  } else if (blockIdx.y == 1){
    __shared__ float row[D];
    row[t] = vW[r*D+t]; __syncthreads();
    float acc = 0.f;
    #pragma unroll 4
    for(int dd=0; dd<D; dd++) acc = fmaf(row[dd], outW[dd*D+t], acc);
    g_W2f[frag_idx(r,t)] = __float2half(acc);
  } else {
    __shared__ float red1[4], red2[4];
    float s1 = qb[t]*kW[r*D+t];
    float s2 = vb[t]*outW[t*D+r];
    s1 = warpSum(s1); s2 = warpSum(s2);
    if((t&31)==0){ red1[t>>5]=s1; red2[t>>5]=s2; }
    __syncthreads();
    if(t==0){
      g_bqk[r] = red1[0]+red1[1]+red1[2]+red1[3];
      g_vbp[r] = red2[0]+red2[1]+red2[2]+red2[3];
    }
  }
}

// ---- main fused kernel ----
__global__ __launch_bounds__(256, 4)
void k_main(const float* __restrict__ x_lidar, const int* __restrict__ indices,
            const float* __restrict__ voxel_size, const float* __restrict__ pc_range,
            const float* __restrict__ trans, const float* __restrict__ offW,
            const float* __restrict__ offb, const float* __restrict__ outb,
            const void* pH, const void* pW, float* __restrict__ out, int N)
{
  const int t    = threadIdx.x;
  const int half = t >> 7;
  const int tc   = t & 127;
  const int lane = t & 31;
  const int wih  = tc >> 5;
  const int w8   = t >> 5;          // warp id 0..7
  const int n0   = blockIdx.x * TP;
  const float du = 2.0f/(WF-1), dv = 2.0f/(HF-1);

  __shared__ __align__(16) float xagg_s[TP*D];      // fp32 x (offsets GEMM)
  __shared__ __align__(16) __half xh_s[TP][XHP];    // fp16 x, later fp16 agg
  __shared__ __align__(16) __half2 qkh_s[TP][64];   // fp16 qk tile
  __shared__ __align__(16) SmemU u;
  __shared__ float learned_s[TP][2*P];
  __shared__ float centers_s[TP][2];
  __shared__ int   boff_s[TP];
  __shared__ float valid_s[TP][P];
  __shared__ __half logits_h[2][2][24];             // [half][buf][p]
  __shared__ float S_s[TP];

  // ---- loads: x tile (fp32 + fp16) + transposed offWT stage ----
  {
    const float4* xs = (const float4*)x_lidar;
    for(int j=t; j<TP*(D/4); j+=256){
      int pt = j>>5;
      int n = n0+pt; if(n>=N) n = N-1;
      float4 v = xs[(size_t)n*(D/4) + (j&31)];
      ((float4*)xagg_s)[j] = v;
      int c = (j&31)*4;
      *(__half2*)&xh_s[pt][c]   = __float22half2_rn(make_float2(v.x,v.y));
      *(__half2*)&xh_s[pt][c+2] = __float22half2_rn(make_float2(v.z,v.w));
    }
    for(int j=t; j<D*2*P; j+=256){
      int e = j/(2*P), c = j - e*2*P;
      u.offWT[c*OWP + e] = offW[j];
    }
  }
  __syncthreads();

  // ---- Phase A: GEMV1 via tensor cores: qk = x @ Wqk + bqk (fp16 out) ----
  {
    const unsigned int abase = smem_u32(&xh_s[0][0]);
    const int arow = lane & 15, acolblk = (lane >> 4) * 8;
    float4 acc0 = make_float4(0.f,0.f,0.f,0.f);
    float4 acc1 = make_float4(0.f,0.f,0.f,0.f);
    const uint2* Bf = (const uint2*)g_Wqkf;
    #pragma unroll
    for(int tk=0; tk<8; tk++){
      unsigned int a[4];
      ldmatrix_x4(a, abase + (arow*XHP + tk*16 + acolblk)*2);
      uint2 b0 = __ldg(&Bf[((2*w8  )*8+tk)*32 + lane]);
      uint2 b1 = __ldg(&Bf[((2*w8+1)*8+tk)*32 + lane]);
      mma16816(acc0, a, b0);
      mma16816(acc1, a, b1);
    }
    const int r0 = lane>>2, c0 = (lane&3)*2;
    const int ch0 = (2*w8)*8 + c0, ch1 = (2*w8+1)*8 + c0;
    const int pi0 = w8*8 + (lane&3), pi1 = pi0 + 4;
    const float2 bq0 = *(const float2*)&g_bqk[ch0];
    const float2 bq1 = *(const float2*)&g_bqk[ch1];
    qkh_s[r0][pi0]   = __float22half2_rn(make_float2(acc0.x+bq0.x, acc0.y+bq0.y));
    qkh_s[r0+8][pi0] = __float22half2_rn(make_float2(acc0.z+bq0.x, acc0.w+bq0.y));
    qkh_s[r0][pi1]   = __float22half2_rn(make_float2(acc1.x+bq1.x, acc1.y+bq1.y));
    qkh_s[r0+8][pi1] = __float22half2_rn(make_float2(acc1.z+bq1.x, acc1.w+bq1.y));
  }

  // ---- Phase A: learned offsets (fp32, broadcast-LDS x reads) ----
  {
    const int pt0 = 2*w8, pt1 = 2*w8+1;
    const bool extra = lane < 2;
    const int c0 = lane, c1 = 32 + lane;
    float a00=0.f, a01=0.f, a10=0.f, a11=0.f;
    #pragma unroll 4
    for(int g=0; g<32; g++){
      const float4 w4 = *(const float4*)&u.offWT[c0*OWP + 4*g];
      float4 w4b;
      if(extra) w4b = *(const float4*)&u.offWT[c1*OWP + 4*g];
      const float4 xv0 = *(const float4*)&xagg_s[pt0*D + 4*g];   // broadcast
      const float4 xv1 = *(const float4*)&xagg_s[pt1*D + 4*g];   // broadcast
      a00 = fmaf(w4.x,xv0.x, fmaf(w4.y,xv0.y, fmaf(w4.z,xv0.z, fmaf(w4.w,xv0.w, a00))));
      a10 = fmaf(w4.x,xv1.x, fmaf(w4.y,xv1.y, fmaf(w4.z,xv1.z, fmaf(w4.w,xv1.w, a10))));
      if(extra){
        a01 = fmaf(w4b.x,xv0.x, fmaf(w4b.y,xv0.y, fmaf(w4b.z,xv0.z, fmaf(w4b.w,xv0.w, a01))));
        a11 = fmaf(w4b.x,xv1.x, fmaf(w4b.y,xv1.y, fmaf(w4b.z,xv1.z, fmaf(w4b.w,xv1.w, a11))));
      }
    }
    float sc0 = (c0&1)? 1.5f*dv : 1.5f*du;
    learned_s[pt0][c0] = tanhf(a00 + offb[c0]) * sc0;
    learned_s[pt1][c0] = tanhf(a10 + offb[c0]) * sc0;
    if(extra){
      float sc1 = (c1&1)? 1.5f*dv : 1.5f*du;
      learned_s[pt0][c1] = tanhf(a01 + offb[c1]) * sc1;
      learned_s[pt1][c1] = tanhf(a11 + offb[c1]) * sc1;
    }
  }
  if(t < TP){
    int n = min(n0+t, N-1);
    const int4 idx = *(const int4*)(indices + (size_t)n*4);
    float cvx=voxel_size[0]*8.f, cvy=voxel_size[1]*8.f, cvz=voxel_size[2]*8.f;
    float phx = (float)idx.w*cvx + pc_range[0] + 0.5f*cvx;
    float phy = (float)idx.z*cvy + pc_range[1] + 0.5f*cvy;
    float phz = (float)idx.y*cvz + pc_range[2] + 0.5f*cvz;
    const float* T = trans + idx.x*12;
    float p0 = T[0]*phx + T[1]*phy + T[2]*phz  + T[3];
    float p1 = T[4]*phx + T[5]*phy + T[6]*phz  + T[7];
    float p2 = T[8]*phx + T[9]*phy + T[10]*phz + T[11];
    float depth = fmaxf(p2, 1e-5f);
    const int Wi = read_dim(pW), Hi = read_dim(pH);
    float uf = p0/depth * ((float)WF/(float)Wi);
    float vf = p1/depth * ((float)HF/(float)Hi);
    centers_s[t][0] = uf*du - 1.0f;
    centers_s[t][1] = vf*dv - 1.0f;
    boff_s[t] = idx.x * NPIX;
  }
  __syncthreads();

  // ---- Phase B: geometry (overwrites offWT union) ----
  for(int j=t; j<TP*P; j+=256){
    int pt = j/P, p = j - pt*P;
    float gx = centers_s[pt][0] + c_base[2*p]  *du + learned_s[pt][2*p];
    float gy = centers_s[pt][1] + c_base[2*p+1]*dv + learned_s[pt][2*p+1];
    valid_s[pt][p] = (fabsf(gx)<=1.f && fabsf(gy)<=1.f) ? 1.f : 0.f;
    float px = (gx+1.f)*0.5f*(WF-1);
    float py = (gy+1.f)*0.5f*(HF-1);
    float fxf = floorf(px), fyf = floorf(py);
    int x0=(int)fxf, y0=(int)fyf;
    float fx = px-fxf, fy = py-fyf;
    int bb = boff_s[pt];
    #pragma unroll
    for(int tap=0;tap<4;tap++){
      int xc = x0 + (tap&1), yc = y0 + (tap>>1);
      bool inb = (xc>=0 && xc<WF && yc>=0 && yc<HF);
      float wx = (tap&1)? fx : 1.f-fx;
      float wy = (tap>>1)? fy : 1.f-fy;
      u.s.w[pt][p][tap] = __float2half2_rn(inb ? wx*wy : 0.f);
      int xcc = min(max(xc,0),WF-1), ycc = min(max(yc,0),HF-1);
      u.s.o[pt][p][tap] = (bb + ycc*WF + xcc)*(D/2);   // half2 index
    }
  }
  __syncthreads();

  const float scale = 0.17677669529663687f;

  // ---- main loop: pipelined, ONE barrier per point ----
  int buf = 0;
  for(int ii=0; ii<TP; ii+=2){
    const int i = ii + half;
    const __half2 q0 = qkh_s[i][lane];
    const __half2 q1 = qkh_s[i][32+lane];
    __half2 sv0[5], sv1[5];
    __half2 d2[5];

    #pragma unroll
    for(int k=0;k<4;k++){
      const int p = wih + 4*k;
      const uint4 wraw = *(const uint4*)u.s.w[i][p];
      const int4  ov = *(const int4*) u.s.o[i][p];
      __half2 s0, s1;
      sample_h2(wraw, ov, lane, s0, s1);
      sv0[k]=s0; sv1[k]=s1;
      d2[k] = __hfma2(s1, q1, __hmul2(s0, q0));
    }
    if(wih==3){
      const uint4 wraw = *(const uint4*)u.s.w[i][16];
      const int4  ov = *(const int4*) u.s.o[i][16];
      __half2 s0, s1;
      sample_h2(wraw, ov, lane, s0, s1);
      sv0[4]=s0; sv1[4]=s1;
      d2[4] = __hfma2(s1, q1, __hmul2(s0, q0));
    }
    // packed half2 butterfly reductions (2 dots per chain)
    {
      __half2 e01 = __halves2half2(hsum2(d2[0]), hsum2(d2[1]));
      __half2 e23 = __halves2half2(hsum2(d2[2]), hsum2(d2[3]));
      #pragma unroll
      for(int o=16;o>0;o>>=1){
        e01 = __hadd2(e01, shfl_xor_h2(e01, o));
        e23 = __hadd2(e23, shfl_xor_h2(e23, o));
      }
      if(lane==0){
        logits_h[half][buf][wih]    = __low2half(e01);
        logits_h[half][buf][wih+4]  = __high2half(e01);
        logits_h[half][buf][wih+8]  = __low2half(e23);
        logits_h[half][buf][wih+12] = __high2half(e23);
      }
      if(wih==3){
        __half2 e4 = __halves2half2(hsum2(d2[4]), __float2half(0.f));
        #pragma unroll
        for(int o=16;o>0;o>>=1) e4 = __hadd2(e4, shfl_xor_h2(e4, o));
        if(lane==0) logits_h[half][buf][16] = __low2half(e4);
      }
    }
    barhalf(half);

    // combine previous point's aggregates into fp16 agg tile (deferred)
    if(ii >= 2 && tc < 64){
      const int ip = ii - 2 + half;
      const int pb = buf^1;
      __half2 v = __hadd2(__hadd2(u.s.paggh[half][pb][0][tc], u.s.paggh[half][pb][1][tc]),
                          __hadd2(u.s.paggh[half][pb][2][tc], u.s.paggh[half][pb][3][tc]));
      *(__half2*)&xh_s[ip][2*tc] = v;
    }

    // collapsed masked softmax (all warps; aux by wih==0)
    float myA;
    {
      const bool act = lane < P;
      const bool isv = act && (valid_s[i][lane] > 0.f);
      float l = isv ? __half2float(logits_h[half][buf][lane])*scale : -10000.f;
      float e = isv ? expf(l) : 0.f;
      float Ssum = warpSum(e);
      unsigned int vmask = __ballot_sync(0xffffffffu, isv);
      myA = vmask ? e * (1.f/Ssum) : 0.f;
      if(wih==0){
        float pc = fmaxf(myA, 1e-6f);
        float ent = warpSum(act ? -pc*logf(pc) : 0.f);
        float lx = act ? learned_s[i][2*lane]   : 0.f;
        float ly = act ? learned_s[i][2*lane+1] : 0.f;
        float nrm = warpSum(act ? sqrtf(lx*lx+ly*ly) : 0.f);
        if(lane==0){
          S_s[i] = vmask ? 1.f : 0.f;
          int n = n0 + i;
          if(n < N){
            float vcnt = (float)__popc(vmask);
            float inst = (nrm/(float)P) / (1.5f*sqrtf(du*du+dv*dv));
            size_t base = (size_t)N*D;
            out[base + n]               = vcnt/(float)P;
            out[base + (size_t)N + n]   = fminf(fmaxf(expf(-inst),0.f),1.f);
            out[base + 2*(size_t)N + n] = fminf(fmaxf(1.f - ent/logf((float)P),0.f),1.f);
          }
        }
      }
    }

    // aggregate in registers with shfl-broadcast attn -> half2 pagg (buffered)
    {
      float4 acc4 = make_float4(0.f,0.f,0.f,0.f);
      #pragma unroll
      for(int k=0;k<4;k++){
        float a = __shfl_sync(0xffffffffu, myA, wih+4*k);
        const float2 lo = __half22float2(sv0[k]);
        const float2 hi = __half22float2(sv1[k]);
        acc4.x = fmaf(a, lo.x, acc4.x);
        acc4.y = fmaf(a, lo.y, acc4.y);
        acc4.z = fmaf(a, hi.x, acc4.z);
        acc4.w = fmaf(a, hi.y, acc4.w);
      }
      float a16 = __shfl_sync(0xffffffffu, myA, 16);
      if(wih==3){
        const float2 lo = __half22float2(sv0[4]);
        const float2 hi = __half22float2(sv1[4]);
        acc4.x = fmaf(a16, lo.x, acc4.x);
        acc4.y = fmaf(a16, lo.y, acc4.y);
        acc4.z = fmaf(a16, hi.x, acc4.z);
        acc4.w = fmaf(a16, hi.y, acc4.w);
      }
      u.s.paggh[half][buf][wih][lane]    = __float22half2_rn(make_float2(acc4.x, acc4.y));
      u.s.paggh[half][buf][wih][32+lane] = __float22half2_rn(make_float2(acc4.z, acc4.w));
    }
    buf ^= 1;
  }
  barhalf(half);
  if(tc < 64){   // final combine
    const int ip = TP - 2 + half;
    const int pb = buf^1;
    __half2 v = __hadd2(__hadd2(u.s.paggh[half][pb][0][tc], u.s.paggh[half][pb][1][tc]),
                        __hadd2(u.s.paggh[half][pb][2][tc], u.s.paggh[half][pb][3][tc]));
    *(__half2*)&xh_s[ip][2*tc] = v;
  }
  __syncthreads();

  // ---- GEMV2 via tensor cores: out = agg @ W2 + S*vbp + out_b ----
  {
    const unsigned int abase = smem_u32(&xh_s[0][0]);
    const int arow = lane & 15, acolblk = (lane >> 4) * 8;
    float4 acc0 = make_float4(0.f,0.f,0.f,0.f);
    float4 acc1 = make_float4(0.f,0.f,0.f,0.f);
    const uint2* Bf = (const uint2*)g_W2f;
    #pragma unroll
    for(int tk=0; tk<8; tk++){
      unsigned int a[4];
      ldmatrix_x4(a, abase + (arow*XHP + tk*16 + acolblk)*2);
      uint2 b0 = __ldg(&Bf[((2*w8  )*8+tk)*32 + lane]);
      uint2 b1 = __ldg(&Bf[((2*w8+1)*8+tk)*32 + lane]);
      mma16816(acc0, a, b0);
      mma16816(acc1, a, b1);
    }
    const int r0 = lane>>2, c0 = (lane&3)*2;
    const float S0 = S_s[r0], S1 = S_s[r0+8];
    #pragma unroll
    for(int nt=0; nt<2; nt++){
      const int ch = (2*w8+nt)*8 + c0;
      const float4 acc = nt ? acc1 : acc0;
      const float2 ob  = *(const float2*)&outb[ch];
      const float2 vbp = *(const float2*)&g_vbp[ch];
      if(n0+r0 < N)
        *(float2*)&out[(size_t)(n0+r0)*D + ch] =
          make_float2(acc.x + ob.x + S0*vbp.x, acc.y + ob.y + S0*vbp.y);
      if(n0+r0+8 < N)
        *(float2*)&out[(size_t)(n0+r0+8)*D + ch] =
          make_float2(acc.z + ob.x + S1*vbp.x, acc.w + ob.y + S1*vbp.y);
    }
  }
}

extern "C" void kernel_launch(void* const* d_in, const int* in_sizes, int n_in,
                              void* d_out, int out_size) {
  const float* x      = (const float*)d_in[0];
  const int*   indices= (const int*)  d_in[1];
  const float* img    = (const float*)d_in[2];
  const float* voxel  = (const float*)d_in[3];
  const float* pcr    = (const float*)d_in[4];
  const float* trans  = (const float*)d_in[5];
  const float* offW   = (const float*)d_in[6];
  const float* offb   = (const float*)d_in[7];
  const float* qW     = (const float*)d_in[8];
  const float* qb     = (const float*)d_in[9];
  const float* kW     = (const float*)d_in[10];
  const float* vW     = (const float*)d_in[12];
  const float* vb     = (const float*)d_in[13];
  const float* outW   = (const float*)d_in[14];
  const float* outb   = (const float*)d_in[15];
  const void*  pH     = d_in[16];
  const void*  pW     = d_in[17];

  int N = in_sizes[0]/D;
  int B = in_sizes[5]/12;

  dim3 tb(32,8);
  k_img_transpose<<<dim3(NPIX/32, D/32, B), tb>>>(img);
  k_transpose_kw<<<dim3(D/32, D/32), tb>>>(kW);
  k_prep_mats<<<dim3(D,3), D>>>(qW, vW, outW, kW, qb, vb);
  k_main<<<(N+TP-1)/TP, 256>>>(x, indices, voxel, pcr, trans, offW, offb, outb,
                               pH, pW, (float*)d_out, N);
}

// round 14
// speedup vs baseline: 4.1094x; 1.2346x over previous
#include <cuda_runtime.h>
#include <cuda_fp16.h>
#include <cstdint>

#define D   128
#define P   17
#define HF  56
#define WF  100
#define TP  16
#define NPIX (HF*WF)
#define XHP 136   // fp16 x-tile row pitch (halves)
#define OWC 40    // padded offset-weight cols (2P=34 -> 40)

// ---- device scratch ----
__device__ __half g_imgT16[2*NPIX*D];            // [B,H,W,C] fp16
__device__ float g_kT[D*D];                      // k_W^T
__device__ __align__(16) __half g_Wqkf[D*D];     // fragment-linear fp16 weights
__device__ __align__(16) __half g_W2f[D*D];
__device__ __align__(16) __half g_offWf[D*OWC];  // offset weights hi
__device__ __align__(16) __half g_offWlf[D*OWC]; // offset weights lo (residual)
__device__ float g_bqk[D];
__device__ float g_vbp[D];

__constant__ float c_base[2*P] = {
  -1,-1, -1,0, -1,1, 0,-1, 0,0, 0,1, 1,-1, 1,0, 1,1,
  -3,-3, -3,0, -3,3, 0,-3, 0,3, 3,-3, 3,0, 3,3 };

struct SmemS {
  __half2 w[TP][P][4];              // dup'd fp16 tap weights
  int     o[TP][P][4];
  __half2 paggh[2][2][4][64];       // [half][buf][warp][chpair]
};

__device__ __forceinline__ float warpSum(float v){
  #pragma unroll
  for(int o=16;o>0;o>>=1) v += __shfl_xor_sync(0xffffffffu, v, o);
  return v;
}
__device__ __forceinline__ __half2 shfl_xor_h2(__half2 v, int o){
  unsigned int u; memcpy(&u,&v,4);
  u = __shfl_xor_sync(0xffffffffu, u, o);
  __half2 r; memcpy(&r,&u,4); return r;
}
__device__ __forceinline__ __half hsum2(__half2 v){
  return __hadd(__low2half(v), __high2half(v));
}
__device__ __forceinline__ int read_dim(const void* p){
  int iv = *(const int*)p;
  if (iv > 0 && iv < 1000000) return iv;
  return (int)(*(const float*)p);
}
__device__ __forceinline__ void barhalf(int half){
  asm volatile("bar.sync %0, 128;" :: "r"(half+1) : "memory");
}
__device__ __forceinline__ unsigned int smem_u32(const void* p){
  return (unsigned int)__cvta_generic_to_shared(p);
}
__device__ __forceinline__ void ldmatrix_x4(unsigned int r[4], unsigned int addr){
  asm volatile("ldmatrix.sync.aligned.m8n8.x4.shared.b16 {%0,%1,%2,%3}, [%4];"
    : "=r"(r[0]),"=r"(r[1]),"=r"(r[2]),"=r"(r[3]) : "r"(addr));
}
__device__ __forceinline__ void mma16816(float4& d, const unsigned int a[4], uint2 b){
  asm volatile("mma.sync.aligned.m16n8k16.row.col.f32.f16.f16.f32 "
    "{%0,%1,%2,%3}, {%4,%5,%6,%7}, {%8,%9}, {%0,%1,%2,%3};"
    : "+f"(d.x),"+f"(d.y),"+f"(d.z),"+f"(d.w)
    : "r"(a[0]),"r"(a[1]),"r"(a[2]),"r"(a[3]), "r"(b.x),"r"(b.y));
}

// element (e,ch) -> fragment-linear half index (B operand of m16n8k16.row.col)
__device__ __forceinline__ int frag_idx(int e, int ch){
  int tn = ch>>3, tk = e>>4, nl = ch&7, kl = e&15;
  int lane = nl*4 + ((kl&7)>>1);
  int reg  = kl>>3, pair = kl&1;
  return ((tn*8+tk)*32 + lane)*4 + reg*2 + pair;
}

// fp16 bilinear tap via HFMA2
__device__ __forceinline__ void sample_h2(uint4 wraw, int4 ov, int lane,
                                          __half2& s0, __half2& s1){
  const __half2 w0 = *(const __half2*)&wraw.x;
  const __half2 w1 = *(const __half2*)&wraw.y;
  const __half2 w2 = *(const __half2*)&wraw.z;
  const __half2 w3 = *(const __half2*)&wraw.w;
  const __half2* base = (const __half2*)g_imgT16;
  __half2 aL=__ldg(base+ov.x+lane), aH=__ldg(base+ov.x+32+lane);
  __half2 bL=__ldg(base+ov.y+lane), bH=__ldg(base+ov.y+32+lane);
  __half2 cL=__ldg(base+ov.z+lane), cH=__ldg(base+ov.z+32+lane);
  __half2 dL=__ldg(base+ov.w+lane), dH=__ldg(base+ov.w+32+lane);
  s0 = __hfma2(w3,dL, __hfma2(w2,cL, __hfma2(w1,bL, __hmul2(w0,aL))));
  s1 = __hfma2(w3,dH, __hfma2(w2,cH, __hfma2(w1,bH, __hmul2(w0,aH))));
}

// ---- tiled img transpose + fp16 convert ----
__global__ void k_img_transpose(const float* __restrict__ img){
  __shared__ float tile[32][33];
  const int b  = blockIdx.z;
  const int yx0 = blockIdx.x*32, c0 = blockIdx.y*32;
  const int tx = threadIdx.x, ty = threadIdx.y;   // 32x8
  #pragma unroll
  for(int cc=0;cc<32;cc+=8)
    tile[cc+ty][tx] = img[((size_t)(b*D + c0+cc+ty))*NPIX + yx0 + tx];
  __syncthreads();
  #pragma unroll
  for(int yy=0;yy<32;yy+=8)
    g_imgT16[((size_t)(b*NPIX + yx0+yy+ty))*D + c0 + tx] = __float2half(tile[tx][yy+ty]);
}

// ---- tiled kW transpose ----
__global__ void k_transpose_kw(const float* __restrict__ kW){
  __shared__ float tile[32][33];
  const int c0 = blockIdx.x*32, d0 = blockIdx.y*32;
  const int tx = threadIdx.x, ty = threadIdx.y;
  #pragma unroll
  for(int cc=0;cc<32;cc+=8)
    tile[cc+ty][tx] = kW[(c0+cc+ty)*D + d0 + tx];
  __syncthreads();
  #pragma unroll
  for(int yy=0;yy<32;yy+=8)
    g_kT[(d0+yy+ty)*D + c0 + tx] = tile[tx][yy+ty];
}

// ---- matrix + vector preps (fragment-linear fp16) ----
__global__ void k_prep_mats(const float* __restrict__ qW,
                            const float* __restrict__ vW,
                            const float* __restrict__ outW,
                            const float* __restrict__ kW,
                            const float* __restrict__ qb,
                            const float* __restrict__ vb,
                            const float* __restrict__ offW){
  const int r = blockIdx.x, t = threadIdx.x;   // r = e, t = ch
  if (blockIdx.y == 0){
    __shared__ float row[D];
    row[t] = qW[r*D+t]; __syncthreads();
    float acc = 0.f;
    #pragma unroll 4
    for(int dd=0; dd<D; dd++) acc = fmaf(row[dd], g_kT[dd*D+t], acc);
    g_Wqkf[frag_idx(r,t)] = __float2half(acc);
  } else if (blockIdx.y == 1){
    __shared__ float row[D];
    row[t] = vW[r*D+t]; __syncthreads();
    float acc = 0.f;
    #pragma unroll 4
    for(int dd=0; dd<D; dd++) acc = fmaf(row[dd], outW[dd*D+t], acc);
    g_W2f[frag_idx(r,t)] = __float2half(acc);
  } else if (blockIdx.y == 2){
    __shared__ float red1[4], red2[4];
    float s1 = qb[t]*kW[r*D+t];
    float s2 = vb[t]*outW[t*D+r];
    s1 = warpSum(s1); s2 = warpSum(s2);
    if((t&31)==0){ red1[t>>5]=s1; red2[t>>5]=s2; }
    __syncthreads();
    if(t==0){
      g_bqk[r] = red1[0]+red1[1]+red1[2]+red1[3];
      g_vbp[r] = red2[0]+red2[1]+red2[2]+red2[3];
    }
  } else {
    // offset weights: hi + residual-lo, fragment-linear, padded to OWC cols
    if(t < OWC){
      float v = (t < 2*P) ? offW[r*(2*P) + t] : 0.f;
      __half h = __float2half(v);
      g_offWf[frag_idx(r,t)]  = h;
      g_offWlf[frag_idx(r,t)] = __float2half(v - __half2float(h));
    }
  }
}

// ---- main fused kernel ----
__global__ __launch_bounds__(256, 4)
void k_main(const float* __restrict__ x_lidar, const int* __restrict__ indices,
            const float* __restrict__ voxel_size, const float* __restrict__ pc_range,
            const float* __restrict__ trans, const float* __restrict__ offb,
            const float* __restrict__ outb,
            const void* pH, const void* pW, float* __restrict__ out, int N)
{
  const int t    = threadIdx.x;
  const int half = t >> 7;
  const int tc   = t & 127;
  const int lane = t & 31;
  const int wih  = tc >> 5;
  const int w8   = t >> 5;          // warp id 0..7
  const int n0   = blockIdx.x * TP;
  const float du = 2.0f/(WF-1), dv = 2.0f/(HF-1);

  __shared__ __align__(16) __half xh_s[TP][XHP];    // fp16 x (hi), later fp16 agg
  __shared__ __align__(16) __half xlo_s[TP][XHP];   // fp16 x residual (lo)
  __shared__ __align__(16) __half2 qkh_s[TP][64];   // fp16 qk tile
  __shared__ __align__(16) SmemS u;
  __shared__ float learned_s[TP][2*P];
  __shared__ float centers_s[TP][2];
  __shared__ int   boff_s[TP];
  __shared__ float valid_s[TP][P];
  __shared__ __half logits_h[2][2][24];             // [half][buf][p]
  __shared__ float S_s[TP];

  // ---- load x tile as fp16 hi + lo residual ----
  {
    const float4* xs = (const float4*)x_lidar;
    for(int j=t; j<TP*(D/4); j+=256){
      int pt = j>>5;
      int n = n0+pt; if(n>=N) n = N-1;
      float4 v = xs[(size_t)n*(D/4) + (j&31)];
      __half2 h0 = __float22half2_rn(make_float2(v.x,v.y));
      __half2 h1 = __float22half2_rn(make_float2(v.z,v.w));
      uint2 h; memcpy(&h.x,&h0,4); memcpy(&h.y,&h1,4);
      *(uint2*)&xh_s[pt][(j&31)*4] = h;
      float2 f0 = __half22float2(h0), f1 = __half22float2(h1);
      __half2 l0 = __float22half2_rn(make_float2(v.x-f0.x, v.y-f0.y));
      __half2 l1 = __float22half2_rn(make_float2(v.z-f1.x, v.w-f1.y));
      uint2 l; memcpy(&l.x,&l0,4); memcpy(&l.y,&l1,4);
      *(uint2*)&xlo_s[pt][(j&31)*4] = l;
    }
  }
  __syncthreads();

  const unsigned int abase = smem_u32(&xh_s[0][0]);
  const unsigned int lbase = smem_u32(&xlo_s[0][0]);
  const int arow = lane & 15, acolblk = (lane >> 4) * 8;

  // ---- Phase A: GEMV1 via tensor cores: qk = x @ Wqk + bqk (fp16 out) ----
  {
    float4 acc0 = make_float4(0.f,0.f,0.f,0.f);
    float4 acc1 = make_float4(0.f,0.f,0.f,0.f);
    const uint2* Bf = (const uint2*)g_Wqkf;
    #pragma unroll
    for(int tk=0; tk<8; tk++){
      unsigned int a[4];
      ldmatrix_x4(a, abase + (arow*XHP + tk*16 + acolblk)*2);
      uint2 b0 = __ldg(&Bf[((2*w8  )*8+tk)*32 + lane]);
      uint2 b1 = __ldg(&Bf[((2*w8+1)*8+tk)*32 + lane]);
      mma16816(acc0, a, b0);
      mma16816(acc1, a, b1);
    }
    const int r0 = lane>>2, c0 = (lane&3)*2;
    const int ch0 = (2*w8)*8 + c0, ch1 = (2*w8+1)*8 + c0;
    const int pi0 = w8*8 + (lane&3), pi1 = pi0 + 4;
    const float2 bq0 = *(const float2*)&g_bqk[ch0];
    const float2 bq1 = *(const float2*)&g_bqk[ch1];
    qkh_s[r0][pi0]   = __float22half2_rn(make_float2(acc0.x+bq0.x, acc0.y+bq0.y));
    qkh_s[r0+8][pi0] = __float22half2_rn(make_float2(acc0.z+bq0.x, acc0.w+bq0.y));
    qkh_s[r0][pi1]   = __float22half2_rn(make_float2(acc1.x+bq1.x, acc1.y+bq1.y));
    qkh_s[r0+8][pi1] = __float22half2_rn(make_float2(acc1.z+bq1.x, acc1.w+bq1.y));
  }

  // ---- Phase A: learned offsets via COMPENSATED tensor-core GEMM (warps 0-4) ----
  // acc = xhi@Whi + xlo@Whi + xhi@Wlo  (residual term xlo@Wlo ~5e-8, dropped)
  if(w8 < 5){
    float4 acc = make_float4(0.f,0.f,0.f,0.f);
    const uint2* Bh = (const uint2*)g_offWf;
    const uint2* Bl = (const uint2*)g_offWlf;
    #pragma unroll
    for(int tk=0; tk<8; tk++){
      unsigned int ah[4], al[4];
      ldmatrix_x4(ah, abase + (arow*XHP + tk*16 + acolblk)*2);
      ldmatrix_x4(al, lbase + (arow*XHP + tk*16 + acolblk)*2);
      uint2 bh = __ldg(&Bh[(w8*8+tk)*32 + lane]);
      uint2 bl = __ldg(&Bl[(w8*8+tk)*32 + lane]);
      mma16816(acc, ah, bh);
      mma16816(acc, al, bh);
      mma16816(acc, ah, bl);
    }
    const int r0 = lane>>2, c0 = (lane&3)*2;
    const int col0 = w8*8 + c0, col1 = col0 + 1;
    if(col0 < 2*P){
      float ob0 = __ldg(&offb[col0]);
      float sc0 = (col0&1)? 1.5f*dv : 1.5f*du;
      learned_s[r0][col0]   = tanhf(acc.x + ob0) * sc0;
      learned_s[r0+8][col0] = tanhf(acc.z + ob0) * sc0;
    }
    if(col1 < 2*P){
      float ob1 = __ldg(&offb[col1]);
      float sc1 = (col1&1)? 1.5f*dv : 1.5f*du;
      learned_s[r0][col1]   = tanhf(acc.y + ob1) * sc1;
      learned_s[r0+8][col1] = tanhf(acc.w + ob1) * sc1;
    }
  }
  if(t < TP){
    int n = min(n0+t, N-1);
    const int4 idx = *(const int4*)(indices + (size_t)n*4);
    float cvx=voxel_size[0]*8.f, cvy=voxel_size[1]*8.f, cvz=voxel_size[2]*8.f;
    float phx = (float)idx.w*cvx + pc_range[0] + 0.5f*cvx;
    float phy = (float)idx.z*cvy + pc_range[1] + 0.5f*cvy;
    float phz = (float)idx.y*cvz + pc_range[2] + 0.5f*cvz;
    const float* T = trans + idx.x*12;
    float p0 = T[0]*phx + T[1]*phy + T[2]*phz  + T[3];
    float p1 = T[4]*phx + T[5]*phy + T[6]*phz  + T[7];
    float p2 = T[8]*phx + T[9]*phy + T[10]*phz + T[11];
    float depth = fmaxf(p2, 1e-5f);
    const int Wi = read_dim(pW), Hi = read_dim(pH);
    float uf = p0/depth * ((float)WF/(float)Wi);
    float vf = p1/depth * ((float)HF/(float)Hi);
    centers_s[t][0] = uf*du - 1.0f;
    centers_s[t][1] = vf*dv - 1.0f;
    boff_s[t] = idx.x * NPIX;
  }
  __syncthreads();

  // ---- Phase B: geometry ----
  for(int j=t; j<TP*P; j+=256){
    int pt = j/P, p = j - pt*P;
    float gx = centers_s[pt][0] + c_base[2*p]  *du + learned_s[pt][2*p];
    float gy = centers_s[pt][1] + c_base[2*p+1]*dv + learned_s[pt][2*p+1];
    valid_s[pt][p] = (fabsf(gx)<=1.f && fabsf(gy)<=1.f) ? 1.f : 0.f;
    float px = (gx+1.f)*0.5f*(WF-1);
    float py = (gy+1.f)*0.5f*(HF-1);
    float fxf = floorf(px), fyf = floorf(py);
    int x0=(int)fxf, y0=(int)fyf;
    float fx = px-fxf, fy = py-fyf;
    int bb = boff_s[pt];
    #pragma unroll
    for(int tap=0;tap<4;tap++){
      int xc = x0 + (tap&1), yc = y0 + (tap>>1);
      bool inb = (xc>=0 && xc<WF && yc>=0 && yc<HF);
      float wx = (tap&1)? fx : 1.f-fx;
      float wy = (tap>>1)? fy : 1.f-fy;
      u.w[pt][p][tap] = __float2half2_rn(inb ? wx*wy : 0.f);
      int xcc = min(max(xc,0),WF-1), ycc = min(max(yc,0),HF-1);
      u.o[pt][p][tap] = (bb + ycc*WF + xcc)*(D/2);   // half2 index
    }
  }
  __syncthreads();

  const float scale = 0.17677669529663687f;

  // ---- main loop: pipelined, ONE barrier per point ----
  int buf = 0;
  for(int ii=0; ii<TP; ii+=2){
    const int i = ii + half;
    const __half2 q0 = qkh_s[i][lane];
    const __half2 q1 = qkh_s[i][32+lane];
    __half2 sv0[5], sv1[5];
    __half2 d2[5];

    #pragma unroll
    for(int k=0;k<4;k++){
      const int p = wih + 4*k;
      const uint4 wraw = *(const uint4*)u.w[i][p];
      const int4  ov = *(const int4*) u.o[i][p];
      __half2 s0, s1;
      sample_h2(wraw, ov, lane, s0, s1);
      sv0[k]=s0; sv1[k]=s1;
      d2[k] = __hfma2(s1, q1, __hmul2(s0, q0));
    }
    if(wih==3){
      const uint4 wraw = *(const uint4*)u.w[i][16];
      const int4  ov = *(const int4*) u.o[i][16];
      __half2 s0, s1;
      sample_h2(wraw, ov, lane, s0, s1);
      sv0[4]=s0; sv1[4]=s1;
      d2[4] = __hfma2(s1, q1, __hmul2(s0, q0));
    }
    // packed half2 butterfly reductions (2 dots per chain)
    {
      __half2 e01 = __halves2half2(hsum2(d2[0]), hsum2(d2[1]));
      __half2 e23 = __halves2half2(hsum2(d2[2]), hsum2(d2[3]));
      #pragma unroll
      for(int o=16;o>0;o>>=1){
        e01 = __hadd2(e01, shfl_xor_h2(e01, o));
        e23 = __hadd2(e23, shfl_xor_h2(e23, o));
      }
      if(lane==0){
        logits_h[half][buf][wih]    = __low2half(e01);
        logits_h[half][buf][wih+4]  = __high2half(e01);
        logits_h[half][buf][wih+8]  = __low2half(e23);
        logits_h[half][buf][wih+12] = __high2half(e23);
      }
      if(wih==3){
        __half2 e4 = __halves2half2(hsum2(d2[4]), __float2half(0.f));
        #pragma unroll
        for(int o=16;o>0;o>>=1) e4 = __hadd2(e4, shfl_xor_h2(e4, o));
        if(lane==0) logits_h[half][buf][16] = __low2half(e4);
      }
    }
    barhalf(half);

    // combine previous point's aggregates into fp16 agg tile (deferred)
    if(ii >= 2 && tc < 64){
      const int ip = ii - 2 + half;
      const int pb = buf^1;
      __half2 v = __hadd2(__hadd2(u.paggh[half][pb][0][tc], u.paggh[half][pb][1][tc]),
                          __hadd2(u.paggh[half][pb][2][tc], u.paggh[half][pb][3][tc]));
      *(__half2*)&xh_s[ip][2*tc] = v;
    }

    // collapsed masked softmax (all warps; aux by wih==0)
    float myA;
    {
      const bool act = lane < P;
      const bool isv = act && (valid_s[i][lane] > 0.f);
      float l = isv ? __half2float(logits_h[half][buf][lane])*scale : -10000.f;
      float e = isv ? expf(l) : 0.f;
      float Ssum = warpSum(e);
      unsigned int vmask = __ballot_sync(0xffffffffu, isv);
      myA = vmask ? e * (1.f/Ssum) : 0.f;
      if(wih==0){
        float pc = fmaxf(myA, 1e-6f);
        float ent = warpSum(act ? -pc*logf(pc) : 0.f);
        float lx = act ? learned_s[i][2*lane]   : 0.f;
        float ly = act ? learned_s[i][2*lane+1] : 0.f;
        float nrm = warpSum(act ? sqrtf(lx*lx+ly*ly) : 0.f);
        if(lane==0){
          S_s[i] = vmask ? 1.f : 0.f;
          int n = n0 + i;
          if(n < N){
            float vcnt = (float)__popc(vmask);
            float inst = (nrm/(float)P) / (1.5f*sqrtf(du*du+dv*dv));
            size_t base = (size_t)N*D;
            out[base + n]               = vcnt/(float)P;
            out[base + (size_t)N + n]   = fminf(fmaxf(expf(-inst),0.f),1.f);
            out[base + 2*(size_t)N + n] = fminf(fmaxf(1.f - ent/logf((float)P),0.f),1.f);
          }
        }
      }
    }

    // aggregate in registers with shfl-broadcast attn -> half2 pagg (buffered)
    {
      float4 acc4 = make_float4(0.f,0.f,0.f,0.f);
      #pragma unroll
      for(int k=0;k<4;k++){
        float a = __shfl_sync(0xffffffffu, myA, wih+4*k);
        const float2 lo = __half22float2(sv0[k]);
        const float2 hi = __half22float2(sv1[k]);
        acc4.x = fmaf(a, lo.x, acc4.x);
        acc4.y = fmaf(a, lo.y, acc4.y);
        acc4.z = fmaf(a, hi.x, acc4.z);
        acc4.w = fmaf(a, hi.y, acc4.w);
      }
      float a16 = __shfl_sync(0xffffffffu, myA, 16);
      if(wih==3){
        const float2 lo = __half22float2(sv0[4]);
        const float2 hi = __half22float2(sv1[4]);
        acc4.x = fmaf(a16, lo.x, acc4.x);
        acc4.y = fmaf(a16, lo.y, acc4.y);
        acc4.z = fmaf(a16, hi.x, acc4.z);
        acc4.w = fmaf(a16, hi.y, acc4.w);
      }
      u.paggh[half][buf][wih][lane]    = __float22half2_rn(make_float2(acc4.x, acc4.y));
      u.paggh[half][buf][wih][32+lane] = __float22half2_rn(make_float2(acc4.z, acc4.w));
    }
    buf ^= 1;
  }
  barhalf(half);
  if(tc < 64){   // final combine
    const int ip = TP - 2 + half;
    const int pb = buf^1;
    __half2 v = __hadd2(__hadd2(u.paggh[half][pb][0][tc], u.paggh[half][pb][1][tc]),
                        __hadd2(u.paggh[half][pb][2][tc], u.paggh[half][pb][3][tc]));
    *(__half2*)&xh_s[ip][2*tc] = v;
  }
  __syncthreads();

  // ---- GEMV2 via tensor cores: out = agg @ W2 + S*vbp + out_b ----
  {
    float4 acc0 = make_float4(0.f,0.f,0.f,0.f);
    float4 acc1 = make_float4(0.f,0.f,0.f,0.f);
    const uint2* Bf = (const uint2*)g_W2f;
    #pragma unroll
    for(int tk=0; tk<8; tk++){
      unsigned int a[4];
      ldmatrix_x4(a, abase + (arow*XHP + tk*16 + acolblk)*2);
      uint2 b0 = __ldg(&Bf[((2*w8  )*8+tk)*32 + lane]);
      uint2 b1 = __ldg(&Bf[((2*w8+1)*8+tk)*32 + lane]);
      mma16816(acc0, a, b0);
      mma16816(acc1, a, b1);
    }
    const int r0 = lane>>2, c0 = (lane&3)*2;
    const float S0 = S_s[r0], S1 = S_s[r0+8];
    #pragma unroll
    for(int nt=0; nt<2; nt++){
      const int ch = (2*w8+nt)*8 + c0;
      const float4 acc = nt ? acc1 : acc0;
      const float2 ob  = *(const float2*)&outb[ch];
      const float2 vbp = *(const float2*)&g_vbp[ch];
      if(n0+r0 < N)
        *(float2*)&out[(size_t)(n0+r0)*D + ch] =
          make_float2(acc.x + ob.x + S0*vbp.x, acc.y + ob.y + S0*vbp.y);
      if(n0+r0+8 < N)
        *(float2*)&out[(size_t)(n0+r0+8)*D + ch] =
          make_float2(acc.z + ob.x + S1*vbp.x, acc.w + ob.y + S1*vbp.y);
    }
  }
}

extern "C" void kernel_launch(void* const* d_in, const int* in_sizes, int n_in,
                              void* d_out, int out_size) {
  const float* x      = (const float*)d_in[0];
  const int*   indices= (const int*)  d_in[1];
  const float* img    = (const float*)d_in[2];
  const float* voxel  = (const float*)d_in[3];
  const float* pcr    = (const float*)d_in[4];
  const float* trans  = (const float*)d_in[5];
  const float* offW   = (const float*)d_in[6];
  const float* offb   = (const float*)d_in[7];
  const float* qW     = (const float*)d_in[8];
  const float* qb     = (const float*)d_in[9];
  const float* kW     = (const float*)d_in[10];
  const float* vW     = (const float*)d_in[12];
  const float* vb     = (const float*)d_in[13];
  const float* outW   = (const float*)d_in[14];
  const float* outb   = (const float*)d_in[15];
  const void*  pH     = d_in[16];
  const void*  pW     = d_in[17];

  int N = in_sizes[0]/D;
  int B = in_sizes[5]/12;

  dim3 tb(32,8);
  k_img_transpose<<<dim3(NPIX/32, D/32, B), tb>>>(img);
  k_transpose_kw<<<dim3(D/32, D/32), tb>>>(kW);
  k_prep_mats<<<dim3(D,4), D>>>(qW, vW, outW, kW, qb, vb, offW);
  k_main<<<(N+TP-1)/TP, 256>>>(x, indices, voxel, pcr, trans, offb, outb,
                               pH, pW, (float*)d_out, N);
}

// round 15
// speedup vs baseline: 4.2527x; 1.0349x over previous
#include <cuda_runtime.h>
#include <cuda_fp16.h>
#include <cstdint>

#define D   128
#define P   17
#define HF  56
#define WF  100
#define TP  16
#define NPIX (HF*WF)
#define XHP 136   // fp16 x-tile row pitch (halves)
#define OWC 40    // padded offset-weight cols (2P=34 -> 40)

// ---- device scratch ----
__device__ __half g_imgT16[2*NPIX*D];            // [B,H,W,C] fp16
__device__ float g_kT[D*D];                      // k_W^T
__device__ __align__(16) __half g_Wqkf[D*D];     // pair-fragment fp16 weights
__device__ __align__(16) __half g_W2f[D*D];
__device__ __align__(16) __half g_offWf[D*OWC];  // offset weights hi
__device__ __align__(16) __half g_offWlf[D*OWC]; // offset weights lo (residual)
__device__ float g_bqk[D];
__device__ float g_vbp[D];

__constant__ float c_base[2*P] = {
  -1,-1, -1,0, -1,1, 0,-1, 0,0, 0,1, 1,-1, 1,0, 1,1,
  -3,-3, -3,0, -3,3, 0,-3, 0,3, 3,-3, 3,0, 3,3 };

struct SmemS {
  __half2 w[TP][P][4];              // dup'd fp16 tap weights
  int     o[TP][P][4];              // BYTE offsets into g_imgT16
  __half2 paggh[2][2][4][64];       // [half][buf][warp][chpair]
};

__device__ __forceinline__ float warpSum(float v){
  #pragma unroll
  for(int o=16;o>0;o>>=1) v += __shfl_xor_sync(0xffffffffu, v, o);
  return v;
}
__device__ __forceinline__ __half2 shfl_xor_h2(__half2 v, int o){
  unsigned int u; memcpy(&u,&v,4);
  u = __shfl_xor_sync(0xffffffffu, u, o);
  __half2 r; memcpy(&r,&u,4); return r;
}
__device__ __forceinline__ __half hsum2(__half2 v){
  return __hadd(__low2half(v), __high2half(v));
}
__device__ __forceinline__ int read_dim(const void* p){
  int iv = *(const int*)p;
  if (iv > 0 && iv < 1000000) return iv;
  return (int)(*(const float*)p);
}
__device__ __forceinline__ void barhalf(int half){
  asm volatile("bar.sync %0, 128;" :: "r"(half+1) : "memory");
}
__device__ __forceinline__ unsigned int smem_u32(const void* p){
  return (unsigned int)__cvta_generic_to_shared(p);
}
__device__ __forceinline__ void ldmatrix_x4(unsigned int r[4], unsigned int addr){
  asm volatile("ldmatrix.sync.aligned.m8n8.x4.shared.b16 {%0,%1,%2,%3}, [%4];"
    : "=r"(r[0]),"=r"(r[1]),"=r"(r[2]),"=r"(r[3]) : "r"(addr));
}
__device__ __forceinline__ void mma16816(float4& d, const unsigned int a[4], uint2 b){
  asm volatile("mma.sync.aligned.m16n8k16.row.col.f32.f16.f16.f32 "
    "{%0,%1,%2,%3}, {%4,%5,%6,%7}, {%8,%9}, {%0,%1,%2,%3};"
    : "+f"(d.x),"+f"(d.y),"+f"(d.z),"+f"(d.w)
    : "r"(a[0]),"r"(a[1]),"r"(a[2]),"r"(a[3]), "r"(b.x),"r"(b.y));
}

// element (e,ch) -> PAIRED fragment-linear half index.
// uint4 slot (tn*4 + tk/2)*32 + lane holds [tk even: 2 uint2][tk odd: 2 uint2]
__device__ __forceinline__ int frag_idx(int e, int ch){
  int tn = ch>>3, tk = e>>4, nl = ch&7, kl = e&15;
  int lane = nl*4 + ((kl&7)>>1);
  int reg  = kl>>3, pair = kl&1;
  return ((((tn*4 + (tk>>1))*32 + lane)*2 + (tk&1))*4) + reg*2 + pair;
}

// fp16 bilinear tap via HFMA2; bp = g_imgT16 + lane*4 (byte ptr), ov = byte offsets
__device__ __forceinline__ void sample_h2(uint4 wraw, int4 ov, const char* bp,
                                          __half2& s0, __half2& s1){
  const __half2 w0 = *(const __half2*)&wraw.x;
  const __half2 w1 = *(const __half2*)&wraw.y;
  const __half2 w2 = *(const __half2*)&wraw.z;
  const __half2 w3 = *(const __half2*)&wraw.w;
  __half2 aL=__ldg((const __half2*)(bp+ov.x)), aH=__ldg((const __half2*)(bp+ov.x+128));
  __half2 bL=__ldg((const __half2*)(bp+ov.y)), bH=__ldg((const __half2*)(bp+ov.y+128));
  __half2 cL=__ldg((const __half2*)(bp+ov.z)), cH=__ldg((const __half2*)(bp+ov.z+128));
  __half2 dL=__ldg((const __half2*)(bp+ov.w)), dH=__ldg((const __half2*)(bp+ov.w+128));
  s0 = __hfma2(w3,dL, __hfma2(w2,cL, __hfma2(w1,bL, __hmul2(w0,aL))));
  s1 = __hfma2(w3,dH, __hfma2(w2,cH, __hfma2(w1,bH, __hmul2(w0,aH))));
}

// ---- tiled img transpose + fp16 convert; z==B slice does the kW transpose ----
__global__ void k_img_transpose(const float* __restrict__ img,
                                const float* __restrict__ kW, int B){
  __shared__ float tile[32][33];
  const int tx = threadIdx.x, ty = threadIdx.y;   // 32x8
  if(blockIdx.z < (unsigned)B){
    const int b  = blockIdx.z;
    const int yx0 = blockIdx.x*32, c0 = blockIdx.y*32;
    #pragma unroll
    for(int cc=0;cc<32;cc+=8)
      tile[cc+ty][tx] = img[((size_t)(b*D + c0+cc+ty))*NPIX + yx0 + tx];
    __syncthreads();
    #pragma unroll
    for(int yy=0;yy<32;yy+=8)
      g_imgT16[((size_t)(b*NPIX + yx0+yy+ty))*D + c0 + tx] = __float2half(tile[tx][yy+ty]);
  } else {
    if(blockIdx.x >= 4) return;
    const int c0 = blockIdx.x*32, d0 = blockIdx.y*32;
    #pragma unroll
    for(int cc=0;cc<32;cc+=8)
      tile[cc+ty][tx] = kW[(c0+cc+ty)*D + d0 + tx];
    __syncthreads();
    #pragma unroll
    for(int yy=0;yy<32;yy+=8)
      g_kT[(d0+yy+ty)*D + c0 + tx] = tile[tx][yy+ty];
  }
}

// ---- matrix + vector preps (paired fragment-linear fp16) ----
__global__ void k_prep_mats(const float* __restrict__ qW,
                            const float* __restrict__ vW,
                            const float* __restrict__ outW,
                            const float* __restrict__ kW,
                            const float* __restrict__ qb,
                            const float* __restrict__ vb,
                            const float* __restrict__ offW){
  const int r = blockIdx.x, t = threadIdx.x;   // r = e, t = ch
  if (blockIdx.y == 0){
    __shared__ float row[D];
    row[t] = qW[r*D+t]; __syncthreads();
    float acc = 0.f;
    #pragma unroll 4
    for(int dd=0; dd<D; dd++) acc = fmaf(row[dd], g_kT[dd*D+t], acc);
    g_Wqkf[frag_idx(r,t)] = __float2half(acc);
  } else if (blockIdx.y == 1){
    __shared__ float row[D];
    row[t] = vW[r*D+t]; __syncthreads();
    float acc = 0.f;
    #pragma unroll 4
    for(int dd=0; dd<D; dd++) acc = fmaf(row[dd], outW[dd*D+t], acc);
    g_W2f[frag_idx(r,t)] = __float2half(acc);
  } else if (blockIdx.y == 2){
    __shared__ float red1[4], red2[4];
    float s1 = qb[t]*kW[r*D+t];
    float s2 = vb[t]*outW[t*D+r];
    s1 = warpSum(s1); s2 = warpSum(s2);
    if((t&31)==0){ red1[t>>5]=s1; red2[t>>5]=s2; }
    __syncthreads();
    if(t==0){
      g_bqk[r] = red1[0]+red1[1]+red1[2]+red1[3];
      g_vbp[r] = red2[0]+red2[1]+red2[2]+red2[3];
    }
  } else {
    if(t < OWC){
      float v = (t < 2*P) ? offW[r*(2*P) + t] : 0.f;
      __half h = __float2half(v);
      g_offWf[frag_idx(r,t)]  = h;
      g_offWlf[frag_idx(r,t)] = __float2half(v - __half2float(h));
    }
  }
}

// ---- main fused kernel ----
__global__ __launch_bounds__(256, 4)
void k_main(const float* __restrict__ x_lidar, const int* __restrict__ indices,
            const float* __restrict__ voxel_size, const float* __restrict__ pc_range,
            const float* __restrict__ trans, const float* __restrict__ offb,
            const float* __restrict__ outb,
            const void* pH, const void* pW, float* __restrict__ out, int N)
{
  const int t    = threadIdx.x;
  const int half = t >> 7;
  const int tc   = t & 127;
  const int lane = t & 31;
  const int wih  = tc >> 5;
  const int w8   = t >> 5;          // warp id 0..7
  const int n0   = blockIdx.x * TP;
  const float du = 2.0f/(WF-1), dv = 2.0f/(HF-1);

  __shared__ __align__(16) __half xh_s[TP][XHP];    // fp16 x (hi), later fp16 agg
  __shared__ __align__(16) __half xlo_s[TP][XHP];   // fp16 x residual (lo)
  __shared__ __align__(16) __half2 qkh_s[TP][64];   // fp16 qk tile
  __shared__ __align__(16) SmemS u;
  __shared__ float learned_s[TP][2*P];
  __shared__ float centers_s[TP][2];
  __shared__ int   boff_s[TP];
  __shared__ float valid_s[TP][P];
  __shared__ __half logits_h[2][2][24];             // [half][buf][p]
  __shared__ float S_s[TP];

  // ---- load x tile as fp16 hi + lo residual ----
  {
    const float4* xs = (const float4*)x_lidar;
    for(int j=t; j<TP*(D/4); j+=256){
      int pt = j>>5;
      int n = n0+pt; if(n>=N) n = N-1;
      float4 v = xs[(size_t)n*(D/4) + (j&31)];
      __half2 h0 = __float22half2_rn(make_float2(v.x,v.y));
      __half2 h1 = __float22half2_rn(make_float2(v.z,v.w));
      uint2 h; memcpy(&h.x,&h0,4); memcpy(&h.y,&h1,4);
      *(uint2*)&xh_s[pt][(j&31)*4] = h;
      float2 f0 = __half22float2(h0), f1 = __half22float2(h1);
      __half2 l0 = __float22half2_rn(make_float2(v.x-f0.x, v.y-f0.y));
      __half2 l1 = __float22half2_rn(make_float2(v.z-f1.x, v.w-f1.y));
      uint2 l; memcpy(&l.x,&l0,4); memcpy(&l.y,&l1,4);
      *(uint2*)&xlo_s[pt][(j&31)*4] = l;
    }
  }
  __syncthreads();

  const unsigned int abase = smem_u32(&xh_s[0][0]);
  const unsigned int lbase = smem_u32(&xlo_s[0][0]);
  const int arow = lane & 15, acolblk = (lane >> 4) * 8;
  const int r0l = lane>>2, c0l = (lane&3)*2;

  // ---- Phase A (rebalanced): GEMV1 tiles + compensated offsets GEMM ----
  if(w8 < 5){
    // one GEMV1 tile (tn=w8) + offset tile w8 (3-pass compensated)
    float4 accG = make_float4(0.f,0.f,0.f,0.f);
    float4 accO = make_float4(0.f,0.f,0.f,0.f);
    const uint4* BG  = (const uint4*)g_Wqkf;
    const uint4* BOh = (const uint4*)g_offWf;
    const uint4* BOl = (const uint4*)g_offWlf;
    #pragma unroll
    for(int tk2=0; tk2<4; tk2++){
      unsigned int a0[4], a1[4], l0[4], l1[4];
      ldmatrix_x4(a0, abase + (arow*XHP + (2*tk2  )*16 + acolblk)*2);
      ldmatrix_x4(a1, abase + (arow*XHP + (2*tk2+1)*16 + acolblk)*2);
      ldmatrix_x4(l0, lbase + (arow*XHP + (2*tk2  )*16 + acolblk)*2);
      ldmatrix_x4(l1, lbase + (arow*XHP + (2*tk2+1)*16 + acolblk)*2);
      uint4 rG  = __ldg(&BG [(w8*4+tk2)*32 + lane]);
      uint4 rOh = __ldg(&BOh[(w8*4+tk2)*32 + lane]);
      uint4 rOl = __ldg(&BOl[(w8*4+tk2)*32 + lane]);
      mma16816(accG, a0, make_uint2(rG.x,rG.y));  mma16816(accG, a1, make_uint2(rG.z,rG.w));
      mma16816(accO, a0, make_uint2(rOh.x,rOh.y)); mma16816(accO, a1, make_uint2(rOh.z,rOh.w));
      mma16816(accO, l0, make_uint2(rOh.x,rOh.y)); mma16816(accO, l1, make_uint2(rOh.z,rOh.w));
      mma16816(accO, a0, make_uint2(rOl.x,rOl.y)); mma16816(accO, a1, make_uint2(rOl.z,rOl.w));
    }
    {
      const int ch = w8*8 + c0l;
      const float2 bq = *(const float2*)&g_bqk[ch];
      const int pi = w8*4 + (lane&3);
      qkh_s[r0l][pi]   = __float22half2_rn(make_float2(accG.x+bq.x, accG.y+bq.y));
      qkh_s[r0l+8][pi] = __float22half2_rn(make_float2(accG.z+bq.x, accG.w+bq.y));
    }
    const int col0 = w8*8 + c0l, col1 = col0 + 1;
    if(col0 < 2*P){
      float ob0 = __ldg(&offb[col0]);
      float sc0 = (col0&1)? 1.5f*dv : 1.5f*du;
      learned_s[r0l][col0]   = tanhf(accO.x + ob0) * sc0;
      learned_s[r0l+8][col0] = tanhf(accO.z + ob0) * sc0;
    }
    if(col1 < 2*P){
      float ob1 = __ldg(&offb[col1]);
      float sc1 = (col1&1)? 1.5f*dv : 1.5f*du;
      learned_s[r0l][col1]   = tanhf(accO.y + ob1) * sc1;
      learned_s[r0l+8][col1] = tanhf(accO.w + ob1) * sc1;
    }
  } else {
    // remaining GEMV1 tiles in ldmatrix-sharing pairs: w5:{5,8},{11,14} w6:{6,9},{12,15} w7:{7,10},{13}
    const uint4* BG = (const uint4*)g_Wqkf;
    for(int t0 = w8; t0 < 16; t0 += 6){
      const int tB = t0 + 3;
      const bool hasB = tB < 16;
      float4 acc0 = make_float4(0.f,0.f,0.f,0.f);
      float4 acc1 = make_float4(0.f,0.f,0.f,0.f);
      #pragma unroll
      for(int tk2=0; tk2<4; tk2++){
        unsigned int a0[4], a1[4];
        ldmatrix_x4(a0, abase + (arow*XHP + (2*tk2  )*16 + acolblk)*2);
        ldmatrix_x4(a1, abase + (arow*XHP + (2*tk2+1)*16 + acolblk)*2);
        uint4 rA = __ldg(&BG[(t0*4+tk2)*32 + lane]);
        mma16816(acc0, a0, make_uint2(rA.x,rA.y)); mma16816(acc0, a1, make_uint2(rA.z,rA.w));
        if(hasB){
          uint4 rB = __ldg(&BG[(tB*4+tk2)*32 + lane]);
          mma16816(acc1, a0, make_uint2(rB.x,rB.y)); mma16816(acc1, a1, make_uint2(rB.z,rB.w));
        }
      }
      {
        const int ch = t0*8 + c0l;
        const float2 bq = *(const float2*)&g_bqk[ch];
        const int pi = t0*4 + (lane&3);
        qkh_s[r0l][pi]   = __float22half2_rn(make_float2(acc0.x+bq.x, acc0.y+bq.y));
        qkh_s[r0l+8][pi] = __float22half2_rn(make_float2(acc0.z+bq.x, acc0.w+bq.y));
      }
      if(hasB){
        const int ch = tB*8 + c0l;
        const float2 bq = *(const float2*)&g_bqk[ch];
        const int pi = tB*4 + (lane&3);
        qkh_s[r0l][pi]   = __float22half2_rn(make_float2(acc1.x+bq.x, acc1.y+bq.y));
        qkh_s[r0l+8][pi] = __float22half2_rn(make_float2(acc1.z+bq.x, acc1.w+bq.y));
      }
    }
  }
  if(t < TP){
    int n = min(n0+t, N-1);
    const int4 idx = *(const int4*)(indices + (size_t)n*4);
    float cvx=voxel_size[0]*8.f, cvy=voxel_size[1]*8.f, cvz=voxel_size[2]*8.f;
    float phx = (float)idx.w*cvx + pc_range[0] + 0.5f*cvx;
    float phy = (float)idx.z*cvy + pc_range[1] + 0.5f*cvy;
    float phz = (float)idx.y*cvz + pc_range[2] + 0.5f*cvz;
    const float* T = trans + idx.x*12;
    float p0 = T[0]*phx + T[1]*phy + T[2]*phz  + T[3];
    float p1 = T[4]*phx + T[5]*phy + T[6]*phz  + T[7];
    float p2 = T[8]*phx + T[9]*phy + T[10]*phz + T[11];
    float depth = fmaxf(p2, 1e-5f);
    const int Wi = read_dim(pW), Hi = read_dim(pH);
    float uf = p0/depth * ((float)WF/(float)Wi);
    float vf = p1/depth * ((float)HF/(float)Hi);
    centers_s[t][0] = uf*du - 1.0f;
    centers_s[t][1] = vf*dv - 1.0f;
    boff_s[t] = idx.x * NPIX;
  }
  __syncthreads();

  // ---- Phase B: geometry (o stored as BYTE offsets) ----
  for(int j=t; j<TP*P; j+=256){
    int pt = j/P, p = j - pt*P;
    float gx = centers_s[pt][0] + c_base[2*p]  *du + learned_s[pt][2*p];
    float gy = centers_s[pt][1] + c_base[2*p+1]*dv + learned_s[pt][2*p+1];
    valid_s[pt][p] = (fabsf(gx)<=1.f && fabsf(gy)<=1.f) ? 1.f : 0.f;
    float px = (gx+1.f)*0.5f*(WF-1);
    float py = (gy+1.f)*0.5f*(HF-1);
    float fxf = floorf(px), fyf = floorf(py);
    int x0=(int)fxf, y0=(int)fyf;
    float fx = px-fxf, fy = py-fyf;
    int bb = boff_s[pt];
    #pragma unroll
    for(int tap=0;tap<4;tap++){
      int xc = x0 + (tap&1), yc = y0 + (tap>>1);
      bool inb = (xc>=0 && xc<WF && yc>=0 && yc<HF);
      float wx = (tap&1)? fx : 1.f-fx;
      float wy = (tap>>1)? fy : 1.f-fy;
      u.w[pt][p][tap] = __float2half2_rn(inb ? wx*wy : 0.f);
      int xcc = min(max(xc,0),WF-1), ycc = min(max(yc,0),HF-1);
      u.o[pt][p][tap] = (bb + ycc*WF + xcc)*(D*2);   // byte offset (D ch * 2B)
    }
  }
  __syncthreads();

  const float scale = 0.17677669529663687f;
  const char* bp = (const char*)g_imgT16 + lane*4;

  // ---- main loop: pipelined, ONE barrier per point ----
  int buf = 0;
  for(int ii=0; ii<TP; ii+=2){
    const int i = ii + half;
    const __half2 q0 = qkh_s[i][lane];
    const __half2 q1 = qkh_s[i][32+lane];
    __half2 sv0[5], sv1[5];
    __half2 d2[5];

    #pragma unroll
    for(int k=0;k<4;k++){
      const int p = wih + 4*k;
      const uint4 wraw = *(const uint4*)u.w[i][p];
      const int4  ov = *(const int4*) u.o[i][p];
      __half2 s0, s1;
      sample_h2(wraw, ov, bp, s0, s1);
      sv0[k]=s0; sv1[k]=s1;
      d2[k] = __hfma2(s1, q1, __hmul2(s0, q0));
    }
    if(wih==3){
      const uint4 wraw = *(const uint4*)u.w[i][16];
      const int4  ov = *(const int4*) u.o[i][16];
      __half2 s0, s1;
      sample_h2(wraw, ov, bp, s0, s1);
      sv0[4]=s0; sv1[4]=s1;
      d2[4] = __hfma2(s1, q1, __hmul2(s0, q0));
    }
    // packed half2 butterfly reductions (2 dots per chain)
    {
      __half2 e01 = __halves2half2(hsum2(d2[0]), hsum2(d2[1]));
      __half2 e23 = __halves2half2(hsum2(d2[2]), hsum2(d2[3]));
      #pragma unroll
      for(int o=16;o>0;o>>=1){
        e01 = __hadd2(e01, shfl_xor_h2(e01, o));
        e23 = __hadd2(e23, shfl_xor_h2(e23, o));
      }
      if(lane==0){
        logits_h[half][buf][wih]    = __low2half(e01);
        logits_h[half][buf][wih+4]  = __high2half(e01);
        logits_h[half][buf][wih+8]  = __low2half(e23);
        logits_h[half][buf][wih+12] = __high2half(e23);
      }
      if(wih==3){
        __half2 e4 = __halves2half2(hsum2(d2[4]), __float2half(0.f));
        #pragma unroll
        for(int o=16;o>0;o>>=1) e4 = __hadd2(e4, shfl_xor_h2(e4, o));
        if(lane==0) logits_h[half][buf][16] = __low2half(e4);
      }
    }
    barhalf(half);

    // combine previous point's aggregates into fp16 agg tile (deferred)
    if(ii >= 2 && tc < 64){
      const int ip = ii - 2 + half;
      const int pb = buf^1;
      __half2 v = __hadd2(__hadd2(u.paggh[half][pb][0][tc], u.paggh[half][pb][1][tc]),
                          __hadd2(u.paggh[half][pb][2][tc], u.paggh[half][pb][3][tc]));
      *(__half2*)&xh_s[ip][2*tc] = v;
    }

    // collapsed masked softmax (all warps; aux by wih==0)
    float myA;
    {
      const bool act = lane < P;
      const bool isv = act && (valid_s[i][lane] > 0.f);
      float l = isv ? __half2float(logits_h[half][buf][lane])*scale : -10000.f;
      float e = isv ? expf(l) : 0.f;
      float Ssum = warpSum(e);
      unsigned int vmask = __ballot_sync(0xffffffffu, isv);
      myA = vmask ? e * (1.f/Ssum) : 0.f;
      if(wih==0){
        float pc = fmaxf(myA, 1e-6f);
        float ent = warpSum(act ? -pc*logf(pc) : 0.f);
        float lx = act ? learned_s[i][2*lane]   : 0.f;
        float ly = act ? learned_s[i][2*lane+1] : 0.f;
        float nrm = warpSum(act ? sqrtf(lx*lx+ly*ly) : 0.f);
        if(lane==0){
          S_s[i] = vmask ? 1.f : 0.f;
          int n = n0 + i;
          if(n < N){
            float vcnt = (float)__popc(vmask);
            float inst = (nrm/(float)P) / (1.5f*sqrtf(du*du+dv*dv));
            size_t base = (size_t)N*D;
            out[base + n]               = vcnt/(float)P;
            out[base + (size_t)N + n]   = fminf(fmaxf(expf(-inst),0.f),1.f);
            out[base + 2*(size_t)N + n] = fminf(fmaxf(1.f - ent/logf((float)P),0.f),1.f);
          }
        }
      }
    }

    // aggregate in registers with shfl-broadcast attn -> half2 pagg (buffered)
    {
      float4 acc4 = make_float4(0.f,0.f,0.f,0.f);
      #pragma unroll
      for(int k=0;k<4;k++){
        float a = __shfl_sync(0xffffffffu, myA, wih+4*k);
        const float2 lo = __half22float2(sv0[k]);
        const float2 hi = __half22float2(sv1[k]);
        acc4.x = fmaf(a, lo.x, acc4.x);
        acc4.y = fmaf(a, lo.y, acc4.y);
        acc4.z = fmaf(a, hi.x, acc4.z);
        acc4.w = fmaf(a, hi.y, acc4.w);
      }
      float a16 = __shfl_sync(0xffffffffu, myA, 16);
      if(wih==3){
        const float2 lo = __half22float2(sv0[4]);
        const float2 hi = __half22float2(sv1[4]);
        acc4.x = fmaf(a16, lo.x, acc4.x);
        acc4.y = fmaf(a16, lo.y, acc4.y);
        acc4.z = fmaf(a16, hi.x, acc4.z);
        acc4.w = fmaf(a16, hi.y, acc4.w);
      }
      u.paggh[half][buf][wih][lane]    = __float22half2_rn(make_float2(acc4.x, acc4.y));
      u.paggh[half][buf][wih][32+lane] = __float22half2_rn(make_float2(acc4.z, acc4.w));
    }
    buf ^= 1;
  }
  barhalf(half);
  if(tc < 64){   // final combine
    const int ip = TP - 2 + half;
    const int pb = buf^1;
    __half2 v = __hadd2(__hadd2(u.paggh[half][pb][0][tc], u.paggh[half][pb][1][tc]),
                        __hadd2(u.paggh[half][pb][2][tc], u.paggh[half][pb][3][tc]));
    *(__half2*)&xh_s[ip][2*tc] = v;
  }
  __syncthreads();

  // ---- GEMV2 via tensor cores: out = agg @ W2 + S*vbp + out_b ----
  {
    float4 acc0 = make_float4(0.f,0.f,0.f,0.f);
    float4 acc1 = make_float4(0.f,0.f,0.f,0.f);
    const uint4* Bf = (const uint4*)g_W2f;
    #pragma unroll
    for(int tk2=0; tk2<4; tk2++){
      unsigned int a0[4], a1[4];
      ldmatrix_x4(a0, abase + (arow*XHP + (2*tk2  )*16 + acolblk)*2);
      ldmatrix_x4(a1, abase + (arow*XHP + (2*tk2+1)*16 + acolblk)*2);
      uint4 rA = __ldg(&Bf[((2*w8  )*4+tk2)*32 + lane]);
      uint4 rB = __ldg(&Bf[((2*w8+1)*4+tk2)*32 + lane]);
      mma16816(acc0, a0, make_uint2(rA.x,rA.y)); mma16816(acc0, a1, make_uint2(rA.z,rA.w));
      mma16816(acc1, a0, make_uint2(rB.x,rB.y)); mma16816(acc1, a1, make_uint2(rB.z,rB.w));
    }
    const float S0 = S_s[r0l], S1 = S_s[r0l+8];
    #pragma unroll
    for(int nt=0; nt<2; nt++){
      const int ch = (2*w8+nt)*8 + c0l;
      const float4 acc = nt ? acc1 : acc0;
      const float2 ob  = *(const float2*)&outb[ch];
      const float2 vbp = *(const float2*)&g_vbp[ch];
      if(n0+r0l < N)
        *(float2*)&out[(size_t)(n0+r0l)*D + ch] =
          make_float2(acc.x + ob.x + S0*vbp.x, acc.y + ob.y + S0*vbp.y);
      if(n0+r0l+8 < N)
        *(float2*)&out[(size_t)(n0+r0l+8)*D + ch] =
          make_float2(acc.z + ob.x + S1*vbp.x, acc.w + ob.y + S1*vbp.y);
    }
  }
}

extern "C" void kernel_launch(void* const* d_in, const int* in_sizes, int n_in,
                              void* d_out, int out_size) {
  const float* x      = (const float*)d_in[0];
  const int*   indices= (const int*)  d_in[1];
  const float* img    = (const float*)d_in[2];
  const float* voxel  = (const float*)d_in[3];
  const float* pcr    = (const float*)d_in[4];
  const float* trans  = (const float*)d_in[5];
  const float* offW   = (const float*)d_in[6];
  const float* offb   = (const float*)d_in[7];
  const float* qW     = (const float*)d_in[8];
  const float* qb     = (const float*)d_in[9];
  const float* kW     = (const float*)d_in[10];
  const float* vW     = (const float*)d_in[12];
  const float* vb     = (const float*)d_in[13];
  const float* outW   = (const float*)d_in[14];
  const float* outb   = (const float*)d_in[15];
  const void*  pH     = d_in[16];
  const void*  pW     = d_in[17];

  int N = in_sizes[0]/D;
  int B = in_sizes[5]/12;

  dim3 tb(32,8);
  k_img_transpose<<<dim3(NPIX/32, D/32, B+1), tb>>>(img, kW, B);
  k_prep_mats<<<dim3(D,4), D>>>(qW, vW, outW, kW, qb, vb, offW);
  k_main<<<(N+TP-1)/TP, 256>>>(x, indices, voxel, pcr, trans, offb, outb,
                               pH, pW, (float*)d_out, N);
}

// round 16
// speedup vs baseline: 4.3822x; 1.0305x over previous
#include <cuda_runtime.h>
#include <cuda_fp16.h>
#include <cstdint>

#define D   128
#define P   17
#define HF  56
#define WF  100
#define TP  16
#define NPIX (HF*WF)
#define XHP 136   // fp16 x-tile row pitch (halves)
#define OWC 40    // padded offset-weight cols (2P=34 -> 40)

// ---- device scratch ----
__device__ __half g_imgT16[2*NPIX*D];            // [B,H,W,C] fp16
__device__ float g_kT[D*D];                      // k_W^T
__device__ __align__(16) __half g_Wqkf[D*D];     // pair-fragment fp16 weights
__device__ __align__(16) __half g_W2f[D*D];
__device__ __align__(16) __half g_offWf[D*OWC];  // offset weights hi
__device__ __align__(16) __half g_offWlf[D*OWC]; // offset weights lo (residual)
__device__ float g_bqk[D];
__device__ float g_vbp[D];

__constant__ float c_base[2*P] = {
  -1,-1, -1,0, -1,1, 0,-1, 0,0, 0,1, 1,-1, 1,0, 1,1,
  -3,-3, -3,0, -3,3, 0,-3, 0,3, 3,-3, 3,0, 3,3 };

struct SmemS {
  __half2 w[TP][P][4];              // dup'd fp16 tap weights
  int     o[TP][P][4];              // BYTE offsets into g_imgT16
  __half2 paggh[2][2][4][64];       // [half][buf][warp][chpair]
};

__device__ __forceinline__ float warpSum(float v){
  #pragma unroll
  for(int o=16;o>0;o>>=1) v += __shfl_xor_sync(0xffffffffu, v, o);
  return v;
}
__device__ __forceinline__ __half2 shfl_xor_h2(__half2 v, int o){
  unsigned int u; memcpy(&u,&v,4);
  u = __shfl_xor_sync(0xffffffffu, u, o);
  __half2 r; memcpy(&r,&u,4); return r;
}
__device__ __forceinline__ __half hsum2(__half2 v){
  return __hadd(__low2half(v), __high2half(v));
}
__device__ __forceinline__ int read_dim(const void* p){
  int iv = *(const int*)p;
  if (iv > 0 && iv < 1000000) return iv;
  return (int)(*(const float*)p);
}
__device__ __forceinline__ void barhalf(int half){
  asm volatile("bar.sync %0, 128;" :: "r"(half+1) : "memory");
}
__device__ __forceinline__ unsigned int smem_u32(const void* p){
  return (unsigned int)__cvta_generic_to_shared(p);
}
__device__ __forceinline__ void ldmatrix_x4(unsigned int r[4], unsigned int addr){
  asm volatile("ldmatrix.sync.aligned.m8n8.x4.shared.b16 {%0,%1,%2,%3}, [%4];"
    : "=r"(r[0]),"=r"(r[1]),"=r"(r[2]),"=r"(r[3]) : "r"(addr));
}
__device__ __forceinline__ void mma16816(float4& d, const unsigned int a[4], uint2 b){
  asm volatile("mma.sync.aligned.m16n8k16.row.col.f32.f16.f16.f32 "
    "{%0,%1,%2,%3}, {%4,%5,%6,%7}, {%8,%9}, {%0,%1,%2,%3};"
    : "+f"(d.x),"+f"(d.y),"+f"(d.z),"+f"(d.w)
    : "r"(a[0]),"r"(a[1]),"r"(a[2]),"r"(a[3]), "r"(b.x),"r"(b.y));
}

// element (e,ch) -> PAIRED fragment-linear half index
__device__ __forceinline__ int frag_idx(int e, int ch){
  int tn = ch>>3, tk = e>>4, nl = ch&7, kl = e&15;
  int lane = nl*4 + ((kl&7)>>1);
  int reg  = kl>>3, pair = kl&1;
  return ((((tn*4 + (tk>>1))*32 + lane)*2 + (tk&1))*4) + reg*2 + pair;
}

// fp16 bilinear tap: lane owns 4 consecutive channels 4L..4L+3 via one LDG.64/tap
__device__ __forceinline__ void sample_h2v(uint4 wraw, int4 ov, const char* bp2,
                                           __half2& s0, __half2& s1){
  const __half2 w0 = *(const __half2*)&wraw.x;
  const __half2 w1 = *(const __half2*)&wraw.y;
  const __half2 w2 = *(const __half2*)&wraw.z;
  const __half2 w3 = *(const __half2*)&wraw.w;
  uint2 a = __ldg((const uint2*)(bp2+ov.x));
  uint2 b = __ldg((const uint2*)(bp2+ov.y));
  uint2 c = __ldg((const uint2*)(bp2+ov.z));
  uint2 d = __ldg((const uint2*)(bp2+ov.w));
  __half2 aL,aH,bL,bH,cL,cH,dL,dH;
  memcpy(&aL,&a.x,4); memcpy(&aH,&a.y,4);
  memcpy(&bL,&b.x,4); memcpy(&bH,&b.y,4);
  memcpy(&cL,&c.x,4); memcpy(&cH,&c.y,4);
  memcpy(&dL,&d.x,4); memcpy(&dH,&d.y,4);
  s0 = __hfma2(w3,dL, __hfma2(w2,cL, __hfma2(w1,bL, __hmul2(w0,aL))));
  s1 = __hfma2(w3,dH, __hfma2(w2,cH, __hfma2(w1,bH, __hmul2(w0,aH))));
}

// ---- tiled img transpose + fp16 convert; z==B slice does the kW transpose ----
__global__ void k_img_transpose(const float* __restrict__ img,
                                const float* __restrict__ kW, int B){
  __shared__ float tile[32][33];
  const int tx = threadIdx.x, ty = threadIdx.y;   // 32x8
  if(blockIdx.z < (unsigned)B){
    const int b  = blockIdx.z;
    const int yx0 = blockIdx.x*32, c0 = blockIdx.y*32;
    #pragma unroll
    for(int cc=0;cc<32;cc+=8)
      tile[cc+ty][tx] = img[((size_t)(b*D + c0+cc+ty))*NPIX + yx0 + tx];
    __syncthreads();
    #pragma unroll
    for(int yy=0;yy<32;yy+=8)
      g_imgT16[((size_t)(b*NPIX + yx0+yy+ty))*D + c0 + tx] = __float2half(tile[tx][yy+ty]);
  } else {
    if(blockIdx.x >= 4) return;
    const int c0 = blockIdx.x*32, d0 = blockIdx.y*32;
    #pragma unroll
    for(int cc=0;cc<32;cc+=8)
      tile[cc+ty][tx] = kW[(c0+cc+ty)*D + d0 + tx];
    __syncthreads();
    #pragma unroll
    for(int yy=0;yy<32;yy+=8)
      g_kT[(d0+yy+ty)*D + c0 + tx] = tile[tx][yy+ty];
  }
}

// ---- matrix + vector preps (paired fragment-linear fp16) ----
__global__ void k_prep_mats(const float* __restrict__ qW,
                            const float* __restrict__ vW,
                            const float* __restrict__ outW,
                            const float* __restrict__ kW,
                            const float* __restrict__ qb,
                            const float* __restrict__ vb,
                            const float* __restrict__ offW){
  const int r = blockIdx.x, t = threadIdx.x;   // r = e, t = ch
  if (blockIdx.y == 0){
    __shared__ float row[D];
    row[t] = qW[r*D+t]; __syncthreads();
    float acc = 0.f;
    #pragma unroll 4
    for(int dd=0; dd<D; dd++) acc = fmaf(row[dd], g_kT[dd*D+t], acc);
    g_Wqkf[frag_idx(r,t)] = __float2half(acc);
  } else if (blockIdx.y == 1){
    __shared__ float row[D];
    row[t] = vW[r*D+t]; __syncthreads();
    float acc = 0.f;
    #pragma unroll 4
    for(int dd=0; dd<D; dd++) acc = fmaf(row[dd], outW[dd*D+t], acc);
    g_W2f[frag_idx(r,t)] = __float2half(acc);
  } else if (blockIdx.y == 2){
    __shared__ float red1[4], red2[4];
    float s1 = qb[t]*kW[r*D+t];
    float s2 = vb[t]*outW[t*D+r];
    s1 = warpSum(s1); s2 = warpSum(s2);
    if((t&31)==0){ red1[t>>5]=s1; red2[t>>5]=s2; }
    __syncthreads();
    if(t==0){
      g_bqk[r] = red1[0]+red1[1]+red1[2]+red1[3];
      g_vbp[r] = red2[0]+red2[1]+red2[2]+red2[3];
    }
  } else {
    if(t < OWC){
      float v = (t < 2*P) ? offW[r*(2*P) + t] : 0.f;
      __half h = __float2half(v);
      g_offWf[frag_idx(r,t)]  = h;
      g_offWlf[frag_idx(r,t)] = __float2half(v - __half2float(h));
    }
  }
}

// ---- main fused kernel ----
__global__ __launch_bounds__(256, 4)
void k_main(const float* __restrict__ x_lidar, const int* __restrict__ indices,
            const float* __restrict__ voxel_size, const float* __restrict__ pc_range,
            const float* __restrict__ trans, const float* __restrict__ offb,
            const float* __restrict__ outb,
            const void* pH, const void* pW, float* __restrict__ out, int N)
{
  const int t    = threadIdx.x;
  const int half = t >> 7;
  const int tc   = t & 127;
  const int lane = t & 31;
  const int wih  = tc >> 5;
  const int w8   = t >> 5;          // warp id 0..7
  const int n0   = blockIdx.x * TP;
  const float du = 2.0f/(WF-1), dv = 2.0f/(HF-1);

  __shared__ __align__(16) __half xh_s[TP][XHP];    // fp16 x (hi), later fp16 agg
  __shared__ __align__(16) __half xlo_s[TP][XHP];   // fp16 x residual (lo)
  __shared__ __align__(16) __half2 qkh_s[TP][64];   // fp16 qk tile (pair j = ch 2j,2j+1)
  __shared__ __align__(16) SmemS u;
  __shared__ float learned_s[TP][2*P];
  __shared__ float centers_s[TP][2];
  __shared__ int   boff_s[TP];
  __shared__ float valid_s[TP][P];
  __shared__ __half logits_h[2][2][24];             // [half][buf][p]
  __shared__ float S_s[TP];

  // ---- load x tile as fp16 hi + lo residual ----
  {
    const float4* xs = (const float4*)x_lidar;
    for(int j=t; j<TP*(D/4); j+=256){
      int pt = j>>5;
      int n = n0+pt; if(n>=N) n = N-1;
      float4 v = xs[(size_t)n*(D/4) + (j&31)];
      __half2 h0 = __float22half2_rn(make_float2(v.x,v.y));
      __half2 h1 = __float22half2_rn(make_float2(v.z,v.w));
      uint2 h; memcpy(&h.x,&h0,4); memcpy(&h.y,&h1,4);
      *(uint2*)&xh_s[pt][(j&31)*4] = h;
      float2 f0 = __half22float2(h0), f1 = __half22float2(h1);
      __half2 l0 = __float22half2_rn(make_float2(v.x-f0.x, v.y-f0.y));
      __half2 l1 = __float22half2_rn(make_float2(v.z-f1.x, v.w-f1.y));
      uint2 l; memcpy(&l.x,&l0,4); memcpy(&l.y,&l1,4);
      *(uint2*)&xlo_s[pt][(j&31)*4] = l;
    }
  }
  __syncthreads();

  const unsigned int abase = smem_u32(&xh_s[0][0]);
  const unsigned int lbase = smem_u32(&xlo_s[0][0]);
  const int arow = lane & 15, acolblk = (lane >> 4) * 8;
  const int r0l = lane>>2, c0l = (lane&3)*2;

  // ---- Phase A (rebalanced): GEMV1 tiles + compensated offsets GEMM ----
  if(w8 < 5){
    float4 accG = make_float4(0.f,0.f,0.f,0.f);
    float4 accO = make_float4(0.f,0.f,0.f,0.f);
    const uint4* BG  = (const uint4*)g_Wqkf;
    const uint4* BOh = (const uint4*)g_offWf;
    const uint4* BOl = (const uint4*)g_offWlf;
    #pragma unroll
    for(int tk2=0; tk2<4; tk2++){
      unsigned int a0[4], a1[4], l0[4], l1[4];
      ldmatrix_x4(a0, abase + (arow*XHP + (2*tk2  )*16 + acolblk)*2);
      ldmatrix_x4(a1, abase + (arow*XHP + (2*tk2+1)*16 + acolblk)*2);
      ldmatrix_x4(l0, lbase + (arow*XHP + (2*tk2  )*16 + acolblk)*2);
      ldmatrix_x4(l1, lbase + (arow*XHP + (2*tk2+1)*16 + acolblk)*2);
      uint4 rG  = __ldg(&BG [(w8*4+tk2)*32 + lane]);
      uint4 rOh = __ldg(&BOh[(w8*4+tk2)*32 + lane]);
      uint4 rOl = __ldg(&BOl[(w8*4+tk2)*32 + lane]);
      mma16816(accG, a0, make_uint2(rG.x,rG.y));  mma16816(accG, a1, make_uint2(rG.z,rG.w));
      mma16816(accO, a0, make_uint2(rOh.x,rOh.y)); mma16816(accO, a1, make_uint2(rOh.z,rOh.w));
      mma16816(accO, l0, make_uint2(rOh.x,rOh.y)); mma16816(accO, l1, make_uint2(rOh.z,rOh.w));
      mma16816(accO, a0, make_uint2(rOl.x,rOl.y)); mma16816(accO, a1, make_uint2(rOl.z,rOl.w));
    }
    {
      const int ch = w8*8 + c0l;
      const float2 bq = *(const float2*)&g_bqk[ch];
      const int pi = w8*4 + (lane&3);
      qkh_s[r0l][pi]   = __float22half2_rn(make_float2(accG.x+bq.x, accG.y+bq.y));
      qkh_s[r0l+8][pi] = __float22half2_rn(make_float2(accG.z+bq.x, accG.w+bq.y));
    }
    const int col0 = w8*8 + c0l, col1 = col0 + 1;
    if(col0 < 2*P){
      float ob0 = __ldg(&offb[col0]);
      float sc0 = (col0&1)? 1.5f*dv : 1.5f*du;
      learned_s[r0l][col0]   = tanhf(accO.x + ob0) * sc0;
      learned_s[r0l+8][col0] = tanhf(accO.z + ob0) * sc0;
    }
    if(col1 < 2*P){
      float ob1 = __ldg(&offb[col1]);
      float sc1 = (col1&1)? 1.5f*dv : 1.5f*du;
      learned_s[r0l][col1]   = tanhf(accO.y + ob1) * sc1;
      learned_s[r0l+8][col1] = tanhf(accO.w + ob1) * sc1;
    }
  } else {
    const uint4* BG = (const uint4*)g_Wqkf;
    for(int t0 = w8; t0 < 16; t0 += 6){
      const int tB = t0 + 3;
      const bool hasB = tB < 16;
      float4 acc0 = make_float4(0.f,0.f,0.f,0.f);
      float4 acc1 = make_float4(0.f,0.f,0.f,0.f);
      #pragma unroll
      for(int tk2=0; tk2<4; tk2++){
        unsigned int a0[4], a1[4];
        ldmatrix_x4(a0, abase + (arow*XHP + (2*tk2  )*16 + acolblk)*2);
        ldmatrix_x4(a1, abase + (arow*XHP + (2*tk2+1)*16 + acolblk)*2);
        uint4 rA = __ldg(&BG[(t0*4+tk2)*32 + lane]);
        mma16816(acc0, a0, make_uint2(rA.x,rA.y)); mma16816(acc0, a1, make_uint2(rA.z,rA.w));
        if(hasB){
          uint4 rB = __ldg(&BG[(tB*4+tk2)*32 + lane]);
          mma16816(acc1, a0, make_uint2(rB.x,rB.y)); mma16816(acc1, a1, make_uint2(rB.z,rB.w));
        }
      }
      {
        const int ch = t0*8 + c0l;
        const float2 bq = *(const float2*)&g_bqk[ch];
        const int pi = t0*4 + (lane&3);
        qkh_s[r0l][pi]   = __float22half2_rn(make_float2(acc0.x+bq.x, acc0.y+bq.y));
        qkh_s[r0l+8][pi] = __float22half2_rn(make_float2(acc0.z+bq.x, acc0.w+bq.y));
      }
      if(hasB){
        const int ch = tB*8 + c0l;
        const float2 bq = *(const float2*)&g_bqk[ch];
        const int pi = tB*4 + (lane&3);
        qkh_s[r0l][pi]   = __float22half2_rn(make_float2(acc1.x+bq.x, acc1.y+bq.y));
        qkh_s[r0l+8][pi] = __float22half2_rn(make_float2(acc1.z+bq.x, acc1.w+bq.y));
      }
    }
  }
  if(t < TP){
    int n = min(n0+t, N-1);
    const int4 idx = *(const int4*)(indices + (size_t)n*4);
    float cvx=voxel_size[0]*8.f, cvy=voxel_size[1]*8.f, cvz=voxel_size[2]*8.f;
    float phx = (float)idx.w*cvx + pc_range[0] + 0.5f*cvx;
    float phy = (float)idx.z*cvy + pc_range[1] + 0.5f*cvy;
    float phz = (float)idx.y*cvz + pc_range[2] + 0.5f*cvz;
    const float* T = trans + idx.x*12;
    float p0 = T[0]*phx + T[1]*phy + T[2]*phz  + T[3];
    float p1 = T[4]*phx + T[5]*phy + T[6]*phz  + T[7];
    float p2 = T[8]*phx + T[9]*phy + T[10]*phz + T[11];
    float depth = fmaxf(p2, 1e-5f);
    const int Wi = read_dim(pW), Hi = read_dim(pH);
    float uf = p0/depth * ((float)WF/(float)Wi);
    float vf = p1/depth * ((float)HF/(float)Hi);
    centers_s[t][0] = uf*du - 1.0f;
    centers_s[t][1] = vf*dv - 1.0f;
    boff_s[t] = idx.x * NPIX;
  }
  __syncthreads();

  // ---- Phase B: geometry (o stored as BYTE offsets) ----
  for(int j=t; j<TP*P; j+=256){
    int pt = j/P, p = j - pt*P;
    float gx = centers_s[pt][0] + c_base[2*p]  *du + learned_s[pt][2*p];
    float gy = centers_s[pt][1] + c_base[2*p+1]*dv + learned_s[pt][2*p+1];
    valid_s[pt][p] = (fabsf(gx)<=1.f && fabsf(gy)<=1.f) ? 1.f : 0.f;
    float px = (gx+1.f)*0.5f*(WF-1);
    float py = (gy+1.f)*0.5f*(HF-1);
    float fxf = floorf(px), fyf = floorf(py);
    int x0=(int)fxf, y0=(int)fyf;
    float fx = px-fxf, fy = py-fyf;
    int bb = boff_s[pt];
    #pragma unroll
    for(int tap=0;tap<4;tap++){
      int xc = x0 + (tap&1), yc = y0 + (tap>>1);
      bool inb = (xc>=0 && xc<WF && yc>=0 && yc<HF);
      float wx = (tap&1)? fx : 1.f-fx;
      float wy = (tap>>1)? fy : 1.f-fy;
      u.w[pt][p][tap] = __float2half2_rn(inb ? wx*wy : 0.f);
      int xcc = min(max(xc,0),WF-1), ycc = min(max(yc,0),HF-1);
      u.o[pt][p][tap] = (bb + ycc*WF + xcc)*(D*2);   // byte offset
    }
  }
  __syncthreads();

  const float scale = 0.17677669529663687f;
  const char* bp2 = (const char*)g_imgT16 + lane*8;   // lane owns ch 4L..4L+3

  // ---- main loop: pipelined, ONE barrier per point ----
  int buf = 0;
  for(int ii=0; ii<TP; ii+=2){
    const int i = ii + half;
    const uint2 qr = *(const uint2*)&qkh_s[i][2*lane];
    __half2 q0, q1; memcpy(&q0,&qr.x,4); memcpy(&q1,&qr.y,4);
    __half2 sv0[5], sv1[5];
    __half2 d2[5];

    #pragma unroll
    for(int k=0;k<4;k++){
      const int p = wih + 4*k;
      const uint4 wraw = *(const uint4*)u.w[i][p];
      const int4  ov = *(const int4*) u.o[i][p];
      __half2 s0, s1;
      sample_h2v(wraw, ov, bp2, s0, s1);
      sv0[k]=s0; sv1[k]=s1;
      d2[k] = __hfma2(s1, q1, __hmul2(s0, q0));
    }
    if(wih==3){
      const uint4 wraw = *(const uint4*)u.w[i][16];
      const int4  ov = *(const int4*) u.o[i][16];
      __half2 s0, s1;
      sample_h2v(wraw, ov, bp2, s0, s1);
      sv0[4]=s0; sv1[4]=s1;
      d2[4] = __hfma2(s1, q1, __hmul2(s0, q0));
    }
    // packed half2 butterfly reductions (2 dots per chain)
    {
      __half2 e01 = __halves2half2(hsum2(d2[0]), hsum2(d2[1]));
      __half2 e23 = __halves2half2(hsum2(d2[2]), hsum2(d2[3]));
      #pragma unroll
      for(int o=16;o>0;o>>=1){
        e01 = __hadd2(e01, shfl_xor_h2(e01, o));
        e23 = __hadd2(e23, shfl_xor_h2(e23, o));
      }
      if(lane==0){
        logits_h[half][buf][wih]    = __low2half(e01);
        logits_h[half][buf][wih+4]  = __high2half(e01);
        logits_h[half][buf][wih+8]  = __low2half(e23);
        logits_h[half][buf][wih+12] = __high2half(e23);
      }
      if(wih==3){
        __half2 e4 = __halves2half2(hsum2(d2[4]), __float2half(0.f));
        #pragma unroll
        for(int o=16;o>0;o>>=1) e4 = __hadd2(e4, shfl_xor_h2(e4, o));
        if(lane==0) logits_h[half][buf][16] = __low2half(e4);
      }
    }
    barhalf(half);

    // combine previous point's aggregates into fp16 agg tile (deferred)
    if(ii >= 2 && tc < 64){
      const int ip = ii - 2 + half;
      const int pb = buf^1;
      __half2 v = __hadd2(__hadd2(u.paggh[half][pb][0][tc], u.paggh[half][pb][1][tc]),
                          __hadd2(u.paggh[half][pb][2][tc], u.paggh[half][pb][3][tc]));
      *(__half2*)&xh_s[ip][2*tc] = v;
    }

    // collapsed masked softmax (all warps; aux by wih==0)
    float myA;
    {
      const bool act = lane < P;
      const bool isv = act && (valid_s[i][lane] > 0.f);
      float l = isv ? __half2float(logits_h[half][buf][lane])*scale : -10000.f;
      float e = isv ? expf(l) : 0.f;
      float Ssum = warpSum(e);
      unsigned int vmask = __ballot_sync(0xffffffffu, isv);
      myA = vmask ? e * (1.f/Ssum) : 0.f;
      if(wih==0){
        float pc = fmaxf(myA, 1e-6f);
        float ent = warpSum(act ? -pc*logf(pc) : 0.f);
        float lx = act ? learned_s[i][2*lane]   : 0.f;
        float ly = act ? learned_s[i][2*lane+1] : 0.f;
        float nrm = warpSum(act ? sqrtf(lx*lx+ly*ly) : 0.f);
        if(lane==0){
          S_s[i] = vmask ? 1.f : 0.f;
          int n = n0 + i;
          if(n < N){
            float vcnt = (float)__popc(vmask);
            float inst = (nrm/(float)P) / (1.5f*sqrtf(du*du+dv*dv));
            size_t base = (size_t)N*D;
            out[base + n]               = vcnt/(float)P;
            out[base + (size_t)N + n]   = fminf(fmaxf(expf(-inst),0.f),1.f);
            out[base + 2*(size_t)N + n] = fminf(fmaxf(1.f - ent/logf((float)P),0.f),1.f);
          }
        }
      }
    }

    // aggregate in registers with shfl-broadcast attn -> half2 pagg (buffered)
    {
      float4 acc4 = make_float4(0.f,0.f,0.f,0.f);
      #pragma unroll
      for(int k=0;k<4;k++){
        float a = __shfl_sync(0xffffffffu, myA, wih+4*k);
        const float2 lo = __half22float2(sv0[k]);
        const float2 hi = __half22float2(sv1[k]);
        acc4.x = fmaf(a, lo.x, acc4.x);
        acc4.y = fmaf(a, lo.y, acc4.y);
        acc4.z = fmaf(a, hi.x, acc4.z);
        acc4.w = fmaf(a, hi.y, acc4.w);
      }
      float a16 = __shfl_sync(0xffffffffu, myA, 16);
      if(wih==3){
        const float2 lo = __half22float2(sv0[4]);
        const float2 hi = __half22float2(sv1[4]);
        acc4.x = fmaf(a16, lo.x, acc4.x);
        acc4.y = fmaf(a16, lo.y, acc4.y);
        acc4.z = fmaf(a16, hi.x, acc4.z);
        acc4.w = fmaf(a16, hi.y, acc4.w);
      }
      // lane holds ch 4L..4L+3 -> pagg pair indices 2L, 2L+1 (one STS.64)
      __half2 p0 = __float22half2_rn(make_float2(acc4.x, acc4.y));
      __half2 p1 = __float22half2_rn(make_float2(acc4.z, acc4.w));
      uint2 pr; memcpy(&pr.x,&p0,4); memcpy(&pr.y,&p1,4);
      *(uint2*)&u.paggh[half][buf][wih][2*lane] = pr;
    }
    buf ^= 1;
  }
  barhalf(half);
  if(tc < 64){   // final combine
    const int ip = TP - 2 + half;
    const int pb = buf^1;
    __half2 v = __hadd2(__hadd2(u.paggh[half][pb][0][tc], u.paggh[half][pb][1][tc]),
                        __hadd2(u.paggh[half][pb][2][tc], u.paggh[half][pb][3][tc]));
    *(__half2*)&xh_s[ip][2*tc] = v;
  }
  __syncthreads();

  // ---- GEMV2 via tensor cores: out = agg @ W2 + S*vbp + out_b ----
  {
    float4 acc0 = make_float4(0.f,0.f,0.f,0.f);
    float4 acc1 = make_float4(0.f,0.f,0.f,0.f);
    const uint4* Bf = (const uint4*)g_W2f;
    #pragma unroll
    for(int tk2=0; tk2<4; tk2++){
      unsigned int a0[4], a1[4];
      ldmatrix_x4(a0, abase + (arow*XHP + (2*tk2  )*16 + acolblk)*2);
      ldmatrix_x4(a1, abase + (arow*XHP + (2*tk2+1)*16 + acolblk)*2);
      uint4 rA = __ldg(&Bf[((2*w8  )*4+tk2)*32 + lane]);
      uint4 rB = __ldg(&Bf[((2*w8+1)*4+tk2)*32 + lane]);
      mma16816(acc0, a0, make_uint2(rA.x,rA.y)); mma16816(acc0, a1, make_uint2(rA.z,rA.w));
      mma16816(acc1, a0, make_uint2(rB.x,rB.y)); mma16816(acc1, a1, make_uint2(rB.z,rB.w));
    }
    const float S0 = S_s[r0l], S1 = S_s[r0l+8];
    #pragma unroll
    for(int nt=0; nt<2; nt++){
      const int ch = (2*w8+nt)*8 + c0l;
      const float4 acc = nt ? acc1 : acc0;
      const float2 ob  = *(const float2*)&outb[ch];
      const float2 vbp = *(const float2*)&g_vbp[ch];
      if(n0+r0l < N)
        *(float2*)&out[(size_t)(n0+r0l)*D + ch] =
          make_float2(acc.x + ob.x + S0*vbp.x, acc.y + ob.y + S0*vbp.y);
      if(n0+r0l+8 < N)
        *(float2*)&out[(size_t)(n0+r0l+8)*D + ch] =
          make_float2(acc.z + ob.x + S1*vbp.x, acc.w + ob.y + S1*vbp.y);
    }
  }
}

extern "C" void kernel_launch(void* const* d_in, const int* in_sizes, int n_in,
                              void* d_out, int out_size) {
  const float* x      = (const float*)d_in[0];
  const int*   indices= (const int*)  d_in[1];
  const float* img    = (const float*)d_in[2];
  const float* voxel  = (const float*)d_in[3];
  const float* pcr    = (const float*)d_in[4];
  const float* trans  = (const float*)d_in[5];
  const float* offW   = (const float*)d_in[6];
  const float* offb   = (const float*)d_in[7];
  const float* qW     = (const float*)d_in[8];
  const float* qb     = (const float*)d_in[9];
  const float* kW     = (const float*)d_in[10];
  const float* vW     = (const float*)d_in[12];
  const float* vb     = (const float*)d_in[13];
  const float* outW   = (const float*)d_in[14];
  const float* outb   = (const float*)d_in[15];
  const void*  pH     = d_in[16];
  const void*  pW     = d_in[17];

  int N = in_sizes[0]/D;
  int B = in_sizes[5]/12;

  dim3 tb(32,8);
  k_img_transpose<<<dim3(NPIX/32, D/32, B+1), tb>>>(img, kW, B);
  k_prep_mats<<<dim3(D,4), D>>>(qW, vW, outW, kW, qb, vb, offW);
  k_main<<<(N+TP-1)/TP, 256>>>(x, indices, voxel, pcr, trans, offb, outb,
                               pH, pW, (float*)d_out, N);
}

// round 17
// speedup vs baseline: 4.8354x; 1.1034x over previous
#include <cuda_runtime.h>
#include <cuda_fp16.h>
#include <cstdint>

#define D   128
#define P   17
#define HF  56
#define WF  100
#define TP  16
#define NPIX (HF*WF)
#define XHP 136   // fp16 x-tile row pitch (halves)
#define OWC 40    // padded offset-weight cols (2P=34 -> 40)

// ---- device scratch ----
__device__ __half g_imgT16[2*NPIX*D];            // [B,H,W,C] fp16
__device__ float g_kT[D*D];                      // k_W^T
__device__ __align__(16) __half g_Wqkf[D*D];     // pair-fragment fp16 weights
__device__ __align__(16) __half g_W2f[D*D];
__device__ __align__(16) __half g_offWf[D*OWC];  // offset weights hi
__device__ __align__(16) __half g_offWlf[D*OWC]; // offset weights lo (residual)
__device__ float g_bqk[D];
__device__ float g_vbp[D];

__constant__ float c_base[2*P] = {
  -1,-1, -1,0, -1,1, 0,-1, 0,0, 0,1, 1,-1, 1,0, 1,1,
  -3,-3, -3,0, -3,3, 0,-3, 0,3, 3,-3, 3,0, 3,3 };

struct SmemS {
  __half2 w[TP][P][4];              // dup'd fp16 tap weights
  int     o[TP][P][4];              // BYTE offsets into g_imgT16
  __half2 paggh[2][2][4][64];       // [half][buf][warp][chpair]
};

__device__ __forceinline__ float warpSum(float v){
  #pragma unroll
  for(int o=16;o>0;o>>=1) v += __shfl_xor_sync(0xffffffffu, v, o);
  return v;
}
__device__ __forceinline__ __half2 shfl_xor_h2(__half2 v, int o){
  unsigned int u; memcpy(&u,&v,4);
  u = __shfl_xor_sync(0xffffffffu, u, o);
  __half2 r; memcpy(&r,&u,4); return r;
}
__device__ __forceinline__ __half hsum2(__half2 v){
  return __hadd(__low2half(v), __high2half(v));
}
__device__ __forceinline__ int read_dim(const void* p){
  int iv = *(const int*)p;
  if (iv > 0 && iv < 1000000) return iv;
  return (int)(*(const float*)p);
}
__device__ __forceinline__ void barhalf(int half){
  asm volatile("bar.sync %0, 128;" :: "r"(half+1) : "memory");
}
__device__ __forceinline__ unsigned int smem_u32(const void* p){
  return (unsigned int)__cvta_generic_to_shared(p);
}
__device__ __forceinline__ void ldmatrix_x4(unsigned int r[4], unsigned int addr){
  asm volatile("ldmatrix.sync.aligned.m8n8.x4.shared.b16 {%0,%1,%2,%3}, [%4];"
    : "=r"(r[0]),"=r"(r[1]),"=r"(r[2]),"=r"(r[3]) : "r"(addr));
}
__device__ __forceinline__ void mma16816(float4& d, const unsigned int a[4], uint2 b){
  asm volatile("mma.sync.aligned.m16n8k16.row.col.f32.f16.f16.f32 "
    "{%0,%1,%2,%3}, {%4,%5,%6,%7}, {%8,%9}, {%0,%1,%2,%3};"
    : "+f"(d.x),"+f"(d.y),"+f"(d.z),"+f"(d.w)
    : "r"(a[0]),"r"(a[1]),"r"(a[2]),"r"(a[3]), "r"(b.x),"r"(b.y));
}

// element (e,ch) -> PAIRED fragment-linear half index
__device__ __forceinline__ int frag_idx(int e, int ch){
  int tn = ch>>3, tk = e>>4, nl = ch&7, kl = e&15;
  int lane = nl*4 + ((kl&7)>>1);
  int reg  = kl>>3, pair = kl&1;
  return ((((tn*4 + (tk>>1))*32 + lane)*2 + (tk&1))*4) + reg*2 + pair;
}

// fp16 bilinear tap: lane owns 4 consecutive channels 4L..4L+3 via one LDG.64/tap
__device__ __forceinline__ void sample_h2v(uint4 wraw, int4 ov, const char* bp2,
                                           __half2& s0, __half2& s1){
  const __half2 w0 = *(const __half2*)&wraw.x;
  const __half2 w1 = *(const __half2*)&wraw.y;
  const __half2 w2 = *(const __half2*)&wraw.z;
  const __half2 w3 = *(const __half2*)&wraw.w;
  uint2 a = __ldg((const uint2*)(bp2+ov.x));
  uint2 b = __ldg((const uint2*)(bp2+ov.y));
  uint2 c = __ldg((const uint2*)(bp2+ov.z));
  uint2 d = __ldg((const uint2*)(bp2+ov.w));
  __half2 aL,aH,bL,bH,cL,cH,dL,dH;
  memcpy(&aL,&a.x,4); memcpy(&aH,&a.y,4);
  memcpy(&bL,&b.x,4); memcpy(&bH,&b.y,4);
  memcpy(&cL,&c.x,4); memcpy(&cH,&c.y,4);
  memcpy(&dL,&d.x,4); memcpy(&dH,&d.y,4);
  s0 = __hfma2(w3,dL, __hfma2(w2,cL, __hfma2(w1,bL, __hmul2(w0,aL))));
  s1 = __hfma2(w3,dH, __hfma2(w2,cH, __hfma2(w1,bH, __hmul2(w0,aH))));
}

// ---- tiled img transpose + fp16 convert; z==B slice does the kW transpose ----
__global__ void k_img_transpose(const float* __restrict__ img,
                                const float* __restrict__ kW, int B){
  __shared__ float tile[32][33];
  const int tx = threadIdx.x, ty = threadIdx.y;   // 32x8
  if(blockIdx.z < (unsigned)B){
    const int b  = blockIdx.z;
    const int yx0 = blockIdx.x*32, c0 = blockIdx.y*32;
    #pragma unroll
    for(int cc=0;cc<32;cc+=8)
      tile[cc+ty][tx] = img[((size_t)(b*D + c0+cc+ty))*NPIX + yx0 + tx];
    __syncthreads();
    #pragma unroll
    for(int yy=0;yy<32;yy+=8)
      g_imgT16[((size_t)(b*NPIX + yx0+yy+ty))*D + c0 + tx] = __float2half(tile[tx][yy+ty]);
  } else {
    if(blockIdx.x >= 4) return;
    const int c0 = blockIdx.x*32, d0 = blockIdx.y*32;
    #pragma unroll
    for(int cc=0;cc<32;cc+=8)
      tile[cc+ty][tx] = kW[(c0+cc+ty)*D + d0 + tx];
    __syncthreads();
    #pragma unroll
    for(int yy=0;yy<32;yy+=8)
      g_kT[(d0+yy+ty)*D + c0 + tx] = tile[tx][yy+ty];
  }
}

// ---- matrix + vector preps (paired fragment-linear fp16) ----
__global__ void k_prep_mats(const float* __restrict__ qW,
                            const float* __restrict__ vW,
                            const float* __restrict__ outW,
                            const float* __restrict__ kW,
                            const float* __restrict__ qb,
                            const float* __restrict__ vb,
                            const float* __restrict__ offW){
  const int r = blockIdx.x, t = threadIdx.x;   // r = e, t = ch
  if (blockIdx.y == 0){
    __shared__ float row[D];
    row[t] = qW[r*D+t]; __syncthreads();
    float acc = 0.f;
    #pragma unroll 4
    for(int dd=0; dd<D; dd++) acc = fmaf(row[dd], g_kT[dd*D+t], acc);
    g_Wqkf[frag_idx(r,t)] = __float2half(acc);
  } else if (blockIdx.y == 1){
    __shared__ float row[D];
    row[t] = vW[r*D+t]; __syncthreads();
    float acc = 0.f;
    #pragma unroll 4
    for(int dd=0; dd<D; dd++) acc = fmaf(row[dd], outW[dd*D+t], acc);
    g_W2f[frag_idx(r,t)] = __float2half(acc);
  } else if (blockIdx.y == 2){
    __shared__ float red1[4], red2[4];
    float s1 = qb[t]*kW[r*D+t];
    float s2 = vb[t]*outW[t*D+r];
    s1 = warpSum(s1); s2 = warpSum(s2);
    if((t&31)==0){ red1[t>>5]=s1; red2[t>>5]=s2; }
    __syncthreads();
    if(t==0){
      g_bqk[r] = red1[0]+red1[1]+red1[2]+red1[3];
      g_vbp[r] = red2[0]+red2[1]+red2[2]+red2[3];
    }
  } else {
    if(t < OWC){
      float v = (t < 2*P) ? offW[r*(2*P) + t] : 0.f;
      __half h = __float2half(v);
      g_offWf[frag_idx(r,t)]  = h;
      g_offWlf[frag_idx(r,t)] = __float2half(v - __half2float(h));
    }
  }
}

// ---- main fused kernel ----
__global__ __launch_bounds__(256, 4)
void k_main(const float* __restrict__ x_lidar, const int* __restrict__ indices,
            const float* __restrict__ voxel_size, const float* __restrict__ pc_range,
            const float* __restrict__ trans, const float* __restrict__ offb,
            const float* __restrict__ outb,
            const void* pH, const void* pW, float* __restrict__ out, int N)
{
  const int t    = threadIdx.x;
  const int half = t >> 7;
  const int tc   = t & 127;
  const int lane = t & 31;
  const int wih  = tc >> 5;
  const int w8   = t >> 5;          // warp id 0..7
  const int n0   = blockIdx.x * TP;
  const float du = 2.0f/(WF-1), dv = 2.0f/(HF-1);

  __shared__ __align__(16) __half xh_s[TP][XHP];    // fp16 x (hi), later fp16 agg
  __shared__ __align__(16) __half xlo_s[TP][XHP];   // fp16 x residual (lo)
  __shared__ __align__(16) __half2 qkh_s[TP][64];   // fp16 qk tile (pair j = ch 2j,2j+1)
  __shared__ __align__(16) SmemS u;
  __shared__ float learned_s[TP][2*P];
  __shared__ float centers_s[TP][2];
  __shared__ int   boff_s[TP];
  __shared__ float valid_s[TP][P];
  __shared__ __half logits_h[2][2][24];             // [half][buf][p]
  __shared__ float S_s[TP];

  // ---- load x tile as fp16 hi + lo residual ----
  {
    const float4* xs = (const float4*)x_lidar;
    for(int j=t; j<TP*(D/4); j+=256){
      int pt = j>>5;
      int n = n0+pt; if(n>=N) n = N-1;
      float4 v = xs[(size_t)n*(D/4) + (j&31)];
      __half2 h0 = __float22half2_rn(make_float2(v.x,v.y));
      __half2 h1 = __float22half2_rn(make_float2(v.z,v.w));
      uint2 h; memcpy(&h.x,&h0,4); memcpy(&h.y,&h1,4);
      *(uint2*)&xh_s[pt][(j&31)*4] = h;
      float2 f0 = __half22float2(h0), f1 = __half22float2(h1);
      __half2 l0 = __float22half2_rn(make_float2(v.x-f0.x, v.y-f0.y));
      __half2 l1 = __float22half2_rn(make_float2(v.z-f1.x, v.w-f1.y));
      uint2 l; memcpy(&l.x,&l0,4); memcpy(&l.y,&l1,4);
      *(uint2*)&xlo_s[pt][(j&31)*4] = l;
    }
  }
  __syncthreads();

  const unsigned int abase = smem_u32(&xh_s[0][0]);
  const unsigned int lbase = smem_u32(&xlo_s[0][0]);
  const int arow = lane & 15, acolblk = (lane >> 4) * 8;
  const int r0l = lane>>2, c0l = (lane&3)*2;

  // ---- Phase A (rebalanced): GEMV1 tiles + compensated offsets GEMM ----
  if(w8 < 5){
    float4 accG = make_float4(0.f,0.f,0.f,0.f);
    float4 accO = make_float4(0.f,0.f,0.f,0.f);
    const uint4* BG  = (const uint4*)g_Wqkf;
    const uint4* BOh = (const uint4*)g_offWf;
    const uint4* BOl = (const uint4*)g_offWlf;
    #pragma unroll
    for(int tk2=0; tk2<4; tk2++){
      unsigned int a0[4], a1[4], l0[4], l1[4];
      ldmatrix_x4(a0, abase + (arow*XHP + (2*tk2  )*16 + acolblk)*2);
      ldmatrix_x4(a1, abase + (arow*XHP + (2*tk2+1)*16 + acolblk)*2);
      ldmatrix_x4(l0, lbase + (arow*XHP + (2*tk2  )*16 + acolblk)*2);
      ldmatrix_x4(l1, lbase + (arow*XHP + (2*tk2+1)*16 + acolblk)*2);
      uint4 rG  = __ldg(&BG [(w8*4+tk2)*32 + lane]);
      uint4 rOh = __ldg(&BOh[(w8*4+tk2)*32 + lane]);
      uint4 rOl = __ldg(&BOl[(w8*4+tk2)*32 + lane]);
      mma16816(accG, a0, make_uint2(rG.x,rG.y));  mma16816(accG, a1, make_uint2(rG.z,rG.w));
      mma16816(accO, a0, make_uint2(rOh.x,rOh.y)); mma16816(accO, a1, make_uint2(rOh.z,rOh.w));
      mma16816(accO, l0, make_uint2(rOh.x,rOh.y)); mma16816(accO, l1, make_uint2(rOh.z,rOh.w));
      mma16816(accO, a0, make_uint2(rOl.x,rOl.y)); mma16816(accO, a1, make_uint2(rOl.z,rOl.w));
    }
    {
      const int ch = w8*8 + c0l;
      const float2 bq = *(const float2*)&g_bqk[ch];
      const int pi = w8*4 + (lane&3);
      qkh_s[r0l][pi]   = __float22half2_rn(make_float2(accG.x+bq.x, accG.y+bq.y));
      qkh_s[r0l+8][pi] = __float22half2_rn(make_float2(accG.z+bq.x, accG.w+bq.y));
    }
    const int col0 = w8*8 + c0l, col1 = col0 + 1;
    if(col0 < 2*P){
      float ob0 = __ldg(&offb[col0]);
      float sc0 = (col0&1)? 1.5f*dv : 1.5f*du;
      learned_s[r0l][col0]   = tanhf(accO.x + ob0) * sc0;
      learned_s[r0l+8][col0] = tanhf(accO.z + ob0) * sc0;
    }
    if(col1 < 2*P){
      float ob1 = __ldg(&offb[col1]);
      float sc1 = (col1&1)? 1.5f*dv : 1.5f*du;
      learned_s[r0l][col1]   = tanhf(accO.y + ob1) * sc1;
      learned_s[r0l+8][col1] = tanhf(accO.w + ob1) * sc1;
    }
  } else {
    const uint4* BG = (const uint4*)g_Wqkf;
    for(int t0 = w8; t0 < 16; t0 += 6){
      const int tB = t0 + 3;
      const bool hasB = tB < 16;
      float4 acc0 = make_float4(0.f,0.f,0.f,0.f);
      float4 acc1 = make_float4(0.f,0.f,0.f,0.f);
      #pragma unroll
      for(int tk2=0; tk2<4; tk2++){
        unsigned int a0[4], a1[4];
        ldmatrix_x4(a0, abase + (arow*XHP + (2*tk2  )*16 + acolblk)*2);
        ldmatrix_x4(a1, abase + (arow*XHP + (2*tk2+1)*16 + acolblk)*2);
        uint4 rA = __ldg(&BG[(t0*4+tk2)*32 + lane]);
        mma16816(acc0, a0, make_uint2(rA.x,rA.y)); mma16816(acc0, a1, make_uint2(rA.z,rA.w));
        if(hasB){
          uint4 rB = __ldg(&BG[(tB*4+tk2)*32 + lane]);
          mma16816(acc1, a0, make_uint2(rB.x,rB.y)); mma16816(acc1, a1, make_uint2(rB.z,rB.w));
        }
      }
      {
        const int ch = t0*8 + c0l;
        const float2 bq = *(const float2*)&g_bqk[ch];
        const int pi = t0*4 + (lane&3);
        qkh_s[r0l][pi]   = __float22half2_rn(make_float2(acc0.x+bq.x, acc0.y+bq.y));
        qkh_s[r0l+8][pi] = __float22half2_rn(make_float2(acc0.z+bq.x, acc0.w+bq.y));
      }
      if(hasB){
        const int ch = tB*8 + c0l;
        const float2 bq = *(const float2*)&g_bqk[ch];
        const int pi = tB*4 + (lane&3);
        qkh_s[r0l][pi]   = __float22half2_rn(make_float2(acc1.x+bq.x, acc1.y+bq.y));
        qkh_s[r0l+8][pi] = __float22half2_rn(make_float2(acc1.z+bq.x, acc1.w+bq.y));
      }
    }
  }
  if(t < TP){
    int n = min(n0+t, N-1);
    const int4 idx = *(const int4*)(indices + (size_t)n*4);
    float cvx=voxel_size[0]*8.f, cvy=voxel_size[1]*8.f, cvz=voxel_size[2]*8.f;
    float phx = (float)idx.w*cvx + pc_range[0] + 0.5f*cvx;
    float phy = (float)idx.z*cvy + pc_range[1] + 0.5f*cvy;
    float phz = (float)idx.y*cvz + pc_range[2] + 0.5f*cvz;
    const float* T = trans + idx.x*12;
    float p0 = T[0]*phx + T[1]*phy + T[2]*phz  + T[3];
    float p1 = T[4]*phx + T[5]*phy + T[6]*phz  + T[7];
    float p2 = T[8]*phx + T[9]*phy + T[10]*phz + T[11];
    float depth = fmaxf(p2, 1e-5f);
    const int Wi = read_dim(pW), Hi = read_dim(pH);
    float uf = p0/depth * ((float)WF/(float)Wi);
    float vf = p1/depth * ((float)HF/(float)Hi);
    centers_s[t][0] = uf*du - 1.0f;
    centers_s[t][1] = vf*dv - 1.0f;
    boff_s[t] = idx.x * NPIX;
  }
  __syncthreads();

  // ---- Phase B: geometry (o stored as BYTE offsets) ----
  for(int j=t; j<TP*P; j+=256){
    int pt = j/P, p = j - pt*P;
    float gx = centers_s[pt][0] + c_base[2*p]  *du + learned_s[pt][2*p];
    float gy = centers_s[pt][1] + c_base[2*p+1]*dv + learned_s[pt][2*p+1];
    valid_s[pt][p] = (fabsf(gx)<=1.f && fabsf(gy)<=1.f) ? 1.f : 0.f;
    float px = (gx+1.f)*0.5f*(WF-1);
    float py = (gy+1.f)*0.5f*(HF-1);
    float fxf = floorf(px), fyf = floorf(py);
    int x0=(int)fxf, y0=(int)fyf;
    float fx = px-fxf, fy = py-fyf;
    int bb = boff_s[pt];
    #pragma unroll
    for(int tap=0;tap<4;tap++){
      int xc = x0 + (tap&1), yc = y0 + (tap>>1);
      bool inb = (xc>=0 && xc<WF && yc>=0 && yc<HF);
      float wx = (tap&1)? fx : 1.f-fx;
      float wy = (tap>>1)? fy : 1.f-fy;
      u.w[pt][p][tap] = __float2half2_rn(inb ? wx*wy : 0.f);
      int xcc = min(max(xc,0),WF-1), ycc = min(max(yc,0),HF-1);
      u.o[pt][p][tap] = (bb + ycc*WF + xcc)*(D*2);   // byte offset
    }
  }
  __syncthreads();

  const float scale = 0.17677669529663687f;
  const char* bp2 = (const char*)g_imgT16 + lane*8;   // lane owns ch 4L..4L+3
  const __half2 hzero = __float2half2_rn(0.f);

  // ---- main loop: pipelined, ONE barrier per point ----
  int buf = 0;
  for(int ii=0; ii<TP; ii+=2){
    const int i = ii + half;
    const uint2 qr = *(const uint2*)&qkh_s[i][2*lane];
    __half2 q0, q1; memcpy(&q0,&qr.x,4); memcpy(&q1,&qr.y,4);
    __half2 sv0[5], sv1[5];
    __half2 d2[5];

    // validity-gated sampling: invalid points contribute exact zeros
    #pragma unroll
    for(int k=0;k<4;k++){
      const int p = wih + 4*k;
      if(valid_s[i][p] > 0.f){
        const uint4 wraw = *(const uint4*)u.w[i][p];
        const int4  ov = *(const int4*) u.o[i][p];
        __half2 s0, s1;
        sample_h2v(wraw, ov, bp2, s0, s1);
        sv0[k]=s0; sv1[k]=s1;
        d2[k] = __hfma2(s1, q1, __hmul2(s0, q0));
      } else {
        sv0[k]=hzero; sv1[k]=hzero; d2[k]=hzero;
      }
    }
    if(wih==3){
      if(valid_s[i][16] > 0.f){
        const uint4 wraw = *(const uint4*)u.w[i][16];
        const int4  ov = *(const int4*) u.o[i][16];
        __half2 s0, s1;
        sample_h2v(wraw, ov, bp2, s0, s1);
        sv0[4]=s0; sv1[4]=s1;
        d2[4] = __hfma2(s1, q1, __hmul2(s0, q0));
      } else {
        sv0[4]=hzero; sv1[4]=hzero; d2[4]=hzero;
      }
    }
    // packed half2 butterfly reductions (2 dots per chain)
    {
      __half2 e01 = __halves2half2(hsum2(d2[0]), hsum2(d2[1]));
      __half2 e23 = __halves2half2(hsum2(d2[2]), hsum2(d2[3]));
      #pragma unroll
      for(int o=16;o>0;o>>=1){
        e01 = __hadd2(e01, shfl_xor_h2(e01, o));
        e23 = __hadd2(e23, shfl_xor_h2(e23, o));
      }
      if(lane==0){
        logits_h[half][buf][wih]    = __low2half(e01);
        logits_h[half][buf][wih+4]  = __high2half(e01);
        logits_h[half][buf][wih+8]  = __low2half(e23);
        logits_h[half][buf][wih+12] = __high2half(e23);
      }
      if(wih==3){
        __half2 e4 = __halves2half2(hsum2(d2[4]), __float2half(0.f));
        #pragma unroll
        for(int o=16;o>0;o>>=1) e4 = __hadd2(e4, shfl_xor_h2(e4, o));
        if(lane==0) logits_h[half][buf][16] = __low2half(e4);
      }
    }
    barhalf(half);

    // combine previous point's aggregates into fp16 agg tile (deferred)
    if(ii >= 2 && tc < 64){
      const int ip = ii - 2 + half;
      const int pb = buf^1;
      __half2 v = __hadd2(__hadd2(u.paggh[half][pb][0][tc], u.paggh[half][pb][1][tc]),
                          __hadd2(u.paggh[half][pb][2][tc], u.paggh[half][pb][3][tc]));
      *(__half2*)&xh_s[ip][2*tc] = v;
    }

    // collapsed masked softmax (all warps; aux by wih==0)
    float myA;
    {
      const bool act = lane < P;
      const bool isv = act && (valid_s[i][lane] > 0.f);
      float l = isv ? __half2float(logits_h[half][buf][lane])*scale : -10000.f;
      float e = isv ? expf(l) : 0.f;
      float Ssum = warpSum(e);
      unsigned int vmask = __ballot_sync(0xffffffffu, isv);
      myA = vmask ? e * (1.f/Ssum) : 0.f;
      if(wih==0){
        float pc = fmaxf(myA, 1e-6f);
        float ent = warpSum(act ? -pc*logf(pc) : 0.f);
        float lx = act ? learned_s[i][2*lane]   : 0.f;
        float ly = act ? learned_s[i][2*lane+1] : 0.f;
        float nrm = warpSum(act ? sqrtf(lx*lx+ly*ly) : 0.f);
        if(lane==0){
          S_s[i] = vmask ? 1.f : 0.f;
          int n = n0 + i;
          if(n < N){
            float vcnt = (float)__popc(vmask);
            float inst = (nrm/(float)P) / (1.5f*sqrtf(du*du+dv*dv));
            size_t base = (size_t)N*D;
            out[base + n]               = vcnt/(float)P;
            out[base + (size_t)N + n]   = fminf(fmaxf(expf(-inst),0.f),1.f);
            out[base + 2*(size_t)N + n] = fminf(fmaxf(1.f - ent/logf((float)P),0.f),1.f);
          }
        }
      }
    }

    // aggregate in registers with shfl-broadcast attn -> half2 pagg (buffered)
    {
      float4 acc4 = make_float4(0.f,0.f,0.f,0.f);
      #pragma unroll
      for(int k=0;k<4;k++){
        float a = __shfl_sync(0xffffffffu, myA, wih+4*k);
        const float2 lo = __half22float2(sv0[k]);
        const float2 hi = __half22float2(sv1[k]);
        acc4.x = fmaf(a, lo.x, acc4.x);
        acc4.y = fmaf(a, lo.y, acc4.y);
        acc4.z = fmaf(a, hi.x, acc4.z);
        acc4.w = fmaf(a, hi.y, acc4.w);
      }
      float a16 = __shfl_sync(0xffffffffu, myA, 16);
      if(wih==3){
        const float2 lo = __half22float2(sv0[4]);
        const float2 hi = __half22float2(sv1[4]);
        acc4.x = fmaf(a16, lo.x, acc4.x);
        acc4.y = fmaf(a16, lo.y, acc4.y);
        acc4.z = fmaf(a16, hi.x, acc4.z);
        acc4.w = fmaf(a16, hi.y, acc4.w);
      }
      __half2 p0 = __float22half2_rn(make_float2(acc4.x, acc4.y));
      __half2 p1 = __float22half2_rn(make_float2(acc4.z, acc4.w));
      uint2 pr; memcpy(&pr.x,&p0,4); memcpy(&pr.y,&p1,4);
      *(uint2*)&u.paggh[half][buf][wih][2*lane] = pr;
    }
    buf ^= 1;
  }
  barhalf(half);
  if(tc < 64){   // final combine
    const int ip = TP - 2 + half;
    const int pb = buf^1;
    __half2 v = __hadd2(__hadd2(u.paggh[half][pb][0][tc], u.paggh[half][pb][1][tc]),
                        __hadd2(u.paggh[half][pb][2][tc], u.paggh[half][pb][3][tc]));
    *(__half2*)&xh_s[ip][2*tc] = v;
  }
  __syncthreads();

  // ---- GEMV2 via tensor cores: out = agg @ W2 + S*vbp + out_b ----
  {
    float4 acc0 = make_float4(0.f,0.f,0.f,0.f);
    float4 acc1 = make_float4(0.f,0.f,0.f,0.f);
    const uint4* Bf = (const uint4*)g_W2f;
    #pragma unroll
    for(int tk2=0; tk2<4; tk2++){
      unsigned int a0[4], a1[4];
      ldmatrix_x4(a0, abase + (arow*XHP + (2*tk2  )*16 + acolblk)*2);
      ldmatrix_x4(a1, abase + (arow*XHP + (2*tk2+1)*16 + acolblk)*2);
      uint4 rA = __ldg(&Bf[((2*w8  )*4+tk2)*32 + lane]);
      uint4 rB = __ldg(&Bf[((2*w8+1)*4+tk2)*32 + lane]);
      mma16816(acc0, a0, make_uint2(rA.x,rA.y)); mma16816(acc0, a1, make_uint2(rA.z,rA.w));
      mma16816(acc1, a0, make_uint2(rB.x,rB.y)); mma16816(acc1, a1, make_uint2(rB.z,rB.w));
    }
    const float S0 = S_s[r0l], S1 = S_s[r0l+8];
    #pragma unroll
    for(int nt=0; nt<2; nt++){
      const int ch = (2*w8+nt)*8 + c0l;
      const float4 acc = nt ? acc1 : acc0;
      const float2 ob  = *(const float2*)&outb[ch];
      const float2 vbp = *(const float2*)&g_vbp[ch];
      if(n0+r0l < N)
        *(float2*)&out[(size_t)(n0+r0l)*D + ch] =
          make_float2(acc.x + ob.x + S0*vbp.x, acc.y + ob.y + S0*vbp.y);
      if(n0+r0l+8 < N)
        *(float2*)&out[(size_t)(n0+r0l+8)*D + ch] =
          make_float2(acc.z + ob.x + S1*vbp.x, acc.w + ob.y + S1*vbp.y);
    }
  }
}

extern "C" void kernel_launch(void* const* d_in, const int* in_sizes, int n_in,
                              void* d_out, int out_size) {
  const float* x      = (const float*)d_in[0];
  const int*   indices= (const int*)  d_in[1];
  const float* img    = (const float*)d_in[2];
  const float* voxel  = (const float*)d_in[3];
  const float* pcr    = (const float*)d_in[4];
  const float* trans  = (const float*)d_in[5];
  const float* offW   = (const float*)d_in[6];
  const float* offb   = (const float*)d_in[7];
  const float* qW     = (const float*)d_in[8];
  const float* qb     = (const float*)d_in[9];
  const float* kW     = (const float*)d_in[10];
  const float* vW     = (const float*)d_in[12];
  const float* vb     = (const float*)d_in[13];
  const float* outW   = (const float*)d_in[14];
  const float* outb   = (const float*)d_in[15];
  const void*  pH     = d_in[16];
  const void*  pW     = d_in[17];

  int N = in_sizes[0]/D;
  int B = in_sizes[5]/12;

  dim3 tb(32,8);
  k_img_transpose<<<dim3(NPIX/32, D/32, B+1), tb>>>(img, kW, B);
  k_prep_mats<<<dim3(D,4), D>>>(qW, vW, outW, kW, qb, vb, offW);
  k_main<<<(N+TP-1)/TP, 256>>>(x, indices, voxel, pcr, trans, offb, outb,
                               pH, pW, (float*)d_out, N);
}